// round 9
// baseline (speedup 1.0000x reference)
#include <cuda_runtime.h>
#include <math.h>
#include <stdint.h>

#define L_    1024
#define NB    4
#define E_    512
#define H_    8
#define D_    32
#define DFF_  2048
#define E2_   256
#define TOK   4096      // L*NB
#define PM    2047      // 2L-1
#define KW    31

// ---------------- scratch (static device globals; no allocation) -------------
__device__ float g_h1[(size_t)TOK * DFF_];
__device__ float g_x[(size_t)TOK * E_];
__device__ float g_qkv[(size_t)TOK * 768];
__device__ float g_p[(size_t)2048 * 256];
__device__ float g_total[(size_t)32 * 1024 * 1024];   // (N,H,L,S)
__device__ float g_ctx[(size_t)TOK * E2_];
__device__ float g_x2[(size_t)TOK * E_];
__device__ float g_y[(size_t)TOK * 1024];
__device__ float g_hglu[(size_t)NB * E_ * L_];
__device__ float g_hct[(size_t)TOK * E_];
__device__ float g_x3[(size_t)TOK * E_];
__device__ float g_x4[(size_t)TOK * E_];
__device__ float g_wtf[(size_t)5636096];              // tf32-rounded weights

// tf32 weight scratch offsets
#define OFF_FF1M 0
#define OFF_FF2M 1048576
#define OFF_IN   2097152
#define OFF_POS  2490368
#define OFF_OUT  2621440
#define OFF_PW1  2752512
#define OFF_PW2  3276800
#define OFF_FF1  3538944
#define OFF_FF2  4587520

// ---------------- tf32 / cp.async helpers -------------------------------------
__device__ __forceinline__ uint32_t f2tf(float f) {
    uint32_t u;
    asm("cvt.rna.tf32.f32 %0, %1;" : "=r"(u) : "f"(f));
    return u;
}
__device__ __forceinline__ void mma_tf32(float* c, const uint32_t* a, const uint32_t* b) {
    asm volatile(
        "mma.sync.aligned.m16n8k8.row.col.f32.tf32.tf32.f32 "
        "{%0,%1,%2,%3}, {%4,%5,%6,%7}, {%8,%9}, {%0,%1,%2,%3};"
        : "+f"(c[0]), "+f"(c[1]), "+f"(c[2]), "+f"(c[3])
        : "r"(a[0]), "r"(a[1]), "r"(a[2]), "r"(a[3]), "r"(b[0]), "r"(b[1]));
}
__device__ __forceinline__ void cp16(void* dst_smem, const void* src) {
    uint32_t d = (uint32_t)__cvta_generic_to_shared(dst_smem);
    asm volatile("cp.async.ca.shared.global [%0], [%1], 16;\n" :: "r"(d), "l"(src));
}

// -------- prepass: round 9 weight matrices to tf32 (RNA) into g_wtf ------------
struct CvtArgs {
    const float* src[9];
    int dstoff[9];
    int n4[9];
};
__global__ __launch_bounds__(256) void cvtw_kernel(CvtArgs args) {
    const int wi = blockIdx.y;
    const int idx = blockIdx.x * 256 + threadIdx.x;
    if (idx >= args.n4[wi]) return;
    float4 v = *(const float4*)(args.src[wi] + (size_t)idx * 4);
    uint4 o;
    o.x = f2tf(v.x); o.y = f2tf(v.y); o.z = f2tf(v.z); o.w = f2tf(v.w);
    *(uint4*)(g_wtf + args.dstoff[wi] + (size_t)idx * 4) = o;
}

// ------- cp.async double-buffered tf32 GEMM (8 warps, 64x32 warptile) ---------
// C = A(MxK) B(NxK)^T + bias (+epi). Nn % 128 == 0, Kk % 32 == 0.
// B must be pre-rounded to tf32 (g_wtf). A converted at fragment load.
// EPI: 0 = bias; 1 = bias + DoubleSwish; 2 = bias + residual add
#define TG_STRIDE 36
#define TG_BUFELT (128 * TG_STRIDE)
template <int EPI>
__global__ __launch_bounds__(256, 2) void tgemm(
    const float* __restrict__ A, const float* __restrict__ B,
    const float* __restrict__ bias, const float* __restrict__ res,
    float* __restrict__ C, int M, int Nn, int Kk)
{
    extern __shared__ float smem[];
    float* Af = smem;                    // [2][128][36]
    float* Bf = smem + 2 * TG_BUFELT;    // [2][128][36]

    const int tid   = threadIdx.x;
    const int wid   = tid >> 5;          // 0..7
    const int lane  = tid & 31;
    const int grp   = lane >> 2;
    const int tig   = lane & 3;
    const int row0  = blockIdx.y * 128;
    const int col0  = blockIdx.x * 128;
    const int wm    = (wid >> 2) * 64;   // 0 or 64
    const int wn    = (wid & 3) * 32;    // 0,32,64,96

    float acc[4][4][4];
#pragma unroll
    for (int mt = 0; mt < 4; mt++)
#pragma unroll
        for (int nt = 0; nt < 4; nt++)
#pragma unroll
            for (int q = 0; q < 4; q++) acc[mt][nt][q] = 0.f;

    const int lrr = tid >> 3;            // 0..31
    const int lcc = (tid & 7) * 4;       // 0..28

#define LOADTILE(t, bf) {                                                       \
        const int kk0 = (t) * 32;                                               \
        _Pragma("unroll")                                                       \
        for (int i = 0; i < 4; i++) {                                           \
            int r = lrr + 32 * i;                                               \
            int ar = row0 + r; if (ar >= M) ar = M - 1;                         \
            cp16(&Af[(bf) * TG_BUFELT + r * TG_STRIDE + lcc],                   \
                 A + (size_t)ar * Kk + kk0 + lcc);                              \
            cp16(&Bf[(bf) * TG_BUFELT + r * TG_STRIDE + lcc],                   \
                 B + (size_t)(col0 + r) * Kk + kk0 + lcc);                      \
        }                                                                       \
        asm volatile("cp.async.commit_group;\n" ::); }

    const int ntile = Kk >> 5;
    LOADTILE(0, 0);
    int buf = 0;
    for (int t = 0; t < ntile; t++) {
        if (t + 1 < ntile) {
            LOADTILE(t + 1, buf ^ 1);
            asm volatile("cp.async.wait_group 1;\n" ::);
        } else {
            asm volatile("cp.async.wait_group 0;\n" ::);
        }
        __syncthreads();
        const float* Ab = Af + buf * TG_BUFELT;
        const float* Bb = Bf + buf * TG_BUFELT;
#pragma unroll
        for (int k8 = 0; k8 < 4; k8++) {
            const int kb = k8 * 8;
            uint32_t a[4][4], b[4][2];
#pragma unroll
            for (int mt = 0; mt < 4; mt++) {
                int mr = wm + mt * 16 + grp;
                a[mt][0] = f2tf(Ab[mr * TG_STRIDE + kb + tig]);
                a[mt][1] = f2tf(Ab[(mr + 8) * TG_STRIDE + kb + tig]);
                a[mt][2] = f2tf(Ab[mr * TG_STRIDE + kb + tig + 4]);
                a[mt][3] = f2tf(Ab[(mr + 8) * TG_STRIDE + kb + tig + 4]);
            }
#pragma unroll
            for (int nt = 0; nt < 4; nt++) {
                int nr = wn + nt * 8 + grp;
                b[nt][0] = __float_as_uint(Bb[nr * TG_STRIDE + kb + tig]);
                b[nt][1] = __float_as_uint(Bb[nr * TG_STRIDE + kb + tig + 4]);
            }
#pragma unroll
            for (int mt = 0; mt < 4; mt++)
#pragma unroll
                for (int nt = 0; nt < 4; nt++)
                    mma_tf32(acc[mt][nt], a[mt], b[nt]);
        }
        __syncthreads();
        buf ^= 1;
    }
#undef LOADTILE

#pragma unroll
    for (int mt = 0; mt < 4; mt++) {
        int rbase = row0 + wm + mt * 16 + grp;
#pragma unroll
        for (int nt = 0; nt < 4; nt++) {
            int col = col0 + wn + nt * 8 + tig * 2;
            float2 bb = make_float2(0.f, 0.f);
            if (bias) bb = *(const float2*)(bias + col);
#pragma unroll
            for (int half = 0; half < 2; half++) {
                int row = rbase + half * 8;
                if (row >= M) continue;
                float v0 = acc[mt][nt][half * 2 + 0] + bb.x;
                float v1 = acc[mt][nt][half * 2 + 1] + bb.y;
                if (EPI == 1) {
                    v0 = v0 / (1.f + expf(1.f - v0));
                    v1 = v1 / (1.f + expf(1.f - v1));
                }
                if (EPI == 2) {
                    float2 rr = *(const float2*)(res + (size_t)row * Nn + col);
                    v0 += rr.x; v1 += rr.y;
                }
                *(float2*)(C + (size_t)row * Nn + col) = make_float2(v0, v1);
            }
        }
    }
}
#define TG_SMEM (4 * TG_BUFELT * (int)sizeof(float))   // 73728 bytes

// -------- tf32-MMA scores: total = (QU·KS^T + relshift(QV·PS^T)) * scal -------
#define SC_SMEM (12800 * (int)sizeof(float))   // 51200 bytes
__global__ __launch_bounds__(256) void scores_mma_kernel(
    const float* __restrict__ qkv, const float* __restrict__ p,
    const float* __restrict__ pu, const float* __restrict__ pv,
    float* __restrict__ total)
{
    extern __shared__ float sm[];
    float* QU  = sm;             // [64][36]
    float* QV  = sm + 2304;      // [64][36]
    float* KS  = sm + 4608;      // [64][36]
    float* PS  = sm + 6912;      // [128][36]
    float* ACs = sm;             // [64][68]  (phase 2)
    float* BDs = sm + 4352;      // [64][132] (phase 2)

    const int tid = threadIdx.x;
    const int nh = blockIdx.z;
    const int n = nh >> 3, h = nh & 7;
    const int l0 = blockIdx.y * 64;
    const int s0 = blockIdx.x * 64;
    const int mbase = (L_ - 64) - l0 + s0;

#pragma unroll
    for (int it = 0; it < 2; it++) {
        int u = tid + it * 256;
        int r = u >> 3, d4 = (u & 7) * 4;
        float4 qf = *(const float4*)(qkv + (size_t)((l0 + r) * NB + n) * 768 + h * 32 + d4);
        float4 uu = *(const float4*)(pu + h * 32 + d4);
        float4 vv = *(const float4*)(pv + h * 32 + d4);
        QU[r * 36 + d4 + 0] = qf.x + uu.x; QU[r * 36 + d4 + 1] = qf.y + uu.y;
        QU[r * 36 + d4 + 2] = qf.z + uu.z; QU[r * 36 + d4 + 3] = qf.w + uu.w;
        QV[r * 36 + d4 + 0] = qf.x + vv.x; QV[r * 36 + d4 + 1] = qf.y + vv.y;
        QV[r * 36 + d4 + 2] = qf.z + vv.z; QV[r * 36 + d4 + 3] = qf.w + vv.w;
        float4 kf = *(const float4*)(qkv + (size_t)((s0 + r) * NB + n) * 768 + 256 + h * 32 + d4);
        KS[r * 36 + d4 + 0] = kf.x; KS[r * 36 + d4 + 1] = kf.y;
        KS[r * 36 + d4 + 2] = kf.z; KS[r * 36 + d4 + 3] = kf.w;
    }
#pragma unroll
    for (int it = 0; it < 4; it++) {
        int u = tid + it * 256;
        int r = u >> 3, d4 = (u & 7) * 4;
        int m = mbase + r;
        float4 pf = make_float4(0.f, 0.f, 0.f, 0.f);
        if (m < PM) pf = *(const float4*)(p + (size_t)m * 256 + h * 32 + d4);
        PS[r * 36 + d4 + 0] = pf.x; PS[r * 36 + d4 + 1] = pf.y;
        PS[r * 36 + d4 + 2] = pf.z; PS[r * 36 + d4 + 3] = pf.w;
    }
    __syncthreads();

    const int wid = tid >> 5, lane = tid & 31;
    const int grp = lane >> 2, tig = lane & 3;
    const int wm = (wid >> 1) * 16;
    const int wnA = (wid & 1) * 32;
    const int wnB = (wid & 1) * 64;

    float acA[4][4] = {}, acB[8][4] = {};
#pragma unroll
    for (int k8 = 0; k8 < 4; k8++) {
        const int kb = k8 * 8;
        uint32_t aU[4], aV[4];
        aU[0] = f2tf(QU[(wm + grp) * 36 + kb + tig]);
        aU[1] = f2tf(QU[(wm + grp + 8) * 36 + kb + tig]);
        aU[2] = f2tf(QU[(wm + grp) * 36 + kb + tig + 4]);
        aU[3] = f2tf(QU[(wm + grp + 8) * 36 + kb + tig + 4]);
        aV[0] = f2tf(QV[(wm + grp) * 36 + kb + tig]);
        aV[1] = f2tf(QV[(wm + grp + 8) * 36 + kb + tig]);
        aV[2] = f2tf(QV[(wm + grp) * 36 + kb + tig + 4]);
        aV[3] = f2tf(QV[(wm + grp + 8) * 36 + kb + tig + 4]);
#pragma unroll
        for (int nt = 0; nt < 4; nt++) {
            int nr = wnA + nt * 8 + grp;
            uint32_t b[2] = { f2tf(KS[nr * 36 + kb + tig]), f2tf(KS[nr * 36 + kb + tig + 4]) };
            mma_tf32(acA[nt], aU, b);
        }
#pragma unroll
        for (int nt = 0; nt < 8; nt++) {
            int nr = wnB + nt * 8 + grp;
            uint32_t b[2] = { f2tf(PS[nr * 36 + kb + tig]), f2tf(PS[nr * 36 + kb + tig + 4]) };
            mma_tf32(acB[nt], aV, b);
        }
    }
    __syncthreads();

#pragma unroll
    for (int nt = 0; nt < 4; nt++) {
        int col = wnA + nt * 8 + tig * 2;
        *(float2*)&ACs[(wm + grp) * 68 + col]     = make_float2(acA[nt][0], acA[nt][1]);
        *(float2*)&ACs[(wm + grp + 8) * 68 + col] = make_float2(acA[nt][2], acA[nt][3]);
    }
#pragma unroll
    for (int nt = 0; nt < 8; nt++) {
        int col = wnB + nt * 8 + tig * 2;
        *(float2*)&BDs[(wm + grp) * 132 + col]     = make_float2(acB[nt][0], acB[nt][1]);
        *(float2*)&BDs[(wm + grp + 8) * 132 + col] = make_float2(acB[nt][2], acB[nt][3]);
    }
    __syncthreads();

    const float scal = 0.17677669529663687f;   // 1/sqrt(32)
    const int cc = (tid & 15) * 4;
    const int rb = tid >> 4;
#pragma unroll
    for (int it = 0; it < 4; it++) {
        int r = rb + it * 16;
        int off = 63 - r + cc;
        float4 o;
        o.x = (ACs[r * 68 + cc + 0] + BDs[r * 132 + off + 0]) * scal;
        o.y = (ACs[r * 68 + cc + 1] + BDs[r * 132 + off + 1]) * scal;
        o.z = (ACs[r * 68 + cc + 2] + BDs[r * 132 + off + 2]) * scal;
        o.w = (ACs[r * 68 + cc + 3] + BDs[r * 132 + off + 3]) * scal;
        *(float4*)(total + (((size_t)nh) << 20) + (size_t)(l0 + r) * L_ + s0 + cc) = o;
    }
}

// ---- fused proj_in + scores_out + softmax: one block per (n,l) row ------------
__global__ __launch_bounds__(256) void out_softmax_kernel(
    float* __restrict__ total, const float* __restrict__ asi,
    const float* __restrict__ projIn, const float* __restrict__ projOut,
    float* __restrict__ scores_out)
{
    __shared__ float ts[8][1028];
    __shared__ float pin[64], pout[64];
    __shared__ float red[8][8];
    const int tid = threadIdx.x;
    const int b = blockIdx.x;
    const int n = b >> 10, l = b & 1023;
    if (tid < 64) { pin[tid] = projIn[tid]; pout[tid] = projOut[tid]; }

#pragma unroll
    for (int h = 0; h < 8; h++) {
        float4 v = *(const float4*)(total + (((size_t)(n * 8 + h)) << 20)
                                          + ((size_t)l << 10) + tid * 4);
        *(float4*)&ts[h][tid * 4] = v;
    }
    __syncthreads();

    const int s = tid * 4;
    const size_t abase = ((size_t)n << 23) + ((size_t)l << 13) + ((size_t)s << 3);
    for (int js = 0; js < 4; js++) {
        float4 a0 = *(const float4*)(asi + abase + js * 8);
        float4 a1 = *(const float4*)(asi + abase + js * 8 + 4);
        float a[8] = {a0.x, a0.y, a0.z, a0.w, a1.x, a1.y, a1.z, a1.w};
        float tn8[8];
#pragma unroll
        for (int h = 0; h < 8; h++) {
            float t = ts[h][s + js];
#pragma unroll
            for (int g = 0; g < 8; g++) t = fmaf(a[g], pin[g * 8 + h], t);
            tn8[h] = t;
        }
        float o[8];
#pragma unroll
        for (int g = 0; g < 8; g++) {
            float sum = a[g];
#pragma unroll
            for (int h = 0; h < 8; h++) sum = fmaf(tn8[h], pout[h * 8 + g], sum);
            o[g] = sum;
        }
        *(float4*)(scores_out + abase + js * 8)     = make_float4(o[0], o[1], o[2], o[3]);
        *(float4*)(scores_out + abase + js * 8 + 4) = make_float4(o[4], o[5], o[6], o[7]);
#pragma unroll
        for (int h = 0; h < 8; h++) ts[h][s + js] = tn8[h];
    }

    float mh[8];
#pragma unroll
    for (int h = 0; h < 8; h++) {
        float m = fmaxf(fmaxf(ts[h][s], ts[h][s+1]), fmaxf(ts[h][s+2], ts[h][s+3]));
#pragma unroll
        for (int o = 16; o > 0; o >>= 1) m = fmaxf(m, __shfl_xor_sync(0xffffffffu, m, o));
        mh[h] = m;
    }
    if ((tid & 31) == 0)
#pragma unroll
        for (int h = 0; h < 8; h++) red[h][tid >> 5] = mh[h];
    __syncthreads();
#pragma unroll
    for (int h = 0; h < 8; h++) {
        float m = red[h][0];
#pragma unroll
        for (int w = 1; w < 8; w++) m = fmaxf(m, red[h][w]);
        mh[h] = m;
    }
    __syncthreads();

    float sh[8];
#pragma unroll
    for (int h = 0; h < 8; h++) {
        float s0 = 0.f;
#pragma unroll
        for (int js = 0; js < 4; js++) {
            float e = expf(ts[h][s + js] - mh[h]);
            ts[h][s + js] = e;
            s0 += e;
        }
#pragma unroll
        for (int o = 16; o > 0; o >>= 1) s0 += __shfl_xor_sync(0xffffffffu, s0, o);
        sh[h] = s0;
    }
    if ((tid & 31) == 0)
#pragma unroll
        for (int h = 0; h < 8; h++) red[h][tid >> 5] = sh[h];
    __syncthreads();
#pragma unroll
    for (int h = 0; h < 8; h++) {
        float ss = red[h][0] + red[h][1] + red[h][2] + red[h][3]
                 + red[h][4] + red[h][5] + red[h][6] + red[h][7];
        float inv = 1.f / ss;
        float4 o = make_float4(ts[h][s]*inv, ts[h][s+1]*inv, ts[h][s+2]*inv, ts[h][s+3]*inv);
        *(float4*)(total + (((size_t)(n * 8 + h)) << 20) + ((size_t)l << 10) + s) = o;
    }
}

// -------- ctx[l,n,h*32+d] = sum_s attn[n,h,l,s] * v[s,n,h,d] -------------------
__global__ __launch_bounds__(256) void av_kernel(
    const float* __restrict__ attn, const float* __restrict__ qkv,
    float* __restrict__ ctx)
{
    const int nh = blockIdx.y;
    const int n = nh >> 3, h = nh & 7;
    const int l0 = blockIdx.x * 64;
    __shared__ float As[64][65];
    __shared__ float Vs[64][33];
    const int tid = threadIdx.x;
    const int col = tid & 31;
    const int rg  = tid >> 5;
    float acc[8] = {};
    const float* Abase = attn + (((size_t)nh) << 20) + (((size_t)l0) << 10);
    for (int s0 = 0; s0 < 1024; s0 += 64) {
#pragma unroll
        for (int t = 0; t < 4; t++) {
            int f4 = tid + 256 * t;
            int r = f4 >> 4;
            int c4 = (f4 & 15) * 4;
            float4 v = *(const float4*)(Abase + (((size_t)r) << 10) + s0 + c4);
            As[r][c4] = v.x; As[r][c4 + 1] = v.y; As[r][c4 + 2] = v.z; As[r][c4 + 3] = v.w;
        }
#pragma unroll
        for (int t = 0; t < 8; t++) {
            int flat = tid + 256 * t;
            int r = flat >> 5, dd = flat & 31;
            Vs[r][dd] = qkv[(size_t)((s0 + r) * NB + n) * 768 + 512 + h * 32 + dd];
        }
        __syncthreads();
#pragma unroll
        for (int kk = 0; kk < 64; kk++) {
            float vv = Vs[kk][col];
#pragma unroll
            for (int i = 0; i < 8; i++)
                acc[i] = fmaf(As[rg * 8 + i][kk], vv, acc[i]);
        }
        __syncthreads();
    }
#pragma unroll
    for (int i = 0; i < 8; i++) {
        int l = l0 + rg * 8 + i;
        ctx[(size_t)(l * NB + n) * 256 + h * 32 + col] = acc[i];
    }
}

// -------- GLU with 32x32 smem transpose: y(l,n,:) -> hglu(n,c,l) ---------------
__global__ __launch_bounds__(256) void glu_t_kernel(
    const float* __restrict__ y, float* __restrict__ hglu)
{
    __shared__ float sm[32][33];
    const int l0 = blockIdx.x * 32, c0 = blockIdx.y * 32, n = blockIdx.z;
    const int li = threadIdx.x >> 3;
    const int c4 = (threadIdx.x & 7) * 4;
    size_t t = (size_t)(l0 + li) * NB + n;
    float4 a = *(const float4*)(y + t * 1024 + c0 + c4);
    float4 b = *(const float4*)(y + t * 1024 + c0 + c4 + 512);
    sm[c4 + 0][li] = a.x / (1.f + expf(-b.x));
    sm[c4 + 1][li] = a.y / (1.f + expf(-b.y));
    sm[c4 + 2][li] = a.z / (1.f + expf(-b.z));
    sm[c4 + 3][li] = a.w / (1.f + expf(-b.w));
    __syncthreads();
    const int c = threadIdx.x >> 3;
    const int l4 = (threadIdx.x & 7) * 4;
    float4 o = make_float4(sm[c][l4], sm[c][l4 + 1], sm[c][l4 + 2], sm[c][l4 + 3]);
    *(float4*)(hglu + (((size_t)(n * 512 + c0 + c)) << 10) + l0 + l4) = o;
}

// -------- depthwise conv(K=31) + bias + DoubleSwish, coalesced writes ---------
__global__ __launch_bounds__(256) void dwconv_kernel(
    const float* __restrict__ hglu, const float* __restrict__ w,
    const float* __restrict__ b, float* __restrict__ out)
{
    __shared__ float in_s[32 * 161];
    __shared__ float w_s[32 * 33];
    const int l0 = blockIdx.x * 128;
    const int c0 = blockIdx.y * 32;
    const int n  = blockIdx.z;

    for (int idx = threadIdx.x; idx < 32 * 160; idx += 256) {
        int row = idx / 160, col = idx % 160;
        int gl = l0 + col - 15;
        float v = 0.f;
        if (col < 158 && gl >= 0 && gl < L_)
            v = hglu[(((size_t)(n * 512 + c0 + row)) << 10) + gl];
        in_s[row * 161 + col] = v;
    }
    for (int idx = threadIdx.x; idx < 32 * KW; idx += 256) {
        int c = idx / KW, k = idx % KW;
        w_s[c * 33 + k] = w[(c0 + c) * KW + k];
    }
    __syncthreads();

    const int ci = threadIdx.x & 31;
    const int lq = threadIdx.x >> 5;
    const float bb = b[c0 + ci];
#pragma unroll
    for (int lt = 0; lt < 16; lt++) {
        int ll = lt * 8 + lq;
        float s = bb;
#pragma unroll
        for (int k = 0; k < KW; k++)
            s = fmaf(in_s[ci * 161 + ll + k], w_s[ci * 33 + k], s);
        float v = s / (1.f + expf(1.f - s));
        out[(((size_t)((l0 + ll) * NB + n)) << 9) + c0 + ci] = v;
    }
}

// -------- BasicNorm -> d_out ---------------------------------------------------
__global__ __launch_bounds__(128) void norm_kernel(
    const float* __restrict__ x, const float* __restrict__ leps,
    float* __restrict__ out)
{
    __shared__ float red[4];
    const size_t base = (size_t)blockIdx.x * 512;
    float4 v = ((const float4*)(x + base))[threadIdx.x];
    float ss = v.x * v.x + v.y * v.y + v.z * v.z + v.w * v.w;
#pragma unroll
    for (int o = 16; o > 0; o >>= 1) ss += __shfl_xor_sync(0xffffffffu, ss, o);
    if ((threadIdx.x & 31) == 0) red[threadIdx.x >> 5] = ss;
    __syncthreads();
    float tot = red[0] + red[1] + red[2] + red[3];
    float scale = rsqrtf(tot * (1.f / 512.f) + expf(leps[0]));
    ((float4*)(out + base))[threadIdx.x] =
        make_float4(v.x * scale, v.y * scale, v.z * scale, v.w * scale);
}

// ------------------------------- launcher -------------------------------------
extern "C" void kernel_launch(void* const* d_in, const int* in_sizes, int n_in,
                              void* d_out, int out_size)
{
    const float* src      = (const float*)d_in[0];
    const float* pos_emb  = (const float*)d_in[1];
    const float* asi      = (const float*)d_in[2];
    const float* w_in     = (const float*)d_in[3];
    const float* b_in     = (const float*)d_in[4];
    const float* w_pos    = (const float*)d_in[5];
    const float* pbu      = (const float*)d_in[6];
    const float* pbv      = (const float*)d_in[7];
    const float* projIn   = (const float*)d_in[8];
    const float* projOut  = (const float*)d_in[9];
    const float* w_out    = (const float*)d_in[10];
    const float* b_out    = (const float*)d_in[11];
    const float* w_ff1m   = (const float*)d_in[12];
    const float* b_ff1m   = (const float*)d_in[13];
    const float* w_ff2m   = (const float*)d_in[14];
    const float* b_ff2m   = (const float*)d_in[15];
    const float* w_ff1    = (const float*)d_in[16];
    const float* b_ff1    = (const float*)d_in[17];
    const float* w_ff2    = (const float*)d_in[18];
    const float* b_ff2    = (const float*)d_in[19];
    const float* w_pw1    = (const float*)d_in[20];
    const float* b_pw1    = (const float*)d_in[21];
    const float* w_dw     = (const float*)d_in[22];
    const float* b_dw     = (const float*)d_in[23];
    const float* w_pw2    = (const float*)d_in[24];
    const float* b_pw2    = (const float*)d_in[25];
    const float* leps     = (const float*)d_in[26];

    float* out        = (float*)d_out;
    float* out_scores = out + (size_t)TOK * E_;

    float *h1, *x, *qkv, *p, *total, *ctx, *x2, *y, *hglu, *hct, *x3, *x4, *wtf;
    cudaGetSymbolAddress((void**)&h1,   g_h1);
    cudaGetSymbolAddress((void**)&x,    g_x);
    cudaGetSymbolAddress((void**)&qkv,  g_qkv);
    cudaGetSymbolAddress((void**)&p,    g_p);
    cudaGetSymbolAddress((void**)&total,g_total);
    cudaGetSymbolAddress((void**)&ctx,  g_ctx);
    cudaGetSymbolAddress((void**)&x2,   g_x2);
    cudaGetSymbolAddress((void**)&y,    g_y);
    cudaGetSymbolAddress((void**)&hglu, g_hglu);
    cudaGetSymbolAddress((void**)&hct,  g_hct);
    cudaGetSymbolAddress((void**)&x3,   g_x3);
    cudaGetSymbolAddress((void**)&x4,   g_x4);
    cudaGetSymbolAddress((void**)&wtf,  g_wtf);

    static bool attr_set = false;
    if (!attr_set) {
        cudaFuncSetAttribute(tgemm<0>, cudaFuncAttributeMaxDynamicSharedMemorySize, TG_SMEM);
        cudaFuncSetAttribute(tgemm<1>, cudaFuncAttributeMaxDynamicSharedMemorySize, TG_SMEM);
        cudaFuncSetAttribute(tgemm<2>, cudaFuncAttributeMaxDynamicSharedMemorySize, TG_SMEM);
        cudaFuncSetAttribute(scores_mma_kernel, cudaFuncAttributeMaxDynamicSharedMemorySize, SC_SMEM);
        attr_set = true;
    }

    // prepass: tf32-round all B (weight) operands
    CvtArgs ca;
    ca.src[0] = w_ff1m; ca.dstoff[0] = OFF_FF1M; ca.n4[0] = (DFF_ * E_) / 4;
    ca.src[1] = w_ff2m; ca.dstoff[1] = OFF_FF2M; ca.n4[1] = (E_ * DFF_) / 4;
    ca.src[2] = w_in;   ca.dstoff[2] = OFF_IN;   ca.n4[2] = (768 * E_) / 4;
    ca.src[3] = w_pos;  ca.dstoff[3] = OFF_POS;  ca.n4[3] = (E2_ * E_) / 4;
    ca.src[4] = w_out;  ca.dstoff[4] = OFF_OUT;  ca.n4[4] = (E_ * E2_) / 4;
    ca.src[5] = w_pw1;  ca.dstoff[5] = OFF_PW1;  ca.n4[5] = (1024 * E_) / 4;
    ca.src[6] = w_pw2;  ca.dstoff[6] = OFF_PW2;  ca.n4[6] = (E_ * E_) / 4;
    ca.src[7] = w_ff1;  ca.dstoff[7] = OFF_FF1;  ca.n4[7] = (DFF_ * E_) / 4;
    ca.src[8] = w_ff2;  ca.dstoff[8] = OFF_FF2;  ca.n4[8] = (E_ * DFF_) / 4;
    cvtw_kernel<<<dim3(1024, 9), 256>>>(ca);

    // macaron FFN
    tgemm<1><<<dim3(DFF_ / 128, TOK / 128), 256, TG_SMEM>>>(src, wtf + OFF_FF1M, b_ff1m, nullptr, h1, TOK, DFF_, E_);
    tgemm<2><<<dim3(E_ / 128, TOK / 128), 256, TG_SMEM>>>(h1, wtf + OFF_FF2M, b_ff2m, src, x, TOK, E_, DFF_);

    // attention inputs
    tgemm<0><<<dim3(768 / 128, TOK / 128), 256, TG_SMEM>>>(x, wtf + OFF_IN, b_in, nullptr, qkv, TOK, 768, E_);
    tgemm<0><<<dim3(2, 16), 256, TG_SMEM>>>(pos_emb, wtf + OFF_POS, nullptr, nullptr, p, PM, 256, E_);

    // raw scores (tf32 MMA) -> fused proj_in + scores_out + softmax -> AV
    scores_mma_kernel<<<dim3(16, 16, 32), 256, SC_SMEM>>>(qkv, p, pbu, pbv, total);
    out_softmax_kernel<<<4096, 256>>>(total, asi, projIn, projOut, out_scores);
    av_kernel<<<dim3(16, 32), 256>>>(total, qkv, ctx);
    tgemm<2><<<dim3(E_ / 128, TOK / 128), 256, TG_SMEM>>>(ctx, wtf + OFF_OUT, b_out, x, x2, TOK, E_, E2_);

    // conv module
    tgemm<0><<<dim3(1024 / 128, TOK / 128), 256, TG_SMEM>>>(x2, wtf + OFF_PW1, b_pw1, nullptr, y, TOK, 1024, E_);
    glu_t_kernel<<<dim3(32, 16, NB), 256>>>(y, hglu);
    dwconv_kernel<<<dim3(8, 16, NB), 256>>>(hglu, w_dw, b_dw, hct);
    tgemm<2><<<dim3(E_ / 128, TOK / 128), 256, TG_SMEM>>>(hct, wtf + OFF_PW2, b_pw2, x2, x3, TOK, E_, E_);

    // final FFN + BasicNorm
    tgemm<1><<<dim3(DFF_ / 128, TOK / 128), 256, TG_SMEM>>>(x3, wtf + OFF_FF1, b_ff1, nullptr, h1, TOK, DFF_, E_);
    tgemm<2><<<dim3(E_ / 128, TOK / 128), 256, TG_SMEM>>>(h1, wtf + OFF_FF2, b_ff2, x3, x4, TOK, E_, DFF_);
    norm_kernel<<<TOK, 128>>>(x4, leps, out);
}

// round 11
// speedup vs baseline: 1.0394x; 1.0394x over previous
#include <cuda_runtime.h>
#include <cuda_fp16.h>
#include <math.h>
#include <stdint.h>

#define L_    1024
#define NB    4
#define E_    512
#define H_    8
#define D_    32
#define DFF_  2048
#define E2_   256
#define TOK   4096      // L*NB
#define PM    2047      // 2L-1
#define KW    31

// ---------------- scratch (static device globals; no allocation) -------------
__device__ float g_h1[(size_t)TOK * DFF_];
__device__ float g_x[(size_t)TOK * E_];
__device__ float g_qkv[(size_t)TOK * 768];
__device__ float g_p[(size_t)2048 * 256];
__device__ float g_total[(size_t)32 * 1024 * 1024];   // (N,H,L,S)
__device__ float g_ctx[(size_t)TOK * E2_];
__device__ float g_x2[(size_t)TOK * E_];
__device__ float g_y[(size_t)TOK * 1024];
__device__ float g_hglu[(size_t)NB * E_ * L_];
__device__ float g_hct[(size_t)TOK * E_];
__device__ float g_x3[(size_t)TOK * E_];
__device__ float g_x4[(size_t)TOK * E_];
__device__ __half g_whf[(size_t)5636096];             // fp16 weights

// fp16 weight scratch offsets (elements)
#define OFF_FF1M 0
#define OFF_FF2M 1048576
#define OFF_IN   2097152
#define OFF_POS  2490368
#define OFF_OUT  2621440
#define OFF_PW1  2752512
#define OFF_PW2  3276800
#define OFF_FF1  3538944
#define OFF_FF2  4587520

// ---------------- helpers ------------------------------------------------------
__device__ __forceinline__ uint32_t f2tf(float f) {
    uint32_t u;
    asm("cvt.rna.tf32.f32 %0, %1;" : "=r"(u) : "f"(f));
    return u;
}
__device__ __forceinline__ void mma_tf32(float* c, const uint32_t* a, const uint32_t* b) {
    asm volatile(
        "mma.sync.aligned.m16n8k8.row.col.f32.tf32.tf32.f32 "
        "{%0,%1,%2,%3}, {%4,%5,%6,%7}, {%8,%9}, {%0,%1,%2,%3};"
        : "+f"(c[0]), "+f"(c[1]), "+f"(c[2]), "+f"(c[3])
        : "r"(a[0]), "r"(a[1]), "r"(a[2]), "r"(a[3]), "r"(b[0]), "r"(b[1]));
}
__device__ __forceinline__ void mma_f16(float* c, const uint32_t* a, const uint32_t* b) {
    asm volatile(
        "mma.sync.aligned.m16n8k16.row.col.f32.f16.f16.f32 "
        "{%0,%1,%2,%3}, {%4,%5,%6,%7}, {%8,%9}, {%0,%1,%2,%3};"
        : "+f"(c[0]), "+f"(c[1]), "+f"(c[2]), "+f"(c[3])
        : "r"(a[0]), "r"(a[1]), "r"(a[2]), "r"(a[3]), "r"(b[0]), "r"(b[1]));
}
__device__ __forceinline__ void cp16s(uint32_t daddr, const void* src) {
    asm volatile("cp.async.ca.shared.global [%0], [%1], 16;\n" :: "r"(daddr), "l"(src));
}
__device__ __forceinline__ uint32_t smem_u32(const void* p) {
    uint32_t a;
    asm("{ .reg .u64 t; cvta.to.shared.u64 t, %1; cvt.u32.u64 %0, t; }" : "=r"(a) : "l"(p));
    return a;
}
__device__ __forceinline__ uint32_t pack_h2(float x, float y) {
    __half2 h = __floats2half2_rn(x, y);
    return *(uint32_t*)&h;
}

// -------- prepass: convert 9 weight matrices to fp16 into g_whf ----------------
struct CvtArgs {
    const float* src[9];
    int dstoff[9];
    int n4[9];
};
__global__ __launch_bounds__(256) void cvtw_kernel(CvtArgs args) {
    const int wi = blockIdx.y;
    const int idx = blockIdx.x * 256 + threadIdx.x;
    if (idx >= args.n4[wi]) return;
    float4 v = *(const float4*)(args.src[wi] + (size_t)idx * 4);
    uint32_t lo = pack_h2(v.x, v.y);
    uint32_t hi = pack_h2(v.z, v.w);
    *(uint2*)(g_whf + args.dstoff[wi] + (size_t)idx * 4) = make_uint2(lo, hi);
}

// ------- cp.async double-buffered fp16 GEMM (8 warps, 64x32 warptile) ---------
// C = A(MxK) B(NxK)^T + bias (+epi). Nn % 128 == 0, Kk % 32 == 0.
// B pre-converted to fp16 (g_whf); A converted to fp16 at staging (RN).
// smem: halves, row stride 40 (conflict-free fragment loads).
// EPI: 0 = bias; 1 = bias + DoubleSwish; 2 = bias + residual add
#define TH_STRIDE 40
#define TH_BUF    (128 * TH_STRIDE)     // halves per buffer
#define TH_SMEM   (4 * TH_BUF * 2)      // bytes = 40960
template <int EPI>
__global__ __launch_bounds__(256, 2) void hgemm(
    const float* __restrict__ A, const __half* __restrict__ B,
    const float* __restrict__ bias, const float* __restrict__ res,
    float* __restrict__ C, int M, int Nn, int Kk)
{
    extern __shared__ __half smh[];
    const uint32_t smb = smem_u32(smh);
    const int tid   = threadIdx.x;
    const int wid   = tid >> 5;
    const int lane  = tid & 31;
    const int grp   = lane >> 2;
    const int tig   = lane & 3;
    const int row0  = blockIdx.y * 128;
    const int col0  = blockIdx.x * 128;
    const int wm    = (wid >> 2) * 64;   // 0 or 64
    const int wn    = (wid & 3) * 32;    // 0,32,64,96
    const int srow  = tid >> 1;          // 0..127 (staging row)
    const int shalf = (tid & 1) * 16;    // staging half-col base

    float acc[4][4][4];
#pragma unroll
    for (int mt = 0; mt < 4; mt++)
#pragma unroll
        for (int nt = 0; nt < 4; nt++)
#pragma unroll
            for (int q = 0; q < 4; q++) acc[mt][nt][q] = 0.f;

    float4 ast[4];
#define LDGA(t) {                                                               \
        int ar = row0 + srow; if (ar >= M) ar = M - 1;                          \
        const float* ap = A + (size_t)ar * Kk + (t) * 32 + shalf;               \
        _Pragma("unroll")                                                       \
        for (int i = 0; i < 4; i++) ast[i] = *(const float4*)(ap + i * 4); }
#define STSA(bf) {                                                              \
        __half* dst = smh + (bf) * TH_BUF + srow * TH_STRIDE + shalf;           \
        _Pragma("unroll")                                                       \
        for (int i = 0; i < 4; i++) {                                           \
            uint32_t h0 = pack_h2(ast[i].x, ast[i].y);                          \
            uint32_t h1 = pack_h2(ast[i].z, ast[i].w);                          \
            *(uint2*)(dst + i * 4) = make_uint2(h0, h1); } }
#define LOADB(t) {                                                              \
        uint32_t base = smb + (uint32_t)((2 + ((t) & 1)) * TH_BUF + srow * TH_STRIDE) * 2; \
        const __half* bp = B + (size_t)(col0 + srow) * Kk + (t) * 32 + shalf;   \
        cp16s(base + shalf * 2,      bp);                                       \
        cp16s(base + shalf * 2 + 16, bp + 8);                                   \
        asm volatile("cp.async.commit_group;" ::: "memory"); }

    const int ntile = Kk >> 5;
    LDGA(0); STSA(0);
    if (ntile > 1) LDGA(1);
    LOADB(0);
    int buf = 0;
    for (int t = 0; t < ntile; t++) {
        if (t + 1 < ntile) { LOADB(t + 1); STSA(buf ^ 1); }
        if (t + 2 < ntile) LDGA(t + 2);
        if (t + 1 < ntile) asm volatile("cp.async.wait_group 1;" ::: "memory");
        else               asm volatile("cp.async.wait_group 0;" ::: "memory");
        __syncthreads();
        const __half* Ab = smh + buf * TH_BUF;
        const __half* Bb = smh + (2 + buf) * TH_BUF;
#pragma unroll
        for (int kst = 0; kst < 2; kst++) {
            const int kb = kst * 16;
            uint32_t a[4][4], b[4][2];
#pragma unroll
            for (int mt = 0; mt < 4; mt++) {
                int mr = wm + mt * 16 + grp;
                a[mt][0] = *(const uint32_t*)(Ab + mr * TH_STRIDE + kb + tig * 2);
                a[mt][1] = *(const uint32_t*)(Ab + (mr + 8) * TH_STRIDE + kb + tig * 2);
                a[mt][2] = *(const uint32_t*)(Ab + mr * TH_STRIDE + kb + 8 + tig * 2);
                a[mt][3] = *(const uint32_t*)(Ab + (mr + 8) * TH_STRIDE + kb + 8 + tig * 2);
            }
#pragma unroll
            for (int nt = 0; nt < 4; nt++) {
                int nr = wn + nt * 8 + grp;
                b[nt][0] = *(const uint32_t*)(Bb + nr * TH_STRIDE + kb + tig * 2);
                b[nt][1] = *(const uint32_t*)(Bb + nr * TH_STRIDE + kb + 8 + tig * 2);
            }
#pragma unroll
            for (int mt = 0; mt < 4; mt++)
#pragma unroll
                for (int nt = 0; nt < 4; nt++)
                    mma_f16(acc[mt][nt], a[mt], b[nt]);
        }
        __syncthreads();
        buf ^= 1;
    }
#undef LDGA
#undef STSA
#undef LOADB

#pragma unroll
    for (int mt = 0; mt < 4; mt++) {
        int rbase = row0 + wm + mt * 16 + grp;
#pragma unroll
        for (int nt = 0; nt < 4; nt++) {
            int col = col0 + wn + nt * 8 + tig * 2;
            float2 bb = make_float2(0.f, 0.f);
            if (bias) bb = *(const float2*)(bias + col);
#pragma unroll
            for (int half = 0; half < 2; half++) {
                int row = rbase + half * 8;
                if (row >= M) continue;
                float v0 = acc[mt][nt][half * 2 + 0] + bb.x;
                float v1 = acc[mt][nt][half * 2 + 1] + bb.y;
                if (EPI == 1) {
                    v0 = v0 / (1.f + expf(1.f - v0));
                    v1 = v1 / (1.f + expf(1.f - v1));
                }
                if (EPI == 2) {
                    float2 rr = *(const float2*)(res + (size_t)row * Nn + col);
                    v0 += rr.x; v1 += rr.y;
                }
                *(float2*)(C + (size_t)row * Nn + col) = make_float2(v0, v1);
            }
        }
    }
}

// -------- tf32-MMA scores: total = (QU·KS^T + relshift(QV·PS^T)) * scal -------
#define SC_SMEM (12800 * (int)sizeof(float))   // 51200 bytes
__global__ __launch_bounds__(256) void scores_mma_kernel(
    const float* __restrict__ qkv, const float* __restrict__ p,
    const float* __restrict__ pu, const float* __restrict__ pv,
    float* __restrict__ total)
{
    extern __shared__ float sm[];
    float* QU  = sm;             // [64][36]
    float* QV  = sm + 2304;      // [64][36]
    float* KS  = sm + 4608;      // [64][36]
    float* PS  = sm + 6912;      // [128][36]
    float* ACs = sm;             // [64][68]  (phase 2)
    float* BDs = sm + 4352;      // [64][132] (phase 2)

    const int tid = threadIdx.x;
    const int nh = blockIdx.z;
    const int n = nh >> 3, h = nh & 7;
    const int l0 = blockIdx.y * 64;
    const int s0 = blockIdx.x * 64;
    const int mbase = (L_ - 64) - l0 + s0;

#pragma unroll
    for (int it = 0; it < 2; it++) {
        int u = tid + it * 256;
        int r = u >> 3, d4 = (u & 7) * 4;
        float4 qf = *(const float4*)(qkv + (size_t)((l0 + r) * NB + n) * 768 + h * 32 + d4);
        float4 uu = *(const float4*)(pu + h * 32 + d4);
        float4 vv = *(const float4*)(pv + h * 32 + d4);
        QU[r * 36 + d4 + 0] = qf.x + uu.x; QU[r * 36 + d4 + 1] = qf.y + uu.y;
        QU[r * 36 + d4 + 2] = qf.z + uu.z; QU[r * 36 + d4 + 3] = qf.w + uu.w;
        QV[r * 36 + d4 + 0] = qf.x + vv.x; QV[r * 36 + d4 + 1] = qf.y + vv.y;
        QV[r * 36 + d4 + 2] = qf.z + vv.z; QV[r * 36 + d4 + 3] = qf.w + vv.w;
        float4 kf = *(const float4*)(qkv + (size_t)((s0 + r) * NB + n) * 768 + 256 + h * 32 + d4);
        KS[r * 36 + d4 + 0] = kf.x; KS[r * 36 + d4 + 1] = kf.y;
        KS[r * 36 + d4 + 2] = kf.z; KS[r * 36 + d4 + 3] = kf.w;
    }
#pragma unroll
    for (int it = 0; it < 4; it++) {
        int u = tid + it * 256;
        int r = u >> 3, d4 = (u & 7) * 4;
        int m = mbase + r;
        float4 pf = make_float4(0.f, 0.f, 0.f, 0.f);
        if (m < PM) pf = *(const float4*)(p + (size_t)m * 256 + h * 32 + d4);
        PS[r * 36 + d4 + 0] = pf.x; PS[r * 36 + d4 + 1] = pf.y;
        PS[r * 36 + d4 + 2] = pf.z; PS[r * 36 + d4 + 3] = pf.w;
    }
    __syncthreads();

    const int wid = tid >> 5, lane = tid & 31;
    const int grp = lane >> 2, tig = lane & 3;
    const int wm = (wid >> 1) * 16;
    const int wnA = (wid & 1) * 32;
    const int wnB = (wid & 1) * 64;

    float acA[4][4] = {}, acB[8][4] = {};
#pragma unroll
    for (int k8 = 0; k8 < 4; k8++) {
        const int kb = k8 * 8;
        uint32_t aU[4], aV[4];
        aU[0] = f2tf(QU[(wm + grp) * 36 + kb + tig]);
        aU[1] = f2tf(QU[(wm + grp + 8) * 36 + kb + tig]);
        aU[2] = f2tf(QU[(wm + grp) * 36 + kb + tig + 4]);
        aU[3] = f2tf(QU[(wm + grp + 8) * 36 + kb + tig + 4]);
        aV[0] = f2tf(QV[(wm + grp) * 36 + kb + tig]);
        aV[1] = f2tf(QV[(wm + grp + 8) * 36 + kb + tig]);
        aV[2] = f2tf(QV[(wm + grp) * 36 + kb + tig + 4]);
        aV[3] = f2tf(QV[(wm + grp + 8) * 36 + kb + tig + 4]);
#pragma unroll
        for (int nt = 0; nt < 4; nt++) {
            int nr = wnA + nt * 8 + grp;
            uint32_t b[2] = { f2tf(KS[nr * 36 + kb + tig]), f2tf(KS[nr * 36 + kb + tig + 4]) };
            mma_tf32(acA[nt], aU, b);
        }
#pragma unroll
        for (int nt = 0; nt < 8; nt++) {
            int nr = wnB + nt * 8 + grp;
            uint32_t b[2] = { f2tf(PS[nr * 36 + kb + tig]), f2tf(PS[nr * 36 + kb + tig + 4]) };
            mma_tf32(acB[nt], aV, b);
        }
    }
    __syncthreads();

#pragma unroll
    for (int nt = 0; nt < 4; nt++) {
        int col = wnA + nt * 8 + tig * 2;
        *(float2*)&ACs[(wm + grp) * 68 + col]     = make_float2(acA[nt][0], acA[nt][1]);
        *(float2*)&ACs[(wm + grp + 8) * 68 + col] = make_float2(acA[nt][2], acA[nt][3]);
    }
#pragma unroll
    for (int nt = 0; nt < 8; nt++) {
        int col = wnB + nt * 8 + tig * 2;
        *(float2*)&BDs[(wm + grp) * 132 + col]     = make_float2(acB[nt][0], acB[nt][1]);
        *(float2*)&BDs[(wm + grp + 8) * 132 + col] = make_float2(acB[nt][2], acB[nt][3]);
    }
    __syncthreads();

    const float scal = 0.17677669529663687f;   // 1/sqrt(32)
    const int cc = (tid & 15) * 4;
    const int rb = tid >> 4;
#pragma unroll
    for (int it = 0; it < 4; it++) {
        int r = rb + it * 16;
        int off = 63 - r + cc;
        float4 o;
        o.x = (ACs[r * 68 + cc + 0] + BDs[r * 132 + off + 0]) * scal;
        o.y = (ACs[r * 68 + cc + 1] + BDs[r * 132 + off + 1]) * scal;
        o.z = (ACs[r * 68 + cc + 2] + BDs[r * 132 + off + 2]) * scal;
        o.w = (ACs[r * 68 + cc + 3] + BDs[r * 132 + off + 3]) * scal;
        *(float4*)(total + (((size_t)nh) << 20) + (size_t)(l0 + r) * L_ + s0 + cc) = o;
    }
}

// ---- fused proj_in + scores_out + softmax: one block per (n,l) row ------------
__global__ __launch_bounds__(256) void out_softmax_kernel(
    float* __restrict__ total, const float* __restrict__ asi,
    const float* __restrict__ projIn, const float* __restrict__ projOut,
    float* __restrict__ scores_out)
{
    __shared__ float ts[8][1028];
    __shared__ float pin[64], pout[64];
    __shared__ float red[8][8];
    const int tid = threadIdx.x;
    const int b = blockIdx.x;
    const int n = b >> 10, l = b & 1023;
    if (tid < 64) { pin[tid] = projIn[tid]; pout[tid] = projOut[tid]; }

#pragma unroll
    for (int h = 0; h < 8; h++) {
        float4 v = *(const float4*)(total + (((size_t)(n * 8 + h)) << 20)
                                          + ((size_t)l << 10) + tid * 4);
        *(float4*)&ts[h][tid * 4] = v;
    }
    __syncthreads();

    const int s = tid * 4;
    const size_t abase = ((size_t)n << 23) + ((size_t)l << 13) + ((size_t)s << 3);
    for (int js = 0; js < 4; js++) {
        float4 a0 = *(const float4*)(asi + abase + js * 8);
        float4 a1 = *(const float4*)(asi + abase + js * 8 + 4);
        float a[8] = {a0.x, a0.y, a0.z, a0.w, a1.x, a1.y, a1.z, a1.w};
        float tn8[8];
#pragma unroll
        for (int h = 0; h < 8; h++) {
            float t = ts[h][s + js];
#pragma unroll
            for (int g = 0; g < 8; g++) t = fmaf(a[g], pin[g * 8 + h], t);
            tn8[h] = t;
        }
        float o[8];
#pragma unroll
        for (int g = 0; g < 8; g++) {
            float sum = a[g];
#pragma unroll
            for (int h = 0; h < 8; h++) sum = fmaf(tn8[h], pout[h * 8 + g], sum);
            o[g] = sum;
        }
        *(float4*)(scores_out + abase + js * 8)     = make_float4(o[0], o[1], o[2], o[3]);
        *(float4*)(scores_out + abase + js * 8 + 4) = make_float4(o[4], o[5], o[6], o[7]);
#pragma unroll
        for (int h = 0; h < 8; h++) ts[h][s + js] = tn8[h];
    }

    float mh[8];
#pragma unroll
    for (int h = 0; h < 8; h++) {
        float m = fmaxf(fmaxf(ts[h][s], ts[h][s+1]), fmaxf(ts[h][s+2], ts[h][s+3]));
#pragma unroll
        for (int o = 16; o > 0; o >>= 1) m = fmaxf(m, __shfl_xor_sync(0xffffffffu, m, o));
        mh[h] = m;
    }
    if ((tid & 31) == 0)
#pragma unroll
        for (int h = 0; h < 8; h++) red[h][tid >> 5] = mh[h];
    __syncthreads();
#pragma unroll
    for (int h = 0; h < 8; h++) {
        float m = red[h][0];
#pragma unroll
        for (int w = 1; w < 8; w++) m = fmaxf(m, red[h][w]);
        mh[h] = m;
    }
    __syncthreads();

    float sh[8];
#pragma unroll
    for (int h = 0; h < 8; h++) {
        float s0 = 0.f;
#pragma unroll
        for (int js = 0; js < 4; js++) {
            float e = expf(ts[h][s + js] - mh[h]);
            ts[h][s + js] = e;
            s0 += e;
        }
#pragma unroll
        for (int o = 16; o > 0; o >>= 1) s0 += __shfl_xor_sync(0xffffffffu, s0, o);
        sh[h] = s0;
    }
    if ((tid & 31) == 0)
#pragma unroll
        for (int h = 0; h < 8; h++) red[h][tid >> 5] = sh[h];
    __syncthreads();
#pragma unroll
    for (int h = 0; h < 8; h++) {
        float ss = red[h][0] + red[h][1] + red[h][2] + red[h][3]
                 + red[h][4] + red[h][5] + red[h][6] + red[h][7];
        float inv = 1.f / ss;
        float4 o = make_float4(ts[h][s]*inv, ts[h][s+1]*inv, ts[h][s+2]*inv, ts[h][s+3]*inv);
        *(float4*)(total + (((size_t)(n * 8 + h)) << 20) + ((size_t)l << 10) + s) = o;
    }
}

// -------- ctx[l,n,h*32+d] = sum_s attn[n,h,l,s] * v[s,n,h,d] -------------------
__global__ __launch_bounds__(256) void av_kernel(
    const float* __restrict__ attn, const float* __restrict__ qkv,
    float* __restrict__ ctx)
{
    const int nh = blockIdx.y;
    const int n = nh >> 3, h = nh & 7;
    const int l0 = blockIdx.x * 64;
    __shared__ float As[64][65];
    __shared__ float Vs[64][33];
    const int tid = threadIdx.x;
    const int col = tid & 31;
    const int rg  = tid >> 5;
    float acc[8] = {};
    const float* Abase = attn + (((size_t)nh) << 20) + (((size_t)l0) << 10);
    for (int s0 = 0; s0 < 1024; s0 += 64) {
#pragma unroll
        for (int t = 0; t < 4; t++) {
            int f4 = tid + 256 * t;
            int r = f4 >> 4;
            int c4 = (f4 & 15) * 4;
            float4 v = *(const float4*)(Abase + (((size_t)r) << 10) + s0 + c4);
            As[r][c4] = v.x; As[r][c4 + 1] = v.y; As[r][c4 + 2] = v.z; As[r][c4 + 3] = v.w;
        }
#pragma unroll
        for (int t = 0; t < 8; t++) {
            int flat = tid + 256 * t;
            int r = flat >> 5, dd = flat & 31;
            Vs[r][dd] = qkv[(size_t)((s0 + r) * NB + n) * 768 + 512 + h * 32 + dd];
        }
        __syncthreads();
#pragma unroll
        for (int kk = 0; kk < 64; kk++) {
            float vv = Vs[kk][col];
#pragma unroll
            for (int i = 0; i < 8; i++)
                acc[i] = fmaf(As[rg * 8 + i][kk], vv, acc[i]);
        }
        __syncthreads();
    }
#pragma unroll
    for (int i = 0; i < 8; i++) {
        int l = l0 + rg * 8 + i;
        ctx[(size_t)(l * NB + n) * 256 + h * 32 + col] = acc[i];
    }
}

// -------- GLU with 32x32 smem transpose: y(l,n,:) -> hglu(n,c,l) ---------------
__global__ __launch_bounds__(256) void glu_t_kernel(
    const float* __restrict__ y, float* __restrict__ hglu)
{
    __shared__ float sm[32][33];
    const int l0 = blockIdx.x * 32, c0 = blockIdx.y * 32, n = blockIdx.z;
    const int li = threadIdx.x >> 3;
    const int c4 = (threadIdx.x & 7) * 4;
    size_t t = (size_t)(l0 + li) * NB + n;
    float4 a = *(const float4*)(y + t * 1024 + c0 + c4);
    float4 b = *(const float4*)(y + t * 1024 + c0 + c4 + 512);
    sm[c4 + 0][li] = a.x / (1.f + expf(-b.x));
    sm[c4 + 1][li] = a.y / (1.f + expf(-b.y));
    sm[c4 + 2][li] = a.z / (1.f + expf(-b.z));
    sm[c4 + 3][li] = a.w / (1.f + expf(-b.w));
    __syncthreads();
    const int c = threadIdx.x >> 3;
    const int l4 = (threadIdx.x & 7) * 4;
    float4 o = make_float4(sm[c][l4], sm[c][l4 + 1], sm[c][l4 + 2], sm[c][l4 + 3]);
    *(float4*)(hglu + (((size_t)(n * 512 + c0 + c)) << 10) + l0 + l4) = o;
}

// -------- depthwise conv(K=31) + bias + DoubleSwish, coalesced writes ---------
__global__ __launch_bounds__(256) void dwconv_kernel(
    const float* __restrict__ hglu, const float* __restrict__ w,
    const float* __restrict__ b, float* __restrict__ out)
{
    __shared__ float in_s[32 * 161];
    __shared__ float w_s[32 * 33];
    const int l0 = blockIdx.x * 128;
    const int c0 = blockIdx.y * 32;
    const int n  = blockIdx.z;

    for (int idx = threadIdx.x; idx < 32 * 160; idx += 256) {
        int row = idx / 160, col = idx % 160;
        int gl = l0 + col - 15;
        float v = 0.f;
        if (col < 158 && gl >= 0 && gl < L_)
            v = hglu[(((size_t)(n * 512 + c0 + row)) << 10) + gl];
        in_s[row * 161 + col] = v;
    }
    for (int idx = threadIdx.x; idx < 32 * KW; idx += 256) {
        int c = idx / KW, k = idx % KW;
        w_s[c * 33 + k] = w[(c0 + c) * KW + k];
    }
    __syncthreads();

    const int ci = threadIdx.x & 31;
    const int lq = threadIdx.x >> 5;
    const float bb = b[c0 + ci];
#pragma unroll
    for (int lt = 0; lt < 16; lt++) {
        int ll = lt * 8 + lq;
        float s = bb;
#pragma unroll
        for (int k = 0; k < KW; k++)
            s = fmaf(in_s[ci * 161 + ll + k], w_s[ci * 33 + k], s);
        float v = s / (1.f + expf(1.f - s));
        out[(((size_t)((l0 + ll) * NB + n)) << 9) + c0 + ci] = v;
    }
}

// -------- BasicNorm -> d_out ---------------------------------------------------
__global__ __launch_bounds__(128) void norm_kernel(
    const float* __restrict__ x, const float* __restrict__ leps,
    float* __restrict__ out)
{
    __shared__ float red[4];
    const size_t base = (size_t)blockIdx.x * 512;
    float4 v = ((const float4*)(x + base))[threadIdx.x];
    float ss = v.x * v.x + v.y * v.y + v.z * v.z + v.w * v.w;
#pragma unroll
    for (int o = 16; o > 0; o >>= 1) ss += __shfl_xor_sync(0xffffffffu, ss, o);
    if ((threadIdx.x & 31) == 0) red[threadIdx.x >> 5] = ss;
    __syncthreads();
    float tot = red[0] + red[1] + red[2] + red[3];
    float scale = rsqrtf(tot * (1.f / 512.f) + expf(leps[0]));
    ((float4*)(out + base))[threadIdx.x] =
        make_float4(v.x * scale, v.y * scale, v.z * scale, v.w * scale);
}

// ------------------------------- launcher -------------------------------------
extern "C" void kernel_launch(void* const* d_in, const int* in_sizes, int n_in,
                              void* d_out, int out_size)
{
    const float* src      = (const float*)d_in[0];
    const float* pos_emb  = (const float*)d_in[1];
    const float* asi      = (const float*)d_in[2];
    const float* w_in     = (const float*)d_in[3];
    const float* b_in     = (const float*)d_in[4];
    const float* w_pos    = (const float*)d_in[5];
    const float* pbu      = (const float*)d_in[6];
    const float* pbv      = (const float*)d_in[7];
    const float* projIn   = (const float*)d_in[8];
    const float* projOut  = (const float*)d_in[9];
    const float* w_out    = (const float*)d_in[10];
    const float* b_out    = (const float*)d_in[11];
    const float* w_ff1m   = (const float*)d_in[12];
    const float* b_ff1m   = (const float*)d_in[13];
    const float* w_ff2m   = (const float*)d_in[14];
    const float* b_ff2m   = (const float*)d_in[15];
    const float* w_ff1    = (const float*)d_in[16];
    const float* b_ff1    = (const float*)d_in[17];
    const float* w_ff2    = (const float*)d_in[18];
    const float* b_ff2    = (const float*)d_in[19];
    const float* w_pw1    = (const float*)d_in[20];
    const float* b_pw1    = (const float*)d_in[21];
    const float* w_dw     = (const float*)d_in[22];
    const float* b_dw     = (const float*)d_in[23];
    const float* w_pw2    = (const float*)d_in[24];
    const float* b_pw2    = (const float*)d_in[25];
    const float* leps     = (const float*)d_in[26];

    float* out        = (float*)d_out;
    float* out_scores = out + (size_t)TOK * E_;

    float *h1, *x, *qkv, *p, *total, *ctx, *x2, *y, *hglu, *hct, *x3, *x4;
    __half* whf;
    cudaGetSymbolAddress((void**)&h1,   g_h1);
    cudaGetSymbolAddress((void**)&x,    g_x);
    cudaGetSymbolAddress((void**)&qkv,  g_qkv);
    cudaGetSymbolAddress((void**)&p,    g_p);
    cudaGetSymbolAddress((void**)&total,g_total);
    cudaGetSymbolAddress((void**)&ctx,  g_ctx);
    cudaGetSymbolAddress((void**)&x2,   g_x2);
    cudaGetSymbolAddress((void**)&y,    g_y);
    cudaGetSymbolAddress((void**)&hglu, g_hglu);
    cudaGetSymbolAddress((void**)&hct,  g_hct);
    cudaGetSymbolAddress((void**)&x3,   g_x3);
    cudaGetSymbolAddress((void**)&x4,   g_x4);
    cudaGetSymbolAddress((void**)&whf,  g_whf);

    static bool attr_set = false;
    if (!attr_set) {
        cudaFuncSetAttribute(hgemm<0>, cudaFuncAttributeMaxDynamicSharedMemorySize, TH_SMEM);
        cudaFuncSetAttribute(hgemm<1>, cudaFuncAttributeMaxDynamicSharedMemorySize, TH_SMEM);
        cudaFuncSetAttribute(hgemm<2>, cudaFuncAttributeMaxDynamicSharedMemorySize, TH_SMEM);
        cudaFuncSetAttribute(scores_mma_kernel, cudaFuncAttributeMaxDynamicSharedMemorySize, SC_SMEM);
        attr_set = true;
    }

    // prepass: convert all B (weight) operands to fp16
    CvtArgs ca;
    ca.src[0] = w_ff1m; ca.dstoff[0] = OFF_FF1M; ca.n4[0] = (DFF_ * E_) / 4;
    ca.src[1] = w_ff2m; ca.dstoff[1] = OFF_FF2M; ca.n4[1] = (E_ * DFF_) / 4;
    ca.src[2] = w_in;   ca.dstoff[2] = OFF_IN;   ca.n4[2] = (768 * E_) / 4;
    ca.src[3] = w_pos;  ca.dstoff[3] = OFF_POS;  ca.n4[3] = (E2_ * E_) / 4;
    ca.src[4] = w_out;  ca.dstoff[4] = OFF_OUT;  ca.n4[4] = (E_ * E2_) / 4;
    ca.src[5] = w_pw1;  ca.dstoff[5] = OFF_PW1;  ca.n4[5] = (1024 * E_) / 4;
    ca.src[6] = w_pw2;  ca.dstoff[6] = OFF_PW2;  ca.n4[6] = (E_ * E_) / 4;
    ca.src[7] = w_ff1;  ca.dstoff[7] = OFF_FF1;  ca.n4[7] = (DFF_ * E_) / 4;
    ca.src[8] = w_ff2;  ca.dstoff[8] = OFF_FF2;  ca.n4[8] = (E_ * DFF_) / 4;
    cvtw_kernel<<<dim3(1024, 9), 256>>>(ca);

    // macaron FFN
    hgemm<1><<<dim3(DFF_ / 128, TOK / 128), 256, TH_SMEM>>>(src, whf + OFF_FF1M, b_ff1m, nullptr, h1, TOK, DFF_, E_);
    hgemm<2><<<dim3(E_ / 128, TOK / 128), 256, TH_SMEM>>>(h1, whf + OFF_FF2M, b_ff2m, src, x, TOK, E_, DFF_);

    // attention inputs
    hgemm<0><<<dim3(768 / 128, TOK / 128), 256, TH_SMEM>>>(x, whf + OFF_IN, b_in, nullptr, qkv, TOK, 768, E_);
    hgemm<0><<<dim3(2, 16), 256, TH_SMEM>>>(pos_emb, whf + OFF_POS, nullptr, nullptr, p, PM, 256, E_);

    // raw scores (tf32 MMA) -> fused proj_in + scores_out + softmax -> AV
    scores_mma_kernel<<<dim3(16, 16, 32), 256, SC_SMEM>>>(qkv, p, pbu, pbv, total);
    out_softmax_kernel<<<4096, 256>>>(total, asi, projIn, projOut, out_scores);
    av_kernel<<<dim3(16, 32), 256>>>(total, qkv, ctx);
    hgemm<2><<<dim3(E_ / 128, TOK / 128), 256, TH_SMEM>>>(ctx, whf + OFF_OUT, b_out, x, x2, TOK, E_, E2_);

    // conv module
    hgemm<0><<<dim3(1024 / 128, TOK / 128), 256, TH_SMEM>>>(x2, whf + OFF_PW1, b_pw1, nullptr, y, TOK, 1024, E_);
    glu_t_kernel<<<dim3(32, 16, NB), 256>>>(y, hglu);
    dwconv_kernel<<<dim3(8, 16, NB), 256>>>(hglu, w_dw, b_dw, hct);
    hgemm<2><<<dim3(E_ / 128, TOK / 128), 256, TH_SMEM>>>(hct, whf + OFF_PW2, b_pw2, x2, x3, TOK, E_, E_);

    // final FFN + BasicNorm
    hgemm<1><<<dim3(DFF_ / 128, TOK / 128), 256, TH_SMEM>>>(x3, whf + OFF_FF1, b_ff1, nullptr, h1, TOK, DFF_, E_);
    hgemm<2><<<dim3(E_ / 128, TOK / 128), 256, TH_SMEM>>>(h1, whf + OFF_FF2, b_ff2, x3, x4, TOK, E_, DFF_);
    norm_kernel<<<TOK, 128>>>(x4, leps, out);
}

// round 12
// speedup vs baseline: 1.1382x; 1.0951x over previous
#include <cuda_runtime.h>
#include <cuda_fp16.h>
#include <math.h>
#include <stdint.h>

#define L_    1024
#define NB    4
#define E_    512
#define H_    8
#define D_    32
#define DFF_  2048
#define E2_   256
#define TOK   4096      // L*NB
#define PM    2047      // 2L-1
#define KW    31

// ---------------- scratch (static device globals; no allocation) -------------
__device__ float g_h1[(size_t)TOK * DFF_];            // reused as __half for h1
__device__ float g_x[(size_t)TOK * E_];
__device__ float g_qkv[(size_t)TOK * 768];
__device__ float g_p[(size_t)2048 * 256];
__device__ float g_total[(size_t)32 * 1024 * 1024];   // (N,H,L,S) logits
__device__ __half g_attnh[(size_t)32 * 1024 * 1024];  // (N,H,L,S) probs fp16
__device__ float g_ctx[(size_t)TOK * E2_];
__device__ float g_x2[(size_t)TOK * E_];
__device__ float g_y[(size_t)TOK * 1024];
__device__ float g_hglu[(size_t)NB * E_ * L_];
__device__ float g_hct[(size_t)TOK * E_];
__device__ float g_x3[(size_t)TOK * E_];
__device__ float g_x4[(size_t)TOK * E_];
__device__ __half g_whf[(size_t)5636096];             // fp16 weights

// fp16 weight scratch offsets (elements)
#define OFF_FF1M 0
#define OFF_FF2M 1048576
#define OFF_IN   2097152
#define OFF_POS  2490368
#define OFF_OUT  2621440
#define OFF_PW1  2752512
#define OFF_PW2  3276800
#define OFF_FF1  3538944
#define OFF_FF2  4587520

// ---------------- helpers ------------------------------------------------------
__device__ __forceinline__ uint32_t f2tf(float f) {
    uint32_t u;
    asm("cvt.rna.tf32.f32 %0, %1;" : "=r"(u) : "f"(f));
    return u;
}
__device__ __forceinline__ void mma_tf32(float* c, const uint32_t* a, const uint32_t* b) {
    asm volatile(
        "mma.sync.aligned.m16n8k8.row.col.f32.tf32.tf32.f32 "
        "{%0,%1,%2,%3}, {%4,%5,%6,%7}, {%8,%9}, {%0,%1,%2,%3};"
        : "+f"(c[0]), "+f"(c[1]), "+f"(c[2]), "+f"(c[3])
        : "r"(a[0]), "r"(a[1]), "r"(a[2]), "r"(a[3]), "r"(b[0]), "r"(b[1]));
}
__device__ __forceinline__ void mma_f16(float* c, const uint32_t* a, const uint32_t* b) {
    asm volatile(
        "mma.sync.aligned.m16n8k16.row.col.f32.f16.f16.f32 "
        "{%0,%1,%2,%3}, {%4,%5,%6,%7}, {%8,%9}, {%0,%1,%2,%3};"
        : "+f"(c[0]), "+f"(c[1]), "+f"(c[2]), "+f"(c[3])
        : "r"(a[0]), "r"(a[1]), "r"(a[2]), "r"(a[3]), "r"(b[0]), "r"(b[1]));
}
__device__ __forceinline__ void cp16s(uint32_t daddr, const void* src) {
    asm volatile("cp.async.ca.shared.global [%0], [%1], 16;\n" :: "r"(daddr), "l"(src));
}
__device__ __forceinline__ uint32_t smem_u32(const void* p) {
    uint32_t a;
    asm("{ .reg .u64 t; cvta.to.shared.u64 t, %1; cvt.u32.u64 %0, t; }" : "=r"(a) : "l"(p));
    return a;
}
__device__ __forceinline__ uint32_t pack_h2(float x, float y) {
    __half2 h = __floats2half2_rn(x, y);
    return *(uint32_t*)&h;
}

// -------- prepass: convert 9 weight matrices to fp16 into g_whf ----------------
struct CvtArgs {
    const float* src[9];
    int dstoff[9];
    int n4[9];
};
__global__ __launch_bounds__(256) void cvtw_kernel(CvtArgs args) {
    const int wi = blockIdx.y;
    const int idx = blockIdx.x * 256 + threadIdx.x;
    if (idx >= args.n4[wi]) return;
    float4 v = *(const float4*)(args.src[wi] + (size_t)idx * 4);
    uint32_t lo = pack_h2(v.x, v.y);
    uint32_t hi = pack_h2(v.z, v.w);
    *(uint2*)(g_whf + args.dstoff[wi] + (size_t)idx * 4) = make_uint2(lo, hi);
}

// ------- cp.async double-buffered fp16 GEMM (8 warps, 64x32 warptile) ---------
// C = A(MxK) B(NxK)^T + bias (+epi). Nn % 128 == 0, Kk % 32 == 0.
// AH: 0 = A fp32 (LDG+cvt staging), 1 = A fp16 (cp.async).
// CH: 0 = C fp32, 1 = C fp16.
// EPI: 0 = bias; 1 = bias + DoubleSwish; 2 = bias + residual add
#define TH_STRIDE 40
#define TH_BUF    (128 * TH_STRIDE)     // halves per buffer
#define TH_SMEM   (4 * TH_BUF * 2)      // bytes = 40960
template <int EPI, int AH, int CH>
__global__ __launch_bounds__(256, 2) void hgemm(
    const void* __restrict__ Av, const __half* __restrict__ B,
    const float* __restrict__ bias, const float* __restrict__ res,
    void* __restrict__ Cv, int M, int Nn, int Kk)
{
    extern __shared__ __half smh[];
    const uint32_t smb = smem_u32(smh);
    const float*  A  = (const float*)Av;
    const __half* Ah = (const __half*)Av;
    float*  C  = (float*)Cv;
    __half* Ch = (__half*)Cv;

    const int tid   = threadIdx.x;
    const int wid   = tid >> 5;
    const int lane  = tid & 31;
    const int grp   = lane >> 2;
    const int tig   = lane & 3;
    const int row0  = blockIdx.y * 128;
    const int col0  = blockIdx.x * 128;
    const int wm    = (wid >> 2) * 64;   // 0 or 64
    const int wn    = (wid & 3) * 32;    // 0,32,64,96
    const int srow  = tid >> 1;          // 0..127 (staging row)
    const int shalf = (tid & 1) * 16;    // staging half-col base

    float acc[4][4][4];
#pragma unroll
    for (int mt = 0; mt < 4; mt++)
#pragma unroll
        for (int nt = 0; nt < 4; nt++)
#pragma unroll
            for (int q = 0; q < 4; q++) acc[mt][nt][q] = 0.f;

    float4 ast[4];
#define LDGA(t) {                                                               \
        int ar = row0 + srow; if (ar >= M) ar = M - 1;                          \
        const float* ap = A + (size_t)ar * Kk + (t) * 32 + shalf;               \
        _Pragma("unroll")                                                       \
        for (int i = 0; i < 4; i++) ast[i] = *(const float4*)(ap + i * 4); }
#define STSA(bf) {                                                              \
        __half* dst = smh + (bf) * TH_BUF + srow * TH_STRIDE + shalf;           \
        _Pragma("unroll")                                                       \
        for (int i = 0; i < 4; i++) {                                           \
            uint32_t h0 = pack_h2(ast[i].x, ast[i].y);                          \
            uint32_t h1 = pack_h2(ast[i].z, ast[i].w);                          \
            *(uint2*)(dst + i * 4) = make_uint2(h0, h1); } }
#define LOADA(t) {                                                              \
        uint32_t base = smb + (uint32_t)((((t) & 1) * TH_BUF + srow * TH_STRIDE) * 2); \
        int ar = row0 + srow; if (ar >= M) ar = M - 1;                          \
        const __half* ap = Ah + (size_t)ar * Kk + (t) * 32 + shalf;             \
        cp16s(base + shalf * 2,      ap);                                       \
        cp16s(base + shalf * 2 + 16, ap + 8); }
#define LOADB(t) {                                                              \
        uint32_t base = smb + (uint32_t)((2 + ((t) & 1)) * TH_BUF + srow * TH_STRIDE) * 2; \
        const __half* bp = B + (size_t)(col0 + srow) * Kk + (t) * 32 + shalf;   \
        cp16s(base + shalf * 2,      bp);                                       \
        cp16s(base + shalf * 2 + 16, bp + 8); }
#define COMMIT asm volatile("cp.async.commit_group;" ::: "memory")

    const int ntile = Kk >> 5;
    if (AH) { LOADA(0); }
    else    { LDGA(0); STSA(0); if (ntile > 1) LDGA(1); }
    LOADB(0); COMMIT;
    int buf = 0;
    for (int t = 0; t < ntile; t++) {
        if (t + 1 < ntile) {
            if (AH) LOADA(t + 1);
            LOADB(t + 1); COMMIT;
            if (!AH) { STSA(buf ^ 1); if (t + 2 < ntile) LDGA(t + 2); }
            asm volatile("cp.async.wait_group 1;" ::: "memory");
        } else {
            asm volatile("cp.async.wait_group 0;" ::: "memory");
        }
        __syncthreads();
        const __half* Ab = smh + buf * TH_BUF;
        const __half* Bb = smh + (2 + buf) * TH_BUF;
#pragma unroll
        for (int kst = 0; kst < 2; kst++) {
            const int kb = kst * 16;
            uint32_t a[4][4], b[4][2];
#pragma unroll
            for (int mt = 0; mt < 4; mt++) {
                int mr = wm + mt * 16 + grp;
                a[mt][0] = *(const uint32_t*)(Ab + mr * TH_STRIDE + kb + tig * 2);
                a[mt][1] = *(const uint32_t*)(Ab + (mr + 8) * TH_STRIDE + kb + tig * 2);
                a[mt][2] = *(const uint32_t*)(Ab + mr * TH_STRIDE + kb + 8 + tig * 2);
                a[mt][3] = *(const uint32_t*)(Ab + (mr + 8) * TH_STRIDE + kb + 8 + tig * 2);
            }
#pragma unroll
            for (int nt = 0; nt < 4; nt++) {
                int nr = wn + nt * 8 + grp;
                b[nt][0] = *(const uint32_t*)(Bb + nr * TH_STRIDE + kb + tig * 2);
                b[nt][1] = *(const uint32_t*)(Bb + nr * TH_STRIDE + kb + 8 + tig * 2);
            }
#pragma unroll
            for (int mt = 0; mt < 4; mt++)
#pragma unroll
                for (int nt = 0; nt < 4; nt++)
                    mma_f16(acc[mt][nt], a[mt], b[nt]);
        }
        __syncthreads();
        buf ^= 1;
    }
#undef LDGA
#undef STSA
#undef LOADA
#undef LOADB
#undef COMMIT

#pragma unroll
    for (int mt = 0; mt < 4; mt++) {
        int rbase = row0 + wm + mt * 16 + grp;
#pragma unroll
        for (int nt = 0; nt < 4; nt++) {
            int col = col0 + wn + nt * 8 + tig * 2;
            float2 bb = make_float2(0.f, 0.f);
            if (bias) bb = *(const float2*)(bias + col);
#pragma unroll
            for (int half = 0; half < 2; half++) {
                int row = rbase + half * 8;
                if (row >= M) continue;
                float v0 = acc[mt][nt][half * 2 + 0] + bb.x;
                float v1 = acc[mt][nt][half * 2 + 1] + bb.y;
                if (EPI == 1) {
                    v0 = v0 / (1.f + expf(1.f - v0));
                    v1 = v1 / (1.f + expf(1.f - v1));
                }
                if (EPI == 2) {
                    float2 rr = *(const float2*)(res + (size_t)row * Nn + col);
                    v0 += rr.x; v1 += rr.y;
                }
                if (CH) {
                    *(uint32_t*)(Ch + (size_t)row * Nn + col) = pack_h2(v0, v1);
                } else {
                    *(float2*)(C + (size_t)row * Nn + col) = make_float2(v0, v1);
                }
            }
        }
    }
}

// -------- tf32-MMA scores: total = (QU·KS^T + relshift(QV·PS^T)) * scal -------
#define SC_SMEM (12800 * (int)sizeof(float))   // 51200 bytes
__global__ __launch_bounds__(256) void scores_mma_kernel(
    const float* __restrict__ qkv, const float* __restrict__ p,
    const float* __restrict__ pu, const float* __restrict__ pv,
    float* __restrict__ total)
{
    extern __shared__ float sm[];
    float* QU  = sm;             // [64][36]
    float* QV  = sm + 2304;      // [64][36]
    float* KS  = sm + 4608;      // [64][36]
    float* PS  = sm + 6912;      // [128][36]
    float* ACs = sm;             // [64][68]  (phase 2)
    float* BDs = sm + 4352;      // [64][132] (phase 2)

    const int tid = threadIdx.x;
    const int nh = blockIdx.z;
    const int n = nh >> 3, h = nh & 7;
    const int l0 = blockIdx.y * 64;
    const int s0 = blockIdx.x * 64;
    const int mbase = (L_ - 64) - l0 + s0;

#pragma unroll
    for (int it = 0; it < 2; it++) {
        int u = tid + it * 256;
        int r = u >> 3, d4 = (u & 7) * 4;
        float4 qf = *(const float4*)(qkv + (size_t)((l0 + r) * NB + n) * 768 + h * 32 + d4);
        float4 uu = *(const float4*)(pu + h * 32 + d4);
        float4 vv = *(const float4*)(pv + h * 32 + d4);
        QU[r * 36 + d4 + 0] = qf.x + uu.x; QU[r * 36 + d4 + 1] = qf.y + uu.y;
        QU[r * 36 + d4 + 2] = qf.z + uu.z; QU[r * 36 + d4 + 3] = qf.w + uu.w;
        QV[r * 36 + d4 + 0] = qf.x + vv.x; QV[r * 36 + d4 + 1] = qf.y + vv.y;
        QV[r * 36 + d4 + 2] = qf.z + vv.z; QV[r * 36 + d4 + 3] = qf.w + vv.w;
        float4 kf = *(const float4*)(qkv + (size_t)((s0 + r) * NB + n) * 768 + 256 + h * 32 + d4);
        KS[r * 36 + d4 + 0] = kf.x; KS[r * 36 + d4 + 1] = kf.y;
        KS[r * 36 + d4 + 2] = kf.z; KS[r * 36 + d4 + 3] = kf.w;
    }
#pragma unroll
    for (int it = 0; it < 4; it++) {
        int u = tid + it * 256;
        int r = u >> 3, d4 = (u & 7) * 4;
        int m = mbase + r;
        float4 pf = make_float4(0.f, 0.f, 0.f, 0.f);
        if (m < PM) pf = *(const float4*)(p + (size_t)m * 256 + h * 32 + d4);
        PS[r * 36 + d4 + 0] = pf.x; PS[r * 36 + d4 + 1] = pf.y;
        PS[r * 36 + d4 + 2] = pf.z; PS[r * 36 + d4 + 3] = pf.w;
    }
    __syncthreads();

    const int wid = tid >> 5, lane = tid & 31;
    const int grp = lane >> 2, tig = lane & 3;
    const int wm = (wid >> 1) * 16;
    const int wnA = (wid & 1) * 32;
    const int wnB = (wid & 1) * 64;

    float acA[4][4] = {}, acB[8][4] = {};
#pragma unroll
    for (int k8 = 0; k8 < 4; k8++) {
        const int kb = k8 * 8;
        uint32_t aU[4], aV[4];
        aU[0] = f2tf(QU[(wm + grp) * 36 + kb + tig]);
        aU[1] = f2tf(QU[(wm + grp + 8) * 36 + kb + tig]);
        aU[2] = f2tf(QU[(wm + grp) * 36 + kb + tig + 4]);
        aU[3] = f2tf(QU[(wm + grp + 8) * 36 + kb + tig + 4]);
        aV[0] = f2tf(QV[(wm + grp) * 36 + kb + tig]);
        aV[1] = f2tf(QV[(wm + grp + 8) * 36 + kb + tig]);
        aV[2] = f2tf(QV[(wm + grp) * 36 + kb + tig + 4]);
        aV[3] = f2tf(QV[(wm + grp + 8) * 36 + kb + tig + 4]);
#pragma unroll
        for (int nt = 0; nt < 4; nt++) {
            int nr = wnA + nt * 8 + grp;
            uint32_t b[2] = { f2tf(KS[nr * 36 + kb + tig]), f2tf(KS[nr * 36 + kb + tig + 4]) };
            mma_tf32(acA[nt], aU, b);
        }
#pragma unroll
        for (int nt = 0; nt < 8; nt++) {
            int nr = wnB + nt * 8 + grp;
            uint32_t b[2] = { f2tf(PS[nr * 36 + kb + tig]), f2tf(PS[nr * 36 + kb + tig + 4]) };
            mma_tf32(acB[nt], aV, b);
        }
    }
    __syncthreads();

#pragma unroll
    for (int nt = 0; nt < 4; nt++) {
        int col = wnA + nt * 8 + tig * 2;
        *(float2*)&ACs[(wm + grp) * 68 + col]     = make_float2(acA[nt][0], acA[nt][1]);
        *(float2*)&ACs[(wm + grp + 8) * 68 + col] = make_float2(acA[nt][2], acA[nt][3]);
    }
#pragma unroll
    for (int nt = 0; nt < 8; nt++) {
        int col = wnB + nt * 8 + tig * 2;
        *(float2*)&BDs[(wm + grp) * 132 + col]     = make_float2(acB[nt][0], acB[nt][1]);
        *(float2*)&BDs[(wm + grp + 8) * 132 + col] = make_float2(acB[nt][2], acB[nt][3]);
    }
    __syncthreads();

    const float scal = 0.17677669529663687f;   // 1/sqrt(32)
    const int cc = (tid & 15) * 4;
    const int rb = tid >> 4;
#pragma unroll
    for (int it = 0; it < 4; it++) {
        int r = rb + it * 16;
        int off = 63 - r + cc;
        float4 o;
        o.x = (ACs[r * 68 + cc + 0] + BDs[r * 132 + off + 0]) * scal;
        o.y = (ACs[r * 68 + cc + 1] + BDs[r * 132 + off + 1]) * scal;
        o.z = (ACs[r * 68 + cc + 2] + BDs[r * 132 + off + 2]) * scal;
        o.w = (ACs[r * 68 + cc + 3] + BDs[r * 132 + off + 3]) * scal;
        *(float4*)(total + (((size_t)nh) << 20) + (size_t)(l0 + r) * L_ + s0 + cc) = o;
    }
}

// ---- fused proj_in + scores_out + softmax: one block per (n,l) row ------------
// attn probabilities written fp16 to attnh.
__global__ __launch_bounds__(256) void out_softmax_kernel(
    const float* __restrict__ total, const float* __restrict__ asi,
    const float* __restrict__ projIn, const float* __restrict__ projOut,
    float* __restrict__ scores_out, __half* __restrict__ attnh)
{
    __shared__ float ts[8][1028];
    __shared__ float pin[64], pout[64];
    __shared__ float red[8][8];
    const int tid = threadIdx.x;
    const int b = blockIdx.x;
    const int n = b >> 10, l = b & 1023;
    if (tid < 64) { pin[tid] = projIn[tid]; pout[tid] = projOut[tid]; }

#pragma unroll
    for (int h = 0; h < 8; h++) {
        float4 v = *(const float4*)(total + (((size_t)(n * 8 + h)) << 20)
                                          + ((size_t)l << 10) + tid * 4);
        *(float4*)&ts[h][tid * 4] = v;
    }
    __syncthreads();

    const int s = tid * 4;
    const size_t abase = ((size_t)n << 23) + ((size_t)l << 13) + ((size_t)s << 3);
    for (int js = 0; js < 4; js++) {
        float4 a0 = *(const float4*)(asi + abase + js * 8);
        float4 a1 = *(const float4*)(asi + abase + js * 8 + 4);
        float a[8] = {a0.x, a0.y, a0.z, a0.w, a1.x, a1.y, a1.z, a1.w};
        float tn8[8];
#pragma unroll
        for (int h = 0; h < 8; h++) {
            float t = ts[h][s + js];
#pragma unroll
            for (int g = 0; g < 8; g++) t = fmaf(a[g], pin[g * 8 + h], t);
            tn8[h] = t;
        }
        float o[8];
#pragma unroll
        for (int g = 0; g < 8; g++) {
            float sum = a[g];
#pragma unroll
            for (int h = 0; h < 8; h++) sum = fmaf(tn8[h], pout[h * 8 + g], sum);
            o[g] = sum;
        }
        *(float4*)(scores_out + abase + js * 8)     = make_float4(o[0], o[1], o[2], o[3]);
        *(float4*)(scores_out + abase + js * 8 + 4) = make_float4(o[4], o[5], o[6], o[7]);
#pragma unroll
        for (int h = 0; h < 8; h++) ts[h][s + js] = tn8[h];
    }

    float mh[8];
#pragma unroll
    for (int h = 0; h < 8; h++) {
        float m = fmaxf(fmaxf(ts[h][s], ts[h][s+1]), fmaxf(ts[h][s+2], ts[h][s+3]));
#pragma unroll
        for (int o = 16; o > 0; o >>= 1) m = fmaxf(m, __shfl_xor_sync(0xffffffffu, m, o));
        mh[h] = m;
    }
    if ((tid & 31) == 0)
#pragma unroll
        for (int h = 0; h < 8; h++) red[h][tid >> 5] = mh[h];
    __syncthreads();
#pragma unroll
    for (int h = 0; h < 8; h++) {
        float m = red[h][0];
#pragma unroll
        for (int w = 1; w < 8; w++) m = fmaxf(m, red[h][w]);
        mh[h] = m;
    }
    __syncthreads();

    float sh[8];
#pragma unroll
    for (int h = 0; h < 8; h++) {
        float s0 = 0.f;
#pragma unroll
        for (int js = 0; js < 4; js++) {
            float e = expf(ts[h][s + js] - mh[h]);
            ts[h][s + js] = e;
            s0 += e;
        }
#pragma unroll
        for (int o = 16; o > 0; o >>= 1) s0 += __shfl_xor_sync(0xffffffffu, s0, o);
        sh[h] = s0;
    }
    if ((tid & 31) == 0)
#pragma unroll
        for (int h = 0; h < 8; h++) red[h][tid >> 5] = sh[h];
    __syncthreads();
#pragma unroll
    for (int h = 0; h < 8; h++) {
        float ss = red[h][0] + red[h][1] + red[h][2] + red[h][3]
                 + red[h][4] + red[h][5] + red[h][6] + red[h][7];
        float inv = 1.f / ss;
        uint32_t h0 = pack_h2(ts[h][s] * inv, ts[h][s+1] * inv);
        uint32_t h1v = pack_h2(ts[h][s+2] * inv, ts[h][s+3] * inv);
        *(uint2*)(attnh + (((size_t)(n * 8 + h)) << 20) + ((size_t)l << 10) + s)
            = make_uint2(h0, h1v);
    }
}

// -------- av via fp16 MMA: ctx[l,n,h*32+d] = sum_s attn[n,h,l,s]*v[s,n,h,d] ---
__global__ __launch_bounds__(128) void av_kernel(
    const __half* __restrict__ attnh, const float* __restrict__ qkv,
    float* __restrict__ ctx)
{
    __shared__ __half As[64 * 136];
    __shared__ __half Vt[32 * 136];
    const int tid = threadIdx.x;
    const int wid = tid >> 5, lane = tid & 31;
    const int grp = lane >> 2, tig = lane & 3;
    const int nh = blockIdx.y;
    const int n = nh >> 3, h = nh & 7;
    const int l0 = blockIdx.x * 64;
    const uint32_t asb = smem_u32(As);
    const int wm = wid * 16;

    float acc[4][4];
#pragma unroll
    for (int nt = 0; nt < 4; nt++)
#pragma unroll
        for (int q = 0; q < 4; q++) acc[nt][q] = 0.f;

    const __half* abase = attnh + (((size_t)nh) << 20) + ((size_t)l0 << 10);

    for (int sc = 0; sc < 1024; sc += 128) {
        // attn tile 64x128 via cp.async
#pragma unroll
        for (int i = 0; i < 8; i++) {
            int idx = tid + 128 * i;
            int r = idx >> 4, c = idx & 15;
            cp16s(asb + (uint32_t)(r * 136 + c * 8) * 2,
                  abase + ((size_t)r << 10) + sc + c * 8);
        }
        asm volatile("cp.async.commit_group;" ::: "memory");
        // V tile: thread sr loads 32 floats, transpose-store to Vt[d][sr]
        {
            int sr = tid;
            const float* vp = qkv + (size_t)((sc + sr) * NB + n) * 768 + 512 + h * 32;
#pragma unroll
            for (int d4 = 0; d4 < 8; d4++) {
                float4 v = *(const float4*)(vp + d4 * 4);
                Vt[(d4 * 4 + 0) * 136 + sr] = __float2half_rn(v.x);
                Vt[(d4 * 4 + 1) * 136 + sr] = __float2half_rn(v.y);
                Vt[(d4 * 4 + 2) * 136 + sr] = __float2half_rn(v.z);
                Vt[(d4 * 4 + 3) * 136 + sr] = __float2half_rn(v.w);
            }
        }
        asm volatile("cp.async.wait_group 0;" ::: "memory");
        __syncthreads();
#pragma unroll
        for (int ks = 0; ks < 8; ks++) {
            const int kb = ks * 16;
            uint32_t a[4], b[4][2];
            a[0] = *(const uint32_t*)(As + (wm + grp) * 136 + kb + tig * 2);
            a[1] = *(const uint32_t*)(As + (wm + grp + 8) * 136 + kb + tig * 2);
            a[2] = *(const uint32_t*)(As + (wm + grp) * 136 + kb + 8 + tig * 2);
            a[3] = *(const uint32_t*)(As + (wm + grp + 8) * 136 + kb + 8 + tig * 2);
#pragma unroll
            for (int nt = 0; nt < 4; nt++) {
                int nr = nt * 8 + grp;
                b[nt][0] = *(const uint32_t*)(Vt + nr * 136 + kb + tig * 2);
                b[nt][1] = *(const uint32_t*)(Vt + nr * 136 + kb + 8 + tig * 2);
            }
#pragma unroll
            for (int nt = 0; nt < 4; nt++)
                mma_f16(acc[nt], a, b[nt]);
        }
        __syncthreads();
    }

#pragma unroll
    for (int nt = 0; nt < 4; nt++) {
        int d = nt * 8 + tig * 2;
#pragma unroll
        for (int half = 0; half < 2; half++) {
            int l = l0 + wm + grp + half * 8;
            *(float2*)(ctx + (size_t)(l * NB + n) * 256 + h * 32 + d)
                = make_float2(acc[nt][half * 2], acc[nt][half * 2 + 1]);
        }
    }
}

// -------- GLU with 32x32 smem transpose: y(l,n,:) -> hglu(n,c,l) ---------------
__global__ __launch_bounds__(256) void glu_t_kernel(
    const float* __restrict__ y, float* __restrict__ hglu)
{
    __shared__ float sm[32][33];
    const int l0 = blockIdx.x * 32, c0 = blockIdx.y * 32, n = blockIdx.z;
    const int li = threadIdx.x >> 3;
    const int c4 = (threadIdx.x & 7) * 4;
    size_t t = (size_t)(l0 + li) * NB + n;
    float4 a = *(const float4*)(y + t * 1024 + c0 + c4);
    float4 b = *(const float4*)(y + t * 1024 + c0 + c4 + 512);
    sm[c4 + 0][li] = a.x / (1.f + expf(-b.x));
    sm[c4 + 1][li] = a.y / (1.f + expf(-b.y));
    sm[c4 + 2][li] = a.z / (1.f + expf(-b.z));
    sm[c4 + 3][li] = a.w / (1.f + expf(-b.w));
    __syncthreads();
    const int c = threadIdx.x >> 3;
    const int l4 = (threadIdx.x & 7) * 4;
    float4 o = make_float4(sm[c][l4], sm[c][l4 + 1], sm[c][l4 + 2], sm[c][l4 + 3]);
    *(float4*)(hglu + (((size_t)(n * 512 + c0 + c)) << 10) + l0 + l4) = o;
}

// -------- depthwise conv(K=31) + bias + DoubleSwish, coalesced writes ---------
__global__ __launch_bounds__(256) void dwconv_kernel(
    const float* __restrict__ hglu, const float* __restrict__ w,
    const float* __restrict__ b, float* __restrict__ out)
{
    __shared__ float in_s[32 * 161];
    __shared__ float w_s[32 * 33];
    const int l0 = blockIdx.x * 128;
    const int c0 = blockIdx.y * 32;
    const int n  = blockIdx.z;

    for (int idx = threadIdx.x; idx < 32 * 160; idx += 256) {
        int row = idx / 160, col = idx % 160;
        int gl = l0 + col - 15;
        float v = 0.f;
        if (col < 158 && gl >= 0 && gl < L_)
            v = hglu[(((size_t)(n * 512 + c0 + row)) << 10) + gl];
        in_s[row * 161 + col] = v;
    }
    for (int idx = threadIdx.x; idx < 32 * KW; idx += 256) {
        int c = idx / KW, k = idx % KW;
        w_s[c * 33 + k] = w[(c0 + c) * KW + k];
    }
    __syncthreads();

    const int ci = threadIdx.x & 31;
    const int lq = threadIdx.x >> 5;
    const float bb = b[c0 + ci];
#pragma unroll
    for (int lt = 0; lt < 16; lt++) {
        int ll = lt * 8 + lq;
        float s = bb;
#pragma unroll
        for (int k = 0; k < KW; k++)
            s = fmaf(in_s[ci * 161 + ll + k], w_s[ci * 33 + k], s);
        float v = s / (1.f + expf(1.f - s));
        out[(((size_t)((l0 + ll) * NB + n)) << 9) + c0 + ci] = v;
    }
}

// -------- BasicNorm -> d_out ---------------------------------------------------
__global__ __launch_bounds__(128) void norm_kernel(
    const float* __restrict__ x, const float* __restrict__ leps,
    float* __restrict__ out)
{
    __shared__ float red[4];
    const size_t base = (size_t)blockIdx.x * 512;
    float4 v = ((const float4*)(x + base))[threadIdx.x];
    float ss = v.x * v.x + v.y * v.y + v.z * v.z + v.w * v.w;
#pragma unroll
    for (int o = 16; o > 0; o >>= 1) ss += __shfl_xor_sync(0xffffffffu, ss, o);
    if ((threadIdx.x & 31) == 0) red[threadIdx.x >> 5] = ss;
    __syncthreads();
    float tot = red[0] + red[1] + red[2] + red[3];
    float scale = rsqrtf(tot * (1.f / 512.f) + expf(leps[0]));
    ((float4*)(out + base))[threadIdx.x] =
        make_float4(v.x * scale, v.y * scale, v.z * scale, v.w * scale);
}

// ------------------------------- launcher -------------------------------------
extern "C" void kernel_launch(void* const* d_in, const int* in_sizes, int n_in,
                              void* d_out, int out_size)
{
    const float* src      = (const float*)d_in[0];
    const float* pos_emb  = (const float*)d_in[1];
    const float* asi      = (const float*)d_in[2];
    const float* w_in     = (const float*)d_in[3];
    const float* b_in     = (const float*)d_in[4];
    const float* w_pos    = (const float*)d_in[5];
    const float* pbu      = (const float*)d_in[6];
    const float* pbv      = (const float*)d_in[7];
    const float* projIn   = (const float*)d_in[8];
    const float* projOut  = (const float*)d_in[9];
    const float* w_out    = (const float*)d_in[10];
    const float* b_out    = (const float*)d_in[11];
    const float* w_ff1m   = (const float*)d_in[12];
    const float* b_ff1m   = (const float*)d_in[13];
    const float* w_ff2m   = (const float*)d_in[14];
    const float* b_ff2m   = (const float*)d_in[15];
    const float* w_ff1    = (const float*)d_in[16];
    const float* b_ff1    = (const float*)d_in[17];
    const float* w_ff2    = (const float*)d_in[18];
    const float* b_ff2    = (const float*)d_in[19];
    const float* w_pw1    = (const float*)d_in[20];
    const float* b_pw1    = (const float*)d_in[21];
    const float* w_dw     = (const float*)d_in[22];
    const float* b_dw     = (const float*)d_in[23];
    const float* w_pw2    = (const float*)d_in[24];
    const float* b_pw2    = (const float*)d_in[25];
    const float* leps     = (const float*)d_in[26];

    float* out        = (float*)d_out;
    float* out_scores = out + (size_t)TOK * E_;

    float *h1, *x, *qkv, *p, *total, *ctx, *x2, *y, *hglu, *hct, *x3, *x4;
    __half *whf, *attnh;
    cudaGetSymbolAddress((void**)&h1,   g_h1);
    cudaGetSymbolAddress((void**)&x,    g_x);
    cudaGetSymbolAddress((void**)&qkv,  g_qkv);
    cudaGetSymbolAddress((void**)&p,    g_p);
    cudaGetSymbolAddress((void**)&total,g_total);
    cudaGetSymbolAddress((void**)&ctx,  g_ctx);
    cudaGetSymbolAddress((void**)&x2,   g_x2);
    cudaGetSymbolAddress((void**)&y,    g_y);
    cudaGetSymbolAddress((void**)&hglu, g_hglu);
    cudaGetSymbolAddress((void**)&hct,  g_hct);
    cudaGetSymbolAddress((void**)&x3,   g_x3);
    cudaGetSymbolAddress((void**)&x4,   g_x4);
    cudaGetSymbolAddress((void**)&whf,  g_whf);
    cudaGetSymbolAddress((void**)&attnh,g_attnh);
    __half* h1h = (__half*)h1;

    static bool attr_set = false;
    if (!attr_set) {
        cudaFuncSetAttribute(hgemm<0,0,0>, cudaFuncAttributeMaxDynamicSharedMemorySize, TH_SMEM);
        cudaFuncSetAttribute(hgemm<1,0,1>, cudaFuncAttributeMaxDynamicSharedMemorySize, TH_SMEM);
        cudaFuncSetAttribute(hgemm<2,1,0>, cudaFuncAttributeMaxDynamicSharedMemorySize, TH_SMEM);
        cudaFuncSetAttribute(hgemm<2,0,0>, cudaFuncAttributeMaxDynamicSharedMemorySize, TH_SMEM);
        cudaFuncSetAttribute(scores_mma_kernel, cudaFuncAttributeMaxDynamicSharedMemorySize, SC_SMEM);
        attr_set = true;
    }

    // prepass: convert all B (weight) operands to fp16
    CvtArgs ca;
    ca.src[0] = w_ff1m; ca.dstoff[0] = OFF_FF1M; ca.n4[0] = (DFF_ * E_) / 4;
    ca.src[1] = w_ff2m; ca.dstoff[1] = OFF_FF2M; ca.n4[1] = (E_ * DFF_) / 4;
    ca.src[2] = w_in;   ca.dstoff[2] = OFF_IN;   ca.n4[2] = (768 * E_) / 4;
    ca.src[3] = w_pos;  ca.dstoff[3] = OFF_POS;  ca.n4[3] = (E2_ * E_) / 4;
    ca.src[4] = w_out;  ca.dstoff[4] = OFF_OUT;  ca.n4[4] = (E_ * E2_) / 4;
    ca.src[5] = w_pw1;  ca.dstoff[5] = OFF_PW1;  ca.n4[5] = (1024 * E_) / 4;
    ca.src[6] = w_pw2;  ca.dstoff[6] = OFF_PW2;  ca.n4[6] = (E_ * E_) / 4;
    ca.src[7] = w_ff1;  ca.dstoff[7] = OFF_FF1;  ca.n4[7] = (DFF_ * E_) / 4;
    ca.src[8] = w_ff2;  ca.dstoff[8] = OFF_FF2;  ca.n4[8] = (E_ * DFF_) / 4;
    cvtw_kernel<<<dim3(1024, 9), 256>>>(ca);

    // macaron FFN (h1 stored fp16; FF2 consumes fp16 A via cp.async)
    hgemm<1,0,1><<<dim3(DFF_ / 128, TOK / 128), 256, TH_SMEM>>>(src, whf + OFF_FF1M, b_ff1m, nullptr, h1h, TOK, DFF_, E_);
    hgemm<2,1,0><<<dim3(E_ / 128, TOK / 128), 256, TH_SMEM>>>(h1h, whf + OFF_FF2M, b_ff2m, src, x, TOK, E_, DFF_);

    // attention inputs
    hgemm<0,0,0><<<dim3(768 / 128, TOK / 128), 256, TH_SMEM>>>(x, whf + OFF_IN, b_in, nullptr, qkv, TOK, 768, E_);
    hgemm<0,0,0><<<dim3(2, 16), 256, TH_SMEM>>>(pos_emb, whf + OFF_POS, nullptr, nullptr, p, PM, 256, E_);

    // scores -> fused proj_in + scores_out + softmax (attn fp16) -> AV (fp16 mma)
    scores_mma_kernel<<<dim3(16, 16, 32), 256, SC_SMEM>>>(qkv, p, pbu, pbv, total);
    out_softmax_kernel<<<4096, 256>>>(total, asi, projIn, projOut, out_scores, attnh);
    av_kernel<<<dim3(16, 32), 128>>>(attnh, qkv, ctx);
    hgemm<2,0,0><<<dim3(E_ / 128, TOK / 128), 256, TH_SMEM>>>(ctx, whf + OFF_OUT, b_out, x, x2, TOK, E_, E2_);

    // conv module
    hgemm<0,0,0><<<dim3(1024 / 128, TOK / 128), 256, TH_SMEM>>>(x2, whf + OFF_PW1, b_pw1, nullptr, y, TOK, 1024, E_);
    glu_t_kernel<<<dim3(32, 16, NB), 256>>>(y, hglu);
    dwconv_kernel<<<dim3(8, 16, NB), 256>>>(hglu, w_dw, b_dw, hct);
    hgemm<2,0,0><<<dim3(E_ / 128, TOK / 128), 256, TH_SMEM>>>(hct, whf + OFF_PW2, b_pw2, x2, x3, TOK, E_, E_);

    // final FFN + BasicNorm
    hgemm<1,0,1><<<dim3(DFF_ / 128, TOK / 128), 256, TH_SMEM>>>(x3, whf + OFF_FF1, b_ff1, nullptr, h1h, TOK, DFF_, E_);
    hgemm<2,1,0><<<dim3(E_ / 128, TOK / 128), 256, TH_SMEM>>>(h1h, whf + OFF_FF2, b_ff2, x3, x4, TOK, E_, DFF_);
    norm_kernel<<<TOK, 128>>>(x4, leps, out);
}

// round 13
// speedup vs baseline: 1.1628x; 1.0216x over previous
#include <cuda_runtime.h>
#include <cuda_fp16.h>
#include <math.h>
#include <stdint.h>

#define L_    1024
#define NB    4
#define E_    512
#define H_    8
#define D_    32
#define DFF_  2048
#define E2_   256
#define TOK   4096      // L*NB
#define PM    2047      // 2L-1
#define KW    31

// ---------------- scratch (static device globals; no allocation) -------------
__device__ float g_h1[(size_t)TOK * DFF_];            // reused as __half for h1
__device__ float g_x[(size_t)TOK * E_];
__device__ float g_qkv[(size_t)TOK * 768];
__device__ float g_p[(size_t)2048 * 256];
__device__ float g_total[(size_t)32 * 1024 * 1024];   // (N,H,L,S) logits
__device__ __half g_attnh[(size_t)32 * 1024 * 1024];  // (N,H,L,S) probs fp16
__device__ float g_ctx[(size_t)TOK * E2_];
__device__ float g_x2[(size_t)TOK * E_];
__device__ float g_y[(size_t)TOK * 1024];
__device__ float g_hct[(size_t)TOK * E_];
__device__ float g_x3[(size_t)TOK * E_];
__device__ float g_x4[(size_t)TOK * E_];
__device__ __half g_whf[(size_t)5636096];             // fp16 weights

// fp16 weight scratch offsets (elements)
#define OFF_FF1M 0
#define OFF_FF2M 1048576
#define OFF_IN   2097152
#define OFF_POS  2490368
#define OFF_OUT  2621440
#define OFF_PW1  2752512
#define OFF_PW2  3276800
#define OFF_FF1  3538944
#define OFF_FF2  4587520

// ---------------- helpers ------------------------------------------------------
__device__ __forceinline__ uint32_t f2tf(float f) {
    uint32_t u;
    asm("cvt.rna.tf32.f32 %0, %1;" : "=r"(u) : "f"(f));
    return u;
}
__device__ __forceinline__ void mma_tf32(float* c, const uint32_t* a, const uint32_t* b) {
    asm volatile(
        "mma.sync.aligned.m16n8k8.row.col.f32.tf32.tf32.f32 "
        "{%0,%1,%2,%3}, {%4,%5,%6,%7}, {%8,%9}, {%0,%1,%2,%3};"
        : "+f"(c[0]), "+f"(c[1]), "+f"(c[2]), "+f"(c[3])
        : "r"(a[0]), "r"(a[1]), "r"(a[2]), "r"(a[3]), "r"(b[0]), "r"(b[1]));
}
__device__ __forceinline__ void mma_f16(float* c, const uint32_t* a, const uint32_t* b) {
    asm volatile(
        "mma.sync.aligned.m16n8k16.row.col.f32.f16.f16.f32 "
        "{%0,%1,%2,%3}, {%4,%5,%6,%7}, {%8,%9}, {%0,%1,%2,%3};"
        : "+f"(c[0]), "+f"(c[1]), "+f"(c[2]), "+f"(c[3])
        : "r"(a[0]), "r"(a[1]), "r"(a[2]), "r"(a[3]), "r"(b[0]), "r"(b[1]));
}
__device__ __forceinline__ void cp16s(uint32_t daddr, const void* src) {
    asm volatile("cp.async.ca.shared.global [%0], [%1], 16;\n" :: "r"(daddr), "l"(src));
}
__device__ __forceinline__ uint32_t smem_u32(const void* p) {
    uint32_t a;
    asm("{ .reg .u64 t; cvta.to.shared.u64 t, %1; cvt.u32.u64 %0, t; }" : "=r"(a) : "l"(p));
    return a;
}
__device__ __forceinline__ uint32_t pack_h2(float x, float y) {
    __half2 h = __floats2half2_rn(x, y);
    return *(uint32_t*)&h;
}

// -------- prepass: convert 9 weight matrices to fp16 into g_whf ----------------
struct CvtArgs {
    const float* src[9];
    int dstoff[9];
    int n4[9];
};
__global__ __launch_bounds__(256) void cvtw_kernel(CvtArgs args) {
    const int wi = blockIdx.y;
    const int idx = blockIdx.x * 256 + threadIdx.x;
    if (idx >= args.n4[wi]) return;
    float4 v = *(const float4*)(args.src[wi] + (size_t)idx * 4);
    uint32_t lo = pack_h2(v.x, v.y);
    uint32_t hi = pack_h2(v.z, v.w);
    *(uint2*)(g_whf + args.dstoff[wi] + (size_t)idx * 4) = make_uint2(lo, hi);
}

// ------- cp.async double-buffered fp16 GEMM, MT-row CTA tile ------------------
// C = A(MxK) B(NxK)^T + bias (+epi). Nn % 128 == 0, Kk % 32 == 0.
// AH: 0 = A fp32 (LDG+cvt staging), 1 = A fp16 (cp.async). CH: C fp32/fp16.
// MT: CTA rows (128 or 64). EPI: 0 bias; 1 bias+DoubleSwish; 2 bias+residual.
#define TH_STRIDE 40
#define TH_SMEM_MT(MT) ((2 * (MT) * TH_STRIDE + 2 * 128 * TH_STRIDE) * 2)
template <int EPI, int AH, int CH, int MT>
__global__ __launch_bounds__(256, 2) void hgemm(
    const void* __restrict__ Av, const __half* __restrict__ B,
    const float* __restrict__ bias, const float* __restrict__ res,
    void* __restrict__ Cv, int M, int Nn, int Kk)
{
    extern __shared__ __half smh[];
    const uint32_t smb = smem_u32(smh);
    const float*  A  = (const float*)Av;
    const __half* Ah = (const __half*)Av;
    float*  C  = (float*)Cv;
    __half* Ch = (__half*)Cv;

    constexpr int TPR  = 256 / MT;        // staging threads per A row (2 or 4)
    constexpr int CHK  = 32 / TPR;        // halves per thread (16 or 8)
    constexpr int ABUF = MT * TH_STRIDE;  // halves per A buffer
    constexpr int BBUF = 128 * TH_STRIDE;
    constexpr int MTS  = MT / 32;         // m-subtiles per warp (4 or 2)

    const int tid   = threadIdx.x;
    const int wid   = tid >> 5;
    const int lane  = tid & 31;
    const int grp   = lane >> 2;
    const int tig   = lane & 3;
    const int row0  = blockIdx.y * MT;
    const int col0  = blockIdx.x * 128;
    const int wm    = (wid >> 2) * (MT / 2);
    const int wn    = (wid & 3) * 32;
    const int srow  = tid / TPR;
    const int scol  = (tid % TPR) * CHK;
    const int brow  = tid >> 1;
    const int bcol  = (tid & 1) * 16;

    float acc[MTS][4][4];
#pragma unroll
    for (int mt = 0; mt < MTS; mt++)
#pragma unroll
        for (int nt = 0; nt < 4; nt++)
#pragma unroll
            for (int q = 0; q < 4; q++) acc[mt][nt][q] = 0.f;

    float4 ast[CHK / 4];
#define LDGA(t) {                                                               \
        int ar = row0 + srow; if (ar >= M) ar = M - 1;                          \
        const float* ap = A + (size_t)ar * Kk + (t) * 32 + scol;                \
        _Pragma("unroll")                                                       \
        for (int i = 0; i < CHK / 4; i++) ast[i] = *(const float4*)(ap + i * 4); }
#define STSA(bf) {                                                              \
        __half* dst = smh + (bf) * ABUF + srow * TH_STRIDE + scol;              \
        _Pragma("unroll")                                                       \
        for (int i = 0; i < CHK / 4; i++) {                                     \
            uint32_t h0 = pack_h2(ast[i].x, ast[i].y);                          \
            uint32_t h1 = pack_h2(ast[i].z, ast[i].w);                          \
            *(uint2*)(dst + i * 4) = make_uint2(h0, h1); } }
#define LOADA(t) {                                                              \
        uint32_t base = smb + (uint32_t)(((t & 1) * ABUF + srow * TH_STRIDE + scol) * 2); \
        int ar = row0 + srow; if (ar >= M) ar = M - 1;                          \
        const __half* ap = Ah + (size_t)ar * Kk + (t) * 32 + scol;              \
        cp16s(base, ap);                                                        \
        if (CHK == 16) cp16s(base + 16, ap + 8); }
#define LOADB(t) {                                                              \
        uint32_t base = smb + (uint32_t)((2 * ABUF + ((t) & 1) * BBUF + brow * TH_STRIDE + bcol) * 2); \
        const __half* bp = B + (size_t)(col0 + brow) * Kk + (t) * 32 + bcol;    \
        cp16s(base,      bp);                                                   \
        cp16s(base + 16, bp + 8); }
#define COMMIT asm volatile("cp.async.commit_group;" ::: "memory")

    const int ntile = Kk >> 5;
    if (AH) { LOADA(0); }
    else    { LDGA(0); STSA(0); if (ntile > 1) LDGA(1); }
    LOADB(0); COMMIT;
    int buf = 0;
    for (int t = 0; t < ntile; t++) {
        if (t + 1 < ntile) {
            if (AH) LOADA(t + 1);
            LOADB(t + 1); COMMIT;
            if (!AH) { STSA(buf ^ 1); if (t + 2 < ntile) LDGA(t + 2); }
            asm volatile("cp.async.wait_group 1;" ::: "memory");
        } else {
            asm volatile("cp.async.wait_group 0;" ::: "memory");
        }
        __syncthreads();
        const __half* Ab = smh + buf * ABUF;
        const __half* Bb = smh + 2 * ABUF + buf * BBUF;
#pragma unroll
        for (int kst = 0; kst < 2; kst++) {
            const int kb = kst * 16;
            uint32_t a[MTS][4], b[4][2];
#pragma unroll
            for (int mt = 0; mt < MTS; mt++) {
                int mr = wm + mt * 16 + grp;
                a[mt][0] = *(const uint32_t*)(Ab + mr * TH_STRIDE + kb + tig * 2);
                a[mt][1] = *(const uint32_t*)(Ab + (mr + 8) * TH_STRIDE + kb + tig * 2);
                a[mt][2] = *(const uint32_t*)(Ab + mr * TH_STRIDE + kb + 8 + tig * 2);
                a[mt][3] = *(const uint32_t*)(Ab + (mr + 8) * TH_STRIDE + kb + 8 + tig * 2);
            }
#pragma unroll
            for (int nt = 0; nt < 4; nt++) {
                int nr = wn + nt * 8 + grp;
                b[nt][0] = *(const uint32_t*)(Bb + nr * TH_STRIDE + kb + tig * 2);
                b[nt][1] = *(const uint32_t*)(Bb + nr * TH_STRIDE + kb + 8 + tig * 2);
            }
#pragma unroll
            for (int mt = 0; mt < MTS; mt++)
#pragma unroll
                for (int nt = 0; nt < 4; nt++)
                    mma_f16(acc[mt][nt], a[mt], b[nt]);
        }
        __syncthreads();
        buf ^= 1;
    }
#undef LDGA
#undef STSA
#undef LOADA
#undef LOADB
#undef COMMIT

#pragma unroll
    for (int mt = 0; mt < MTS; mt++) {
        int rbase = row0 + wm + mt * 16 + grp;
#pragma unroll
        for (int nt = 0; nt < 4; nt++) {
            int col = col0 + wn + nt * 8 + tig * 2;
            float2 bb = make_float2(0.f, 0.f);
            if (bias) bb = *(const float2*)(bias + col);
#pragma unroll
            for (int half = 0; half < 2; half++) {
                int row = rbase + half * 8;
                if (row >= M) continue;
                float v0 = acc[mt][nt][half * 2 + 0] + bb.x;
                float v1 = acc[mt][nt][half * 2 + 1] + bb.y;
                if (EPI == 1) {
                    v0 = v0 / (1.f + expf(1.f - v0));
                    v1 = v1 / (1.f + expf(1.f - v1));
                }
                if (EPI == 2) {
                    float2 rr = *(const float2*)(res + (size_t)row * Nn + col);
                    v0 += rr.x; v1 += rr.y;
                }
                if (CH) {
                    *(uint32_t*)(Ch + (size_t)row * Nn + col) = pack_h2(v0, v1);
                } else {
                    *(float2*)(C + (size_t)row * Nn + col) = make_float2(v0, v1);
                }
            }
        }
    }
}

// -------- tf32-MMA scores: total = (QU·KS^T + relshift(QV·PS^T)) * scal -------
#define SC_SMEM (12800 * (int)sizeof(float))   // 51200 bytes
__global__ __launch_bounds__(256) void scores_mma_kernel(
    const float* __restrict__ qkv, const float* __restrict__ p,
    const float* __restrict__ pu, const float* __restrict__ pv,
    float* __restrict__ total)
{
    extern __shared__ float sm[];
    float* QU  = sm;             // [64][36]
    float* QV  = sm + 2304;      // [64][36]
    float* KS  = sm + 4608;      // [64][36]
    float* PS  = sm + 6912;      // [128][36]
    float* ACs = sm;             // [64][68]  (phase 2)
    float* BDs = sm + 4352;      // [64][132] (phase 2)

    const int tid = threadIdx.x;
    const int nh = blockIdx.z;
    const int n = nh >> 3, h = nh & 7;
    const int l0 = blockIdx.y * 64;
    const int s0 = blockIdx.x * 64;
    const int mbase = (L_ - 64) - l0 + s0;

#pragma unroll
    for (int it = 0; it < 2; it++) {
        int u = tid + it * 256;
        int r = u >> 3, d4 = (u & 7) * 4;
        float4 qf = *(const float4*)(qkv + (size_t)((l0 + r) * NB + n) * 768 + h * 32 + d4);
        float4 uu = *(const float4*)(pu + h * 32 + d4);
        float4 vv = *(const float4*)(pv + h * 32 + d4);
        QU[r * 36 + d4 + 0] = qf.x + uu.x; QU[r * 36 + d4 + 1] = qf.y + uu.y;
        QU[r * 36 + d4 + 2] = qf.z + uu.z; QU[r * 36 + d4 + 3] = qf.w + uu.w;
        QV[r * 36 + d4 + 0] = qf.x + vv.x; QV[r * 36 + d4 + 1] = qf.y + vv.y;
        QV[r * 36 + d4 + 2] = qf.z + vv.z; QV[r * 36 + d4 + 3] = qf.w + vv.w;
        float4 kf = *(const float4*)(qkv + (size_t)((s0 + r) * NB + n) * 768 + 256 + h * 32 + d4);
        KS[r * 36 + d4 + 0] = kf.x; KS[r * 36 + d4 + 1] = kf.y;
        KS[r * 36 + d4 + 2] = kf.z; KS[r * 36 + d4 + 3] = kf.w;
    }
#pragma unroll
    for (int it = 0; it < 4; it++) {
        int u = tid + it * 256;
        int r = u >> 3, d4 = (u & 7) * 4;
        int m = mbase + r;
        float4 pf = make_float4(0.f, 0.f, 0.f, 0.f);
        if (m < PM) pf = *(const float4*)(p + (size_t)m * 256 + h * 32 + d4);
        PS[r * 36 + d4 + 0] = pf.x; PS[r * 36 + d4 + 1] = pf.y;
        PS[r * 36 + d4 + 2] = pf.z; PS[r * 36 + d4 + 3] = pf.w;
    }
    __syncthreads();

    const int wid = tid >> 5, lane = tid & 31;
    const int grp = lane >> 2, tig = lane & 3;
    const int wm = (wid >> 1) * 16;
    const int wnA = (wid & 1) * 32;
    const int wnB = (wid & 1) * 64;

    float acA[4][4] = {}, acB[8][4] = {};
#pragma unroll
    for (int k8 = 0; k8 < 4; k8++) {
        const int kb = k8 * 8;
        uint32_t aU[4], aV[4];
        aU[0] = f2tf(QU[(wm + grp) * 36 + kb + tig]);
        aU[1] = f2tf(QU[(wm + grp + 8) * 36 + kb + tig]);
        aU[2] = f2tf(QU[(wm + grp) * 36 + kb + tig + 4]);
        aU[3] = f2tf(QU[(wm + grp + 8) * 36 + kb + tig + 4]);
        aV[0] = f2tf(QV[(wm + grp) * 36 + kb + tig]);
        aV[1] = f2tf(QV[(wm + grp + 8) * 36 + kb + tig]);
        aV[2] = f2tf(QV[(wm + grp) * 36 + kb + tig + 4]);
        aV[3] = f2tf(QV[(wm + grp + 8) * 36 + kb + tig + 4]);
#pragma unroll
        for (int nt = 0; nt < 4; nt++) {
            int nr = wnA + nt * 8 + grp;
            uint32_t b[2] = { f2tf(KS[nr * 36 + kb + tig]), f2tf(KS[nr * 36 + kb + tig + 4]) };
            mma_tf32(acA[nt], aU, b);
        }
#pragma unroll
        for (int nt = 0; nt < 8; nt++) {
            int nr = wnB + nt * 8 + grp;
            uint32_t b[2] = { f2tf(PS[nr * 36 + kb + tig]), f2tf(PS[nr * 36 + kb + tig + 4]) };
            mma_tf32(acB[nt], aV, b);
        }
    }
    __syncthreads();

#pragma unroll
    for (int nt = 0; nt < 4; nt++) {
        int col = wnA + nt * 8 + tig * 2;
        *(float2*)&ACs[(wm + grp) * 68 + col]     = make_float2(acA[nt][0], acA[nt][1]);
        *(float2*)&ACs[(wm + grp + 8) * 68 + col] = make_float2(acA[nt][2], acA[nt][3]);
    }
#pragma unroll
    for (int nt = 0; nt < 8; nt++) {
        int col = wnB + nt * 8 + tig * 2;
        *(float2*)&BDs[(wm + grp) * 132 + col]     = make_float2(acB[nt][0], acB[nt][1]);
        *(float2*)&BDs[(wm + grp + 8) * 132 + col] = make_float2(acB[nt][2], acB[nt][3]);
    }
    __syncthreads();

    const float scal = 0.17677669529663687f;   // 1/sqrt(32)
    const int cc = (tid & 15) * 4;
    const int rb = tid >> 4;
#pragma unroll
    for (int it = 0; it < 4; it++) {
        int r = rb + it * 16;
        int off = 63 - r + cc;
        float4 o;
        o.x = (ACs[r * 68 + cc + 0] + BDs[r * 132 + off + 0]) * scal;
        o.y = (ACs[r * 68 + cc + 1] + BDs[r * 132 + off + 1]) * scal;
        o.z = (ACs[r * 68 + cc + 2] + BDs[r * 132 + off + 2]) * scal;
        o.w = (ACs[r * 68 + cc + 3] + BDs[r * 132 + off + 3]) * scal;
        *(float4*)(total + (((size_t)nh) << 20) + (size_t)(l0 + r) * L_ + s0 + cc) = o;
    }
}

// ---- fused proj_in + scores_out + softmax: one block per (n,l) row ------------
__global__ __launch_bounds__(256) void out_softmax_kernel(
    const float* __restrict__ total, const float* __restrict__ asi,
    const float* __restrict__ projIn, const float* __restrict__ projOut,
    float* __restrict__ scores_out, __half* __restrict__ attnh)
{
    __shared__ float ts[8][1028];
    __shared__ float pin[64], pout[64];
    __shared__ float red[8][8];
    const int tid = threadIdx.x;
    const int b = blockIdx.x;
    const int n = b >> 10, l = b & 1023;
    if (tid < 64) { pin[tid] = projIn[tid]; pout[tid] = projOut[tid]; }

#pragma unroll
    for (int h = 0; h < 8; h++) {
        float4 v = *(const float4*)(total + (((size_t)(n * 8 + h)) << 20)
                                          + ((size_t)l << 10) + tid * 4);
        *(float4*)&ts[h][tid * 4] = v;
    }
    __syncthreads();

    const int s = tid * 4;
    const size_t abase = ((size_t)n << 23) + ((size_t)l << 13) + ((size_t)s << 3);
    for (int js = 0; js < 4; js++) {
        float4 a0 = *(const float4*)(asi + abase + js * 8);
        float4 a1 = *(const float4*)(asi + abase + js * 8 + 4);
        float a[8] = {a0.x, a0.y, a0.z, a0.w, a1.x, a1.y, a1.z, a1.w};
        float tn8[8];
#pragma unroll
        for (int h = 0; h < 8; h++) {
            float t = ts[h][s + js];
#pragma unroll
            for (int g = 0; g < 8; g++) t = fmaf(a[g], pin[g * 8 + h], t);
            tn8[h] = t;
        }
        float o[8];
#pragma unroll
        for (int g = 0; g < 8; g++) {
            float sum = a[g];
#pragma unroll
            for (int h = 0; h < 8; h++) sum = fmaf(tn8[h], pout[h * 8 + g], sum);
            o[g] = sum;
        }
        *(float4*)(scores_out + abase + js * 8)     = make_float4(o[0], o[1], o[2], o[3]);
        *(float4*)(scores_out + abase + js * 8 + 4) = make_float4(o[4], o[5], o[6], o[7]);
#pragma unroll
        for (int h = 0; h < 8; h++) ts[h][s + js] = tn8[h];
    }

    float mh[8];
#pragma unroll
    for (int h = 0; h < 8; h++) {
        float m = fmaxf(fmaxf(ts[h][s], ts[h][s+1]), fmaxf(ts[h][s+2], ts[h][s+3]));
#pragma unroll
        for (int o = 16; o > 0; o >>= 1) m = fmaxf(m, __shfl_xor_sync(0xffffffffu, m, o));
        mh[h] = m;
    }
    if ((tid & 31) == 0)
#pragma unroll
        for (int h = 0; h < 8; h++) red[h][tid >> 5] = mh[h];
    __syncthreads();
#pragma unroll
    for (int h = 0; h < 8; h++) {
        float m = red[h][0];
#pragma unroll
        for (int w = 1; w < 8; w++) m = fmaxf(m, red[h][w]);
        mh[h] = m;
    }
    __syncthreads();

    float sh[8];
#pragma unroll
    for (int h = 0; h < 8; h++) {
        float s0 = 0.f;
#pragma unroll
        for (int js = 0; js < 4; js++) {
            float e = expf(ts[h][s + js] - mh[h]);
            ts[h][s + js] = e;
            s0 += e;
        }
#pragma unroll
        for (int o = 16; o > 0; o >>= 1) s0 += __shfl_xor_sync(0xffffffffu, s0, o);
        sh[h] = s0;
    }
    if ((tid & 31) == 0)
#pragma unroll
        for (int h = 0; h < 8; h++) red[h][tid >> 5] = sh[h];
    __syncthreads();
#pragma unroll
    for (int h = 0; h < 8; h++) {
        float ss = red[h][0] + red[h][1] + red[h][2] + red[h][3]
                 + red[h][4] + red[h][5] + red[h][6] + red[h][7];
        float inv = 1.f / ss;
        uint32_t h0 = pack_h2(ts[h][s] * inv, ts[h][s+1] * inv);
        uint32_t h1v = pack_h2(ts[h][s+2] * inv, ts[h][s+3] * inv);
        *(uint2*)(attnh + (((size_t)(n * 8 + h)) << 20) + ((size_t)l << 10) + s)
            = make_uint2(h0, h1v);
    }
}

// -------- av via fp16 MMA: ctx[l,n,h*32+d] = sum_s attn[n,h,l,s]*v[s,n,h,d] ---
__global__ __launch_bounds__(128) void av_kernel(
    const __half* __restrict__ attnh, const float* __restrict__ qkv,
    float* __restrict__ ctx)
{
    __shared__ __half As[64 * 136];
    __shared__ __half Vt[32 * 136];
    const int tid = threadIdx.x;
    const int wid = tid >> 5, lane = tid & 31;
    const int grp = lane >> 2, tig = lane & 3;
    const int nh = blockIdx.y;
    const int n = nh >> 3, h = nh & 7;
    const int l0 = blockIdx.x * 64;
    const uint32_t asb = smem_u32(As);
    const int wm = wid * 16;

    float acc[4][4];
#pragma unroll
    for (int nt = 0; nt < 4; nt++)
#pragma unroll
        for (int q = 0; q < 4; q++) acc[nt][q] = 0.f;

    const __half* abase = attnh + (((size_t)nh) << 20) + ((size_t)l0 << 10);

    for (int sc = 0; sc < 1024; sc += 128) {
#pragma unroll
        for (int i = 0; i < 8; i++) {
            int idx = tid + 128 * i;
            int r = idx >> 4, c = idx & 15;
            cp16s(asb + (uint32_t)(r * 136 + c * 8) * 2,
                  abase + ((size_t)r << 10) + sc + c * 8);
        }
        asm volatile("cp.async.commit_group;" ::: "memory");
        {
            int sr = tid;
            const float* vp = qkv + (size_t)((sc + sr) * NB + n) * 768 + 512 + h * 32;
#pragma unroll
            for (int d4 = 0; d4 < 8; d4++) {
                float4 v = *(const float4*)(vp + d4 * 4);
                Vt[(d4 * 4 + 0) * 136 + sr] = __float2half_rn(v.x);
                Vt[(d4 * 4 + 1) * 136 + sr] = __float2half_rn(v.y);
                Vt[(d4 * 4 + 2) * 136 + sr] = __float2half_rn(v.z);
                Vt[(d4 * 4 + 3) * 136 + sr] = __float2half_rn(v.w);
            }
        }
        asm volatile("cp.async.wait_group 0;" ::: "memory");
        __syncthreads();
#pragma unroll
        for (int ks = 0; ks < 8; ks++) {
            const int kb = ks * 16;
            uint32_t a[4], b[4][2];
            a[0] = *(const uint32_t*)(As + (wm + grp) * 136 + kb + tig * 2);
            a[1] = *(const uint32_t*)(As + (wm + grp + 8) * 136 + kb + tig * 2);
            a[2] = *(const uint32_t*)(As + (wm + grp) * 136 + kb + 8 + tig * 2);
            a[3] = *(const uint32_t*)(As + (wm + grp + 8) * 136 + kb + 8 + tig * 2);
#pragma unroll
            for (int nt = 0; nt < 4; nt++) {
                int nr = nt * 8 + grp;
                b[nt][0] = *(const uint32_t*)(Vt + nr * 136 + kb + tig * 2);
                b[nt][1] = *(const uint32_t*)(Vt + nr * 136 + kb + 8 + tig * 2);
            }
#pragma unroll
            for (int nt = 0; nt < 4; nt++)
                mma_f16(acc[nt], a, b[nt]);
        }
        __syncthreads();
    }

#pragma unroll
    for (int nt = 0; nt < 4; nt++) {
        int d = nt * 8 + tig * 2;
#pragma unroll
        for (int half = 0; half < 2; half++) {
            int l = l0 + wm + grp + half * 8;
            *(float2*)(ctx + (size_t)(l * NB + n) * 256 + h * 32 + d)
                = make_float2(acc[nt][half * 2], acc[nt][half * 2 + 1]);
        }
    }
}

// ---- fused GLU + depthwise conv(K=31) + bias + DoubleSwish --------------------
// block: (128 l, 32 c, n). glu computed on the fly into the halo tile.
__global__ __launch_bounds__(256) void gludw_kernel(
    const float* __restrict__ y, const float* __restrict__ w,
    const float* __restrict__ b, float* __restrict__ out)
{
    __shared__ float in_s[32 * 161];
    __shared__ float w_s[32 * 33];
    const int l0 = blockIdx.x * 128;
    const int c0 = blockIdx.y * 32;
    const int n  = blockIdx.z;

    for (int idx = threadIdx.x; idx < 32 * 160; idx += 256) {
        int c = idx & 31, col = idx >> 5;       // col 0..159, c coalesced
        int gl = l0 + col - 15;
        float v = 0.f;
        if (col < 158 && gl >= 0 && gl < L_) {
            size_t base = (size_t)(gl * NB + n) * 1024;
            float a = y[base + c0 + c];
            float g = y[base + c0 + c + 512];
            v = a / (1.f + expf(-g));
        }
        in_s[c * 161 + col] = v;
    }
    for (int idx = threadIdx.x; idx < 32 * KW; idx += 256) {
        int c = idx / KW, k = idx % KW;
        w_s[c * 33 + k] = w[(c0 + c) * KW + k];
    }
    __syncthreads();

    const int ci = threadIdx.x & 31;
    const int lq = threadIdx.x >> 5;
    const float bb = b[c0 + ci];
#pragma unroll
    for (int lt = 0; lt < 16; lt++) {
        int ll = lt * 8 + lq;
        float s = bb;
#pragma unroll
        for (int k = 0; k < KW; k++)
            s = fmaf(in_s[ci * 161 + ll + k], w_s[ci * 33 + k], s);
        float v = s / (1.f + expf(1.f - s));
        out[(((size_t)((l0 + ll) * NB + n)) << 9) + c0 + ci] = v;
    }
}

// -------- BasicNorm -> d_out ---------------------------------------------------
__global__ __launch_bounds__(128) void norm_kernel(
    const float* __restrict__ x, const float* __restrict__ leps,
    float* __restrict__ out)
{
    __shared__ float red[4];
    const size_t base = (size_t)blockIdx.x * 512;
    float4 v = ((const float4*)(x + base))[threadIdx.x];
    float ss = v.x * v.x + v.y * v.y + v.z * v.z + v.w * v.w;
#pragma unroll
    for (int o = 16; o > 0; o >>= 1) ss += __shfl_xor_sync(0xffffffffu, ss, o);
    if ((threadIdx.x & 31) == 0) red[threadIdx.x >> 5] = ss;
    __syncthreads();
    float tot = red[0] + red[1] + red[2] + red[3];
    float scale = rsqrtf(tot * (1.f / 512.f) + expf(leps[0]));
    ((float4*)(out + base))[threadIdx.x] =
        make_float4(v.x * scale, v.y * scale, v.z * scale, v.w * scale);
}

// ------------------------------- launcher -------------------------------------
extern "C" void kernel_launch(void* const* d_in, const int* in_sizes, int n_in,
                              void* d_out, int out_size)
{
    const float* src      = (const float*)d_in[0];
    const float* pos_emb  = (const float*)d_in[1];
    const float* asi      = (const float*)d_in[2];
    const float* w_in     = (const float*)d_in[3];
    const float* b_in     = (const float*)d_in[4];
    const float* w_pos    = (const float*)d_in[5];
    const float* pbu      = (const float*)d_in[6];
    const float* pbv      = (const float*)d_in[7];
    const float* projIn   = (const float*)d_in[8];
    const float* projOut  = (const float*)d_in[9];
    const float* w_out    = (const float*)d_in[10];
    const float* b_out    = (const float*)d_in[11];
    const float* w_ff1m   = (const float*)d_in[12];
    const float* b_ff1m   = (const float*)d_in[13];
    const float* w_ff2m   = (const float*)d_in[14];
    const float* b_ff2m   = (const float*)d_in[15];
    const float* w_ff1    = (const float*)d_in[16];
    const float* b_ff1    = (const float*)d_in[17];
    const float* w_ff2    = (const float*)d_in[18];
    const float* b_ff2    = (const float*)d_in[19];
    const float* w_pw1    = (const float*)d_in[20];
    const float* b_pw1    = (const float*)d_in[21];
    const float* w_dw     = (const float*)d_in[22];
    const float* b_dw     = (const float*)d_in[23];
    const float* w_pw2    = (const float*)d_in[24];
    const float* b_pw2    = (const float*)d_in[25];
    const float* leps     = (const float*)d_in[26];

    float* out        = (float*)d_out;
    float* out_scores = out + (size_t)TOK * E_;

    float *h1, *x, *qkv, *p, *total, *ctx, *x2, *y, *hct, *x3, *x4;
    __half *whf, *attnh;
    cudaGetSymbolAddress((void**)&h1,   g_h1);
    cudaGetSymbolAddress((void**)&x,    g_x);
    cudaGetSymbolAddress((void**)&qkv,  g_qkv);
    cudaGetSymbolAddress((void**)&p,    g_p);
    cudaGetSymbolAddress((void**)&total,g_total);
    cudaGetSymbolAddress((void**)&ctx,  g_ctx);
    cudaGetSymbolAddress((void**)&x2,   g_x2);
    cudaGetSymbolAddress((void**)&y,    g_y);
    cudaGetSymbolAddress((void**)&hct,  g_hct);
    cudaGetSymbolAddress((void**)&x3,   g_x3);
    cudaGetSymbolAddress((void**)&x4,   g_x4);
    cudaGetSymbolAddress((void**)&whf,  g_whf);
    cudaGetSymbolAddress((void**)&attnh,g_attnh);
    __half* h1h = (__half*)h1;

    static bool attr_set = false;
    if (!attr_set) {
        cudaFuncSetAttribute(hgemm<1,0,1,64>,  cudaFuncAttributeMaxDynamicSharedMemorySize, TH_SMEM_MT(64));
        cudaFuncSetAttribute(hgemm<0,0,0,64>,  cudaFuncAttributeMaxDynamicSharedMemorySize, TH_SMEM_MT(64));
        cudaFuncSetAttribute(hgemm<2,1,0,128>, cudaFuncAttributeMaxDynamicSharedMemorySize, TH_SMEM_MT(128));
        cudaFuncSetAttribute(hgemm<2,0,0,128>, cudaFuncAttributeMaxDynamicSharedMemorySize, TH_SMEM_MT(128));
        cudaFuncSetAttribute(hgemm<0,0,0,128>, cudaFuncAttributeMaxDynamicSharedMemorySize, TH_SMEM_MT(128));
        cudaFuncSetAttribute(scores_mma_kernel, cudaFuncAttributeMaxDynamicSharedMemorySize, SC_SMEM);
        attr_set = true;
    }

    // prepass: convert all B (weight) operands to fp16
    CvtArgs ca;
    ca.src[0] = w_ff1m; ca.dstoff[0] = OFF_FF1M; ca.n4[0] = (DFF_ * E_) / 4;
    ca.src[1] = w_ff2m; ca.dstoff[1] = OFF_FF2M; ca.n4[1] = (E_ * DFF_) / 4;
    ca.src[2] = w_in;   ca.dstoff[2] = OFF_IN;   ca.n4[2] = (768 * E_) / 4;
    ca.src[3] = w_pos;  ca.dstoff[3] = OFF_POS;  ca.n4[3] = (E2_ * E_) / 4;
    ca.src[4] = w_out;  ca.dstoff[4] = OFF_OUT;  ca.n4[4] = (E_ * E2_) / 4;
    ca.src[5] = w_pw1;  ca.dstoff[5] = OFF_PW1;  ca.n4[5] = (1024 * E_) / 4;
    ca.src[6] = w_pw2;  ca.dstoff[6] = OFF_PW2;  ca.n4[6] = (E_ * E_) / 4;
    ca.src[7] = w_ff1;  ca.dstoff[7] = OFF_FF1;  ca.n4[7] = (DFF_ * E_) / 4;
    ca.src[8] = w_ff2;  ca.dstoff[8] = OFF_FF2;  ca.n4[8] = (E_ * DFF_) / 4;
    cvtw_kernel<<<dim3(1024, 9), 256>>>(ca);

    // macaron FFN (MT=64 for ff1; h1 fp16; FF2 consumes fp16 A)
    hgemm<1,0,1,64><<<dim3(DFF_ / 128, TOK / 64), 256, TH_SMEM_MT(64)>>>(src, whf + OFF_FF1M, b_ff1m, nullptr, h1h, TOK, DFF_, E_);
    hgemm<2,1,0,128><<<dim3(E_ / 128, TOK / 128), 256, TH_SMEM_MT(128)>>>(h1h, whf + OFF_FF2M, b_ff2m, src, x, TOK, E_, DFF_);

    // attention inputs (MT=64)
    hgemm<0,0,0,64><<<dim3(768 / 128, TOK / 64), 256, TH_SMEM_MT(64)>>>(x, whf + OFF_IN, b_in, nullptr, qkv, TOK, 768, E_);
    hgemm<0,0,0,64><<<dim3(2, 32), 256, TH_SMEM_MT(64)>>>(pos_emb, whf + OFF_POS, nullptr, nullptr, p, PM, 256, E_);

    // scores -> fused proj_in + scores_out + softmax (attn fp16) -> AV
    scores_mma_kernel<<<dim3(16, 16, 32), 256, SC_SMEM>>>(qkv, p, pbu, pbv, total);
    out_softmax_kernel<<<4096, 256>>>(total, asi, projIn, projOut, out_scores, attnh);
    av_kernel<<<dim3(16, 32), 128>>>(attnh, qkv, ctx);
    hgemm<2,0,0,128><<<dim3(E_ / 128, TOK / 128), 256, TH_SMEM_MT(128)>>>(ctx, whf + OFF_OUT, b_out, x, x2, TOK, E_, E2_);

    // conv module (GLU fused into dwconv)
    hgemm<0,0,0,128><<<dim3(1024 / 128, TOK / 128), 256, TH_SMEM_MT(128)>>>(x2, whf + OFF_PW1, b_pw1, nullptr, y, TOK, 1024, E_);
    gludw_kernel<<<dim3(8, 16, NB), 256>>>(y, w_dw, b_dw, hct);
    hgemm<2,0,0,128><<<dim3(E_ / 128, TOK / 128), 256, TH_SMEM_MT(128)>>>(hct, whf + OFF_PW2, b_pw2, x2, x3, TOK, E_, E_);

    // final FFN + BasicNorm
    hgemm<1,0,1,64><<<dim3(DFF_ / 128, TOK / 64), 256, TH_SMEM_MT(64)>>>(x3, whf + OFF_FF1, b_ff1, nullptr, h1h, TOK, DFF_, E_);
    hgemm<2,1,0,128><<<dim3(E_ / 128, TOK / 128), 256, TH_SMEM_MT(128)>>>(h1h, whf + OFF_FF2, b_ff2, x3, x4, TOK, E_, DFF_);
    norm_kernel<<<TOK, 128>>>(x4, leps, out);
}

// round 14
// speedup vs baseline: 1.1786x; 1.0136x over previous
#include <cuda_runtime.h>
#include <cuda_fp16.h>
#include <math.h>
#include <stdint.h>

#define L_    1024
#define NB    4
#define E_    512
#define H_    8
#define D_    32
#define DFF_  2048
#define E2_   256
#define TOK   4096      // L*NB
#define PM    2047      // 2L-1
#define KW    31

// ---------------- scratch (static device globals; no allocation) -------------
__device__ float g_h1[(size_t)TOK * DFF_];            // reused as __half for h1
__device__ float g_x[(size_t)TOK * E_];
__device__ float g_qkv[(size_t)TOK * 768];
__device__ float g_p[(size_t)2048 * 256];
__device__ __half g_th[(size_t)32 * 1024 * 1024];     // (N,H,L,S) logits -> probs
__device__ float g_ctx[(size_t)TOK * E2_];
__device__ float g_x2[(size_t)TOK * E_];
__device__ __half g_y[(size_t)TOK * 1024];            // pw1 output fp16
__device__ float g_hct[(size_t)TOK * E_];
__device__ float g_x3[(size_t)TOK * E_];
__device__ float g_x4[(size_t)TOK * E_];
__device__ __half g_whf[(size_t)5636096];             // fp16 weights

// fp16 weight scratch offsets (elements)
#define OFF_FF1M 0
#define OFF_FF2M 1048576
#define OFF_IN   2097152
#define OFF_POS  2490368
#define OFF_OUT  2621440
#define OFF_PW1  2752512
#define OFF_PW2  3276800
#define OFF_FF1  3538944
#define OFF_FF2  4587520

// ---------------- helpers ------------------------------------------------------
__device__ __forceinline__ uint32_t f2tf(float f) {
    uint32_t u;
    asm("cvt.rna.tf32.f32 %0, %1;" : "=r"(u) : "f"(f));
    return u;
}
__device__ __forceinline__ void mma_tf32(float* c, const uint32_t* a, const uint32_t* b) {
    asm volatile(
        "mma.sync.aligned.m16n8k8.row.col.f32.tf32.tf32.f32 "
        "{%0,%1,%2,%3}, {%4,%5,%6,%7}, {%8,%9}, {%0,%1,%2,%3};"
        : "+f"(c[0]), "+f"(c[1]), "+f"(c[2]), "+f"(c[3])
        : "r"(a[0]), "r"(a[1]), "r"(a[2]), "r"(a[3]), "r"(b[0]), "r"(b[1]));
}
__device__ __forceinline__ void mma_f16(float* c, const uint32_t* a, const uint32_t* b) {
    asm volatile(
        "mma.sync.aligned.m16n8k16.row.col.f32.f16.f16.f32 "
        "{%0,%1,%2,%3}, {%4,%5,%6,%7}, {%8,%9}, {%0,%1,%2,%3};"
        : "+f"(c[0]), "+f"(c[1]), "+f"(c[2]), "+f"(c[3])
        : "r"(a[0]), "r"(a[1]), "r"(a[2]), "r"(a[3]), "r"(b[0]), "r"(b[1]));
}
__device__ __forceinline__ void cp16s(uint32_t daddr, const void* src) {
    asm volatile("cp.async.ca.shared.global [%0], [%1], 16;\n" :: "r"(daddr), "l"(src));
}
__device__ __forceinline__ uint32_t smem_u32(const void* p) {
    uint32_t a;
    asm("{ .reg .u64 t; cvta.to.shared.u64 t, %1; cvt.u32.u64 %0, t; }" : "=r"(a) : "l"(p));
    return a;
}
__device__ __forceinline__ uint32_t pack_h2(float x, float y) {
    __half2 h = __floats2half2_rn(x, y);
    return *(uint32_t*)&h;
}

// -------- prepass: convert 9 weight matrices to fp16 into g_whf ----------------
struct CvtArgs {
    const float* src[9];
    int dstoff[9];
    int n4[9];
};
__global__ __launch_bounds__(256) void cvtw_kernel(CvtArgs args) {
    const int wi = blockIdx.y;
    const int idx = blockIdx.x * 256 + threadIdx.x;
    if (idx >= args.n4[wi]) return;
    float4 v = *(const float4*)(args.src[wi] + (size_t)idx * 4);
    uint32_t lo = pack_h2(v.x, v.y);
    uint32_t hi = pack_h2(v.z, v.w);
    *(uint2*)(g_whf + args.dstoff[wi] + (size_t)idx * 4) = make_uint2(lo, hi);
}

// ------- cp.async double-buffered fp16 GEMM, MT-row CTA tile ------------------
#define TH_STRIDE 40
#define TH_SMEM_MT(MT) ((2 * (MT) * TH_STRIDE + 2 * 128 * TH_STRIDE) * 2)
template <int EPI, int AH, int CH, int MT>
__global__ __launch_bounds__(256, 2) void hgemm(
    const void* __restrict__ Av, const __half* __restrict__ B,
    const float* __restrict__ bias, const float* __restrict__ res,
    void* __restrict__ Cv, int M, int Nn, int Kk)
{
    extern __shared__ __half smh[];
    const uint32_t smb = smem_u32(smh);
    const float*  A  = (const float*)Av;
    const __half* Ah = (const __half*)Av;
    float*  C  = (float*)Cv;
    __half* Ch = (__half*)Cv;

    constexpr int TPR  = 256 / MT;
    constexpr int CHK  = 32 / TPR;
    constexpr int ABUF = MT * TH_STRIDE;
    constexpr int BBUF = 128 * TH_STRIDE;
    constexpr int MTS  = MT / 32;

    const int tid   = threadIdx.x;
    const int wid   = tid >> 5;
    const int lane  = tid & 31;
    const int grp   = lane >> 2;
    const int tig   = lane & 3;
    const int row0  = blockIdx.y * MT;
    const int col0  = blockIdx.x * 128;
    const int wm    = (wid >> 2) * (MT / 2);
    const int wn    = (wid & 3) * 32;
    const int srow  = tid / TPR;
    const int scol  = (tid % TPR) * CHK;
    const int brow  = tid >> 1;
    const int bcol  = (tid & 1) * 16;

    float acc[MTS][4][4];
#pragma unroll
    for (int mt = 0; mt < MTS; mt++)
#pragma unroll
        for (int nt = 0; nt < 4; nt++)
#pragma unroll
            for (int q = 0; q < 4; q++) acc[mt][nt][q] = 0.f;

    float4 ast[CHK / 4];
#define LDGA(t) {                                                               \
        int ar = row0 + srow; if (ar >= M) ar = M - 1;                          \
        const float* ap = A + (size_t)ar * Kk + (t) * 32 + scol;                \
        _Pragma("unroll")                                                       \
        for (int i = 0; i < CHK / 4; i++) ast[i] = *(const float4*)(ap + i * 4); }
#define STSA(bf) {                                                              \
        __half* dst = smh + (bf) * ABUF + srow * TH_STRIDE + scol;              \
        _Pragma("unroll")                                                       \
        for (int i = 0; i < CHK / 4; i++) {                                     \
            uint32_t h0 = pack_h2(ast[i].x, ast[i].y);                          \
            uint32_t h1 = pack_h2(ast[i].z, ast[i].w);                          \
            *(uint2*)(dst + i * 4) = make_uint2(h0, h1); } }
#define LOADA(t) {                                                              \
        uint32_t base = smb + (uint32_t)(((t & 1) * ABUF + srow * TH_STRIDE + scol) * 2); \
        int ar = row0 + srow; if (ar >= M) ar = M - 1;                          \
        const __half* ap = Ah + (size_t)ar * Kk + (t) * 32 + scol;              \
        cp16s(base, ap);                                                        \
        if (CHK == 16) cp16s(base + 16, ap + 8); }
#define LOADB(t) {                                                              \
        uint32_t base = smb + (uint32_t)((2 * ABUF + ((t) & 1) * BBUF + brow * TH_STRIDE + bcol) * 2); \
        const __half* bp = B + (size_t)(col0 + brow) * Kk + (t) * 32 + bcol;    \
        cp16s(base,      bp);                                                   \
        cp16s(base + 16, bp + 8); }
#define COMMIT asm volatile("cp.async.commit_group;" ::: "memory")

    const int ntile = Kk >> 5;
    if (AH) { LOADA(0); }
    else    { LDGA(0); STSA(0); if (ntile > 1) LDGA(1); }
    LOADB(0); COMMIT;
    int buf = 0;
    for (int t = 0; t < ntile; t++) {
        if (t + 1 < ntile) {
            if (AH) LOADA(t + 1);
            LOADB(t + 1); COMMIT;
            if (!AH) { STSA(buf ^ 1); if (t + 2 < ntile) LDGA(t + 2); }
            asm volatile("cp.async.wait_group 1;" ::: "memory");
        } else {
            asm volatile("cp.async.wait_group 0;" ::: "memory");
        }
        __syncthreads();
        const __half* Ab = smh + buf * ABUF;
        const __half* Bb = smh + 2 * ABUF + buf * BBUF;
#pragma unroll
        for (int kst = 0; kst < 2; kst++) {
            const int kb = kst * 16;
            uint32_t a[MTS][4], b[4][2];
#pragma unroll
            for (int mt = 0; mt < MTS; mt++) {
                int mr = wm + mt * 16 + grp;
                a[mt][0] = *(const uint32_t*)(Ab + mr * TH_STRIDE + kb + tig * 2);
                a[mt][1] = *(const uint32_t*)(Ab + (mr + 8) * TH_STRIDE + kb + tig * 2);
                a[mt][2] = *(const uint32_t*)(Ab + mr * TH_STRIDE + kb + 8 + tig * 2);
                a[mt][3] = *(const uint32_t*)(Ab + (mr + 8) * TH_STRIDE + kb + 8 + tig * 2);
            }
#pragma unroll
            for (int nt = 0; nt < 4; nt++) {
                int nr = wn + nt * 8 + grp;
                b[nt][0] = *(const uint32_t*)(Bb + nr * TH_STRIDE + kb + tig * 2);
                b[nt][1] = *(const uint32_t*)(Bb + nr * TH_STRIDE + kb + 8 + tig * 2);
            }
#pragma unroll
            for (int mt = 0; mt < MTS; mt++)
#pragma unroll
                for (int nt = 0; nt < 4; nt++)
                    mma_f16(acc[mt][nt], a[mt], b[nt]);
        }
        __syncthreads();
        buf ^= 1;
    }
#undef LDGA
#undef STSA
#undef LOADA
#undef LOADB
#undef COMMIT

#pragma unroll
    for (int mt = 0; mt < MTS; mt++) {
        int rbase = row0 + wm + mt * 16 + grp;
#pragma unroll
        for (int nt = 0; nt < 4; nt++) {
            int col = col0 + wn + nt * 8 + tig * 2;
            float2 bb = make_float2(0.f, 0.f);
            if (bias) bb = *(const float2*)(bias + col);
#pragma unroll
            for (int half = 0; half < 2; half++) {
                int row = rbase + half * 8;
                if (row >= M) continue;
                float v0 = acc[mt][nt][half * 2 + 0] + bb.x;
                float v1 = acc[mt][nt][half * 2 + 1] + bb.y;
                if (EPI == 1) {
                    v0 = v0 / (1.f + expf(1.f - v0));
                    v1 = v1 / (1.f + expf(1.f - v1));
                }
                if (EPI == 2) {
                    float2 rr = *(const float2*)(res + (size_t)row * Nn + col);
                    v0 += rr.x; v1 += rr.y;
                }
                if (CH) {
                    *(uint32_t*)(Ch + (size_t)row * Nn + col) = pack_h2(v0, v1);
                } else {
                    *(float2*)(C + (size_t)row * Nn + col) = make_float2(v0, v1);
                }
            }
        }
    }
}

// -------- tf32-MMA scores -> fp16 logits: th = (QU·KS^T + rs(QV·PS^T))*scal ---
#define SC_SMEM (12800 * (int)sizeof(float))   // 51200 bytes
__global__ __launch_bounds__(256) void scores_mma_kernel(
    const float* __restrict__ qkv, const float* __restrict__ p,
    const float* __restrict__ pu, const float* __restrict__ pv,
    __half* __restrict__ th)
{
    extern __shared__ float sm[];
    float* QU  = sm;             // [64][36]
    float* QV  = sm + 2304;      // [64][36]
    float* KS  = sm + 4608;      // [64][36]
    float* PS  = sm + 6912;      // [128][36]
    float* ACs = sm;             // [64][68]  (phase 2)
    float* BDs = sm + 4352;      // [64][132] (phase 2)

    const int tid = threadIdx.x;
    const int nh = blockIdx.z;
    const int n = nh >> 3, h = nh & 7;
    const int l0 = blockIdx.y * 64;
    const int s0 = blockIdx.x * 64;
    const int mbase = (L_ - 64) - l0 + s0;

#pragma unroll
    for (int it = 0; it < 2; it++) {
        int u = tid + it * 256;
        int r = u >> 3, d4 = (u & 7) * 4;
        float4 qf = *(const float4*)(qkv + (size_t)((l0 + r) * NB + n) * 768 + h * 32 + d4);
        float4 uu = *(const float4*)(pu + h * 32 + d4);
        float4 vv = *(const float4*)(pv + h * 32 + d4);
        QU[r * 36 + d4 + 0] = qf.x + uu.x; QU[r * 36 + d4 + 1] = qf.y + uu.y;
        QU[r * 36 + d4 + 2] = qf.z + uu.z; QU[r * 36 + d4 + 3] = qf.w + uu.w;
        QV[r * 36 + d4 + 0] = qf.x + vv.x; QV[r * 36 + d4 + 1] = qf.y + vv.y;
        QV[r * 36 + d4 + 2] = qf.z + vv.z; QV[r * 36 + d4 + 3] = qf.w + vv.w;
        float4 kf = *(const float4*)(qkv + (size_t)((s0 + r) * NB + n) * 768 + 256 + h * 32 + d4);
        KS[r * 36 + d4 + 0] = kf.x; KS[r * 36 + d4 + 1] = kf.y;
        KS[r * 36 + d4 + 2] = kf.z; KS[r * 36 + d4 + 3] = kf.w;
    }
#pragma unroll
    for (int it = 0; it < 4; it++) {
        int u = tid + it * 256;
        int r = u >> 3, d4 = (u & 7) * 4;
        int m = mbase + r;
        float4 pf = make_float4(0.f, 0.f, 0.f, 0.f);
        if (m < PM) pf = *(const float4*)(p + (size_t)m * 256 + h * 32 + d4);
        PS[r * 36 + d4 + 0] = pf.x; PS[r * 36 + d4 + 1] = pf.y;
        PS[r * 36 + d4 + 2] = pf.z; PS[r * 36 + d4 + 3] = pf.w;
    }
    __syncthreads();

    const int wid = tid >> 5, lane = tid & 31;
    const int grp = lane >> 2, tig = lane & 3;
    const int wm = (wid >> 1) * 16;
    const int wnA = (wid & 1) * 32;
    const int wnB = (wid & 1) * 64;

    float acA[4][4] = {}, acB[8][4] = {};
#pragma unroll
    for (int k8 = 0; k8 < 4; k8++) {
        const int kb = k8 * 8;
        uint32_t aU[4], aV[4];
        aU[0] = f2tf(QU[(wm + grp) * 36 + kb + tig]);
        aU[1] = f2tf(QU[(wm + grp + 8) * 36 + kb + tig]);
        aU[2] = f2tf(QU[(wm + grp) * 36 + kb + tig + 4]);
        aU[3] = f2tf(QU[(wm + grp + 8) * 36 + kb + tig + 4]);
        aV[0] = f2tf(QV[(wm + grp) * 36 + kb + tig]);
        aV[1] = f2tf(QV[(wm + grp + 8) * 36 + kb + tig]);
        aV[2] = f2tf(QV[(wm + grp) * 36 + kb + tig + 4]);
        aV[3] = f2tf(QV[(wm + grp + 8) * 36 + kb + tig + 4]);
#pragma unroll
        for (int nt = 0; nt < 4; nt++) {
            int nr = wnA + nt * 8 + grp;
            uint32_t b[2] = { f2tf(KS[nr * 36 + kb + tig]), f2tf(KS[nr * 36 + kb + tig + 4]) };
            mma_tf32(acA[nt], aU, b);
        }
#pragma unroll
        for (int nt = 0; nt < 8; nt++) {
            int nr = wnB + nt * 8 + grp;
            uint32_t b[2] = { f2tf(PS[nr * 36 + kb + tig]), f2tf(PS[nr * 36 + kb + tig + 4]) };
            mma_tf32(acB[nt], aV, b);
        }
    }
    __syncthreads();

#pragma unroll
    for (int nt = 0; nt < 4; nt++) {
        int col = wnA + nt * 8 + tig * 2;
        *(float2*)&ACs[(wm + grp) * 68 + col]     = make_float2(acA[nt][0], acA[nt][1]);
        *(float2*)&ACs[(wm + grp + 8) * 68 + col] = make_float2(acA[nt][2], acA[nt][3]);
    }
#pragma unroll
    for (int nt = 0; nt < 8; nt++) {
        int col = wnB + nt * 8 + tig * 2;
        *(float2*)&BDs[(wm + grp) * 132 + col]     = make_float2(acB[nt][0], acB[nt][1]);
        *(float2*)&BDs[(wm + grp + 8) * 132 + col] = make_float2(acB[nt][2], acB[nt][3]);
    }
    __syncthreads();

    const float scal = 0.17677669529663687f;   // 1/sqrt(32)
    const int cc = (tid & 15) * 4;
    const int rb = tid >> 4;
#pragma unroll
    for (int it = 0; it < 4; it++) {
        int r = rb + it * 16;
        int off = 63 - r + cc;
        float o0 = (ACs[r * 68 + cc + 0] + BDs[r * 132 + off + 0]) * scal;
        float o1 = (ACs[r * 68 + cc + 1] + BDs[r * 132 + off + 1]) * scal;
        float o2 = (ACs[r * 68 + cc + 2] + BDs[r * 132 + off + 2]) * scal;
        float o3 = (ACs[r * 68 + cc + 3] + BDs[r * 132 + off + 3]) * scal;
        *(uint2*)(th + (((size_t)nh) << 20) + (size_t)(l0 + r) * L_ + s0 + cc)
            = make_uint2(pack_h2(o0, o1), pack_h2(o2, o3));
    }
}

// ---- fused proj_in + scores_out + softmax: one block per (n,l) row ------------
// reads fp16 logits from th, overwrites th in place with fp16 probs.
__global__ __launch_bounds__(256) void out_softmax_kernel(
    __half* __restrict__ th, const float* __restrict__ asi,
    const float* __restrict__ projIn, const float* __restrict__ projOut,
    float* __restrict__ scores_out)
{
    __shared__ float ts[8][1028];
    __shared__ float pin[64], pout[64];
    __shared__ float red[8][8];
    const int tid = threadIdx.x;
    const int b = blockIdx.x;
    const int n = b >> 10, l = b & 1023;
    if (tid < 64) { pin[tid] = projIn[tid]; pout[tid] = projOut[tid]; }

#pragma unroll
    for (int h = 0; h < 8; h++) {
        uint2 hv = *(const uint2*)(th + (((size_t)(n * 8 + h)) << 20)
                                      + ((size_t)l << 10) + tid * 4);
        float2 p0 = __half22float2(*(__half2*)&hv.x);
        float2 p1 = __half22float2(*(__half2*)&hv.y);
        *(float4*)&ts[h][tid * 4] = make_float4(p0.x, p0.y, p1.x, p1.y);
    }
    __syncthreads();

    const int s = tid * 4;
    const size_t abase = ((size_t)n << 23) + ((size_t)l << 13) + ((size_t)s << 3);
    for (int js = 0; js < 4; js++) {
        float4 a0 = *(const float4*)(asi + abase + js * 8);
        float4 a1 = *(const float4*)(asi + abase + js * 8 + 4);
        float a[8] = {a0.x, a0.y, a0.z, a0.w, a1.x, a1.y, a1.z, a1.w};
        float tn8[8];
#pragma unroll
        for (int h = 0; h < 8; h++) {
            float t = ts[h][s + js];
#pragma unroll
            for (int g = 0; g < 8; g++) t = fmaf(a[g], pin[g * 8 + h], t);
            tn8[h] = t;
        }
        float o[8];
#pragma unroll
        for (int g = 0; g < 8; g++) {
            float sum = a[g];
#pragma unroll
            for (int h = 0; h < 8; h++) sum = fmaf(tn8[h], pout[h * 8 + g], sum);
            o[g] = sum;
        }
        *(float4*)(scores_out + abase + js * 8)     = make_float4(o[0], o[1], o[2], o[3]);
        *(float4*)(scores_out + abase + js * 8 + 4) = make_float4(o[4], o[5], o[6], o[7]);
#pragma unroll
        for (int h = 0; h < 8; h++) ts[h][s + js] = tn8[h];
    }

    float mh[8];
#pragma unroll
    for (int h = 0; h < 8; h++) {
        float m = fmaxf(fmaxf(ts[h][s], ts[h][s+1]), fmaxf(ts[h][s+2], ts[h][s+3]));
#pragma unroll
        for (int o = 16; o > 0; o >>= 1) m = fmaxf(m, __shfl_xor_sync(0xffffffffu, m, o));
        mh[h] = m;
    }
    if ((tid & 31) == 0)
#pragma unroll
        for (int h = 0; h < 8; h++) red[h][tid >> 5] = mh[h];
    __syncthreads();
#pragma unroll
    for (int h = 0; h < 8; h++) {
        float m = red[h][0];
#pragma unroll
        for (int w = 1; w < 8; w++) m = fmaxf(m, red[h][w]);
        mh[h] = m;
    }
    __syncthreads();

    float sh[8];
#pragma unroll
    for (int h = 0; h < 8; h++) {
        float s0 = 0.f;
#pragma unroll
        for (int js = 0; js < 4; js++) {
            float e = expf(ts[h][s + js] - mh[h]);
            ts[h][s + js] = e;
            s0 += e;
        }
#pragma unroll
        for (int o = 16; o > 0; o >>= 1) s0 += __shfl_xor_sync(0xffffffffu, s0, o);
        sh[h] = s0;
    }
    if ((tid & 31) == 0)
#pragma unroll
        for (int h = 0; h < 8; h++) red[h][tid >> 5] = sh[h];
    __syncthreads();
#pragma unroll
    for (int h = 0; h < 8; h++) {
        float ss = red[h][0] + red[h][1] + red[h][2] + red[h][3]
                 + red[h][4] + red[h][5] + red[h][6] + red[h][7];
        float inv = 1.f / ss;
        uint32_t h0 = pack_h2(ts[h][s] * inv, ts[h][s+1] * inv);
        uint32_t h1v = pack_h2(ts[h][s+2] * inv, ts[h][s+3] * inv);
        *(uint2*)(th + (((size_t)(n * 8 + h)) << 20) + ((size_t)l << 10) + s)
            = make_uint2(h0, h1v);
    }
}

// -------- av via fp16 MMA: ctx[l,n,h*32+d] = sum_s attn[n,h,l,s]*v[s,n,h,d] ---
__global__ __launch_bounds__(128) void av_kernel(
    const __half* __restrict__ attnh, const float* __restrict__ qkv,
    float* __restrict__ ctx)
{
    __shared__ __half As[64 * 136];
    __shared__ __half Vt[32 * 136];
    const int tid = threadIdx.x;
    const int wid = tid >> 5, lane = tid & 31;
    const int grp = lane >> 2, tig = lane & 3;
    const int nh = blockIdx.y;
    const int n = nh >> 3, h = nh & 7;
    const int l0 = blockIdx.x * 64;
    const uint32_t asb = smem_u32(As);
    const int wm = wid * 16;

    float acc[4][4];
#pragma unroll
    for (int nt = 0; nt < 4; nt++)
#pragma unroll
        for (int q = 0; q < 4; q++) acc[nt][q] = 0.f;

    const __half* abase = attnh + (((size_t)nh) << 20) + ((size_t)l0 << 10);

    for (int sc = 0; sc < 1024; sc += 128) {
#pragma unroll
        for (int i = 0; i < 8; i++) {
            int idx = tid + 128 * i;
            int r = idx >> 4, c = idx & 15;
            cp16s(asb + (uint32_t)(r * 136 + c * 8) * 2,
                  abase + ((size_t)r << 10) + sc + c * 8);
        }
        asm volatile("cp.async.commit_group;" ::: "memory");
        {
            int sr = tid;
            const float* vp = qkv + (size_t)((sc + sr) * NB + n) * 768 + 512 + h * 32;
#pragma unroll
            for (int d4 = 0; d4 < 8; d4++) {
                float4 v = *(const float4*)(vp + d4 * 4);
                Vt[(d4 * 4 + 0) * 136 + sr] = __float2half_rn(v.x);
                Vt[(d4 * 4 + 1) * 136 + sr] = __float2half_rn(v.y);
                Vt[(d4 * 4 + 2) * 136 + sr] = __float2half_rn(v.z);
                Vt[(d4 * 4 + 3) * 136 + sr] = __float2half_rn(v.w);
            }
        }
        asm volatile("cp.async.wait_group 0;" ::: "memory");
        __syncthreads();
#pragma unroll
        for (int ks = 0; ks < 8; ks++) {
            const int kb = ks * 16;
            uint32_t a[4], b[4][2];
            a[0] = *(const uint32_t*)(As + (wm + grp) * 136 + kb + tig * 2);
            a[1] = *(const uint32_t*)(As + (wm + grp + 8) * 136 + kb + tig * 2);
            a[2] = *(const uint32_t*)(As + (wm + grp) * 136 + kb + 8 + tig * 2);
            a[3] = *(const uint32_t*)(As + (wm + grp + 8) * 136 + kb + 8 + tig * 2);
#pragma unroll
            for (int nt = 0; nt < 4; nt++) {
                int nr = nt * 8 + grp;
                b[nt][0] = *(const uint32_t*)(Vt + nr * 136 + kb + tig * 2);
                b[nt][1] = *(const uint32_t*)(Vt + nr * 136 + kb + 8 + tig * 2);
            }
#pragma unroll
            for (int nt = 0; nt < 4; nt++)
                mma_f16(acc[nt], a, b[nt]);
        }
        __syncthreads();
    }

#pragma unroll
    for (int nt = 0; nt < 4; nt++) {
        int d = nt * 8 + tig * 2;
#pragma unroll
        for (int half = 0; half < 2; half++) {
            int l = l0 + wm + grp + half * 8;
            *(float2*)(ctx + (size_t)(l * NB + n) * 256 + h * 32 + d)
                = make_float2(acc[nt][half * 2], acc[nt][half * 2 + 1]);
        }
    }
}

// ---- fused GLU + depthwise conv(K=31) + bias + DoubleSwish (y fp16) -----------
__global__ __launch_bounds__(256) void gludw_kernel(
    const __half* __restrict__ y, const float* __restrict__ w,
    const float* __restrict__ b, float* __restrict__ out)
{
    __shared__ float in_s[32 * 161];
    __shared__ float w_s[32 * 33];
    const int l0 = blockIdx.x * 128;
    const int c0 = blockIdx.y * 32;
    const int n  = blockIdx.z;

    for (int idx = threadIdx.x; idx < 32 * 160; idx += 256) {
        int c = idx & 31, col = idx >> 5;
        int gl = l0 + col - 15;
        float v = 0.f;
        if (col < 158 && gl >= 0 && gl < L_) {
            size_t base = (size_t)(gl * NB + n) * 1024;
            float a = __half2float(y[base + c0 + c]);
            float g = __half2float(y[base + c0 + c + 512]);
            v = a / (1.f + expf(-g));
        }
        in_s[c * 161 + col] = v;
    }
    for (int idx = threadIdx.x; idx < 32 * KW; idx += 256) {
        int c = idx / KW, k = idx % KW;
        w_s[c * 33 + k] = w[(c0 + c) * KW + k];
    }
    __syncthreads();

    const int ci = threadIdx.x & 31;
    const int lq = threadIdx.x >> 5;
    const float bb = b[c0 + ci];
#pragma unroll
    for (int lt = 0; lt < 16; lt++) {
        int ll = lt * 8 + lq;
        float s = bb;
#pragma unroll
        for (int k = 0; k < KW; k++)
            s = fmaf(in_s[ci * 161 + ll + k], w_s[ci * 33 + k], s);
        float v = s / (1.f + expf(1.f - s));
        out[(((size_t)((l0 + ll) * NB + n)) << 9) + c0 + ci] = v;
    }
}

// -------- BasicNorm -> d_out ---------------------------------------------------
__global__ __launch_bounds__(128) void norm_kernel(
    const float* __restrict__ x, const float* __restrict__ leps,
    float* __restrict__ out)
{
    __shared__ float red[4];
    const size_t base = (size_t)blockIdx.x * 512;
    float4 v = ((const float4*)(x + base))[threadIdx.x];
    float ss = v.x * v.x + v.y * v.y + v.z * v.z + v.w * v.w;
#pragma unroll
    for (int o = 16; o > 0; o >>= 1) ss += __shfl_xor_sync(0xffffffffu, ss, o);
    if ((threadIdx.x & 31) == 0) red[threadIdx.x >> 5] = ss;
    __syncthreads();
    float tot = red[0] + red[1] + red[2] + red[3];
    float scale = rsqrtf(tot * (1.f / 512.f) + expf(leps[0]));
    ((float4*)(out + base))[threadIdx.x] =
        make_float4(v.x * scale, v.y * scale, v.z * scale, v.w * scale);
}

// ------------------------------- launcher -------------------------------------
extern "C" void kernel_launch(void* const* d_in, const int* in_sizes, int n_in,
                              void* d_out, int out_size)
{
    const float* src      = (const float*)d_in[0];
    const float* pos_emb  = (const float*)d_in[1];
    const float* asi      = (const float*)d_in[2];
    const float* w_in     = (const float*)d_in[3];
    const float* b_in     = (const float*)d_in[4];
    const float* w_pos    = (const float*)d_in[5];
    const float* pbu      = (const float*)d_in[6];
    const float* pbv      = (const float*)d_in[7];
    const float* projIn   = (const float*)d_in[8];
    const float* projOut  = (const float*)d_in[9];
    const float* w_out    = (const float*)d_in[10];
    const float* b_out    = (const float*)d_in[11];
    const float* w_ff1m   = (const float*)d_in[12];
    const float* b_ff1m   = (const float*)d_in[13];
    const float* w_ff2m   = (const float*)d_in[14];
    const float* b_ff2m   = (const float*)d_in[15];
    const float* w_ff1    = (const float*)d_in[16];
    const float* b_ff1    = (const float*)d_in[17];
    const float* w_ff2    = (const float*)d_in[18];
    const float* b_ff2    = (const float*)d_in[19];
    const float* w_pw1    = (const float*)d_in[20];
    const float* b_pw1    = (const float*)d_in[21];
    const float* w_dw     = (const float*)d_in[22];
    const float* b_dw     = (const float*)d_in[23];
    const float* w_pw2    = (const float*)d_in[24];
    const float* b_pw2    = (const float*)d_in[25];
    const float* leps     = (const float*)d_in[26];

    float* out        = (float*)d_out;
    float* out_scores = out + (size_t)TOK * E_;

    float *h1, *x, *qkv, *p, *ctx, *x2, *hct, *x3, *x4;
    __half *whf, *th, *y;
    cudaGetSymbolAddress((void**)&h1,   g_h1);
    cudaGetSymbolAddress((void**)&x,    g_x);
    cudaGetSymbolAddress((void**)&qkv,  g_qkv);
    cudaGetSymbolAddress((void**)&p,    g_p);
    cudaGetSymbolAddress((void**)&th,   g_th);
    cudaGetSymbolAddress((void**)&ctx,  g_ctx);
    cudaGetSymbolAddress((void**)&x2,   g_x2);
    cudaGetSymbolAddress((void**)&y,    g_y);
    cudaGetSymbolAddress((void**)&hct,  g_hct);
    cudaGetSymbolAddress((void**)&x3,   g_x3);
    cudaGetSymbolAddress((void**)&x4,   g_x4);
    cudaGetSymbolAddress((void**)&whf,  g_whf);
    __half* h1h = (__half*)h1;

    static bool attr_set = false;
    if (!attr_set) {
        cudaFuncSetAttribute(hgemm<1,0,1,64>,  cudaFuncAttributeMaxDynamicSharedMemorySize, TH_SMEM_MT(64));
        cudaFuncSetAttribute(hgemm<0,0,0,64>,  cudaFuncAttributeMaxDynamicSharedMemorySize, TH_SMEM_MT(64));
        cudaFuncSetAttribute(hgemm<2,1,0,128>, cudaFuncAttributeMaxDynamicSharedMemorySize, TH_SMEM_MT(128));
        cudaFuncSetAttribute(hgemm<2,0,0,128>, cudaFuncAttributeMaxDynamicSharedMemorySize, TH_SMEM_MT(128));
        cudaFuncSetAttribute(hgemm<0,0,1,128>, cudaFuncAttributeMaxDynamicSharedMemorySize, TH_SMEM_MT(128));
        cudaFuncSetAttribute(scores_mma_kernel, cudaFuncAttributeMaxDynamicSharedMemorySize, SC_SMEM);
        attr_set = true;
    }

    // prepass: convert all B (weight) operands to fp16
    CvtArgs ca;
    ca.src[0] = w_ff1m; ca.dstoff[0] = OFF_FF1M; ca.n4[0] = (DFF_ * E_) / 4;
    ca.src[1] = w_ff2m; ca.dstoff[1] = OFF_FF2M; ca.n4[1] = (E_ * DFF_) / 4;
    ca.src[2] = w_in;   ca.dstoff[2] = OFF_IN;   ca.n4[2] = (768 * E_) / 4;
    ca.src[3] = w_pos;  ca.dstoff[3] = OFF_POS;  ca.n4[3] = (E2_ * E_) / 4;
    ca.src[4] = w_out;  ca.dstoff[4] = OFF_OUT;  ca.n4[4] = (E_ * E2_) / 4;
    ca.src[5] = w_pw1;  ca.dstoff[5] = OFF_PW1;  ca.n4[5] = (1024 * E_) / 4;
    ca.src[6] = w_pw2;  ca.dstoff[6] = OFF_PW2;  ca.n4[6] = (E_ * E_) / 4;
    ca.src[7] = w_ff1;  ca.dstoff[7] = OFF_FF1;  ca.n4[7] = (DFF_ * E_) / 4;
    ca.src[8] = w_ff2;  ca.dstoff[8] = OFF_FF2;  ca.n4[8] = (E_ * DFF_) / 4;
    cvtw_kernel<<<dim3(1024, 9), 256>>>(ca);

    // macaron FFN
    hgemm<1,0,1,64><<<dim3(DFF_ / 128, TOK / 64), 256, TH_SMEM_MT(64)>>>(src, whf + OFF_FF1M, b_ff1m, nullptr, h1h, TOK, DFF_, E_);
    hgemm<2,1,0,128><<<dim3(E_ / 128, TOK / 128), 256, TH_SMEM_MT(128)>>>(h1h, whf + OFF_FF2M, b_ff2m, src, x, TOK, E_, DFF_);

    // attention inputs
    hgemm<0,0,0,64><<<dim3(768 / 128, TOK / 64), 256, TH_SMEM_MT(64)>>>(x, whf + OFF_IN, b_in, nullptr, qkv, TOK, 768, E_);
    hgemm<0,0,0,64><<<dim3(2, 32), 256, TH_SMEM_MT(64)>>>(pos_emb, whf + OFF_POS, nullptr, nullptr, p, PM, 256, E_);

    // scores (fp16 logits) -> fused softmax (probs in place) -> AV
    scores_mma_kernel<<<dim3(16, 16, 32), 256, SC_SMEM>>>(qkv, p, pbu, pbv, th);
    out_softmax_kernel<<<4096, 256>>>(th, asi, projIn, projOut, out_scores);
    av_kernel<<<dim3(16, 32), 128>>>(th, qkv, ctx);
    hgemm<2,0,0,128><<<dim3(E_ / 128, TOK / 128), 256, TH_SMEM_MT(128)>>>(ctx, whf + OFF_OUT, b_out, x, x2, TOK, E_, E2_);

    // conv module (pw1 -> fp16 y; GLU fused into dwconv)
    hgemm<0,0,1,128><<<dim3(1024 / 128, TOK / 128), 256, TH_SMEM_MT(128)>>>(x2, whf + OFF_PW1, b_pw1, nullptr, y, TOK, 1024, E_);
    gludw_kernel<<<dim3(8, 16, NB), 256>>>(y, w_dw, b_dw, hct);
    hgemm<2,0,0,128><<<dim3(E_ / 128, TOK / 128), 256, TH_SMEM_MT(128)>>>(hct, whf + OFF_PW2, b_pw2, x2, x3, TOK, E_, E_);

    // final FFN + BasicNorm
    hgemm<1,0,1,64><<<dim3(DFF_ / 128, TOK / 64), 256, TH_SMEM_MT(64)>>>(x3, whf + OFF_FF1, b_ff1, nullptr, h1h, TOK, DFF_, E_);
    hgemm<2,1,0,128><<<dim3(E_ / 128, TOK / 128), 256, TH_SMEM_MT(128)>>>(h1h, whf + OFF_FF2, b_ff2, x3, x4, TOK, E_, DFF_);
    norm_kernel<<<TOK, 128>>>(x4, leps, out);
}

// round 15
// speedup vs baseline: 1.2027x; 1.0204x over previous
#include <cuda_runtime.h>
#include <cuda_fp16.h>
#include <math.h>
#include <stdint.h>

#define L_    1024
#define NB    4
#define E_    512
#define H_    8
#define D_    32
#define DFF_  2048
#define E2_   256
#define TOK   4096      // L*NB
#define PM    2047      // 2L-1
#define KW    31

// ---------------- scratch (static device globals; no allocation) -------------
__device__ float g_h1[(size_t)TOK * DFF_];            // reused as __half for h1
__device__ float g_x[(size_t)TOK * E_];
__device__ float g_qkv[(size_t)TOK * 768];
__device__ float g_p[(size_t)2048 * 256];
__device__ __half g_th[(size_t)32 * 1024 * 1024];     // (N,H,L,S) logits -> probs
__device__ float g_ctx[(size_t)TOK * E2_];
__device__ float g_x2[(size_t)TOK * E_];
__device__ __half g_y[(size_t)TOK * 1024];            // pw1 output fp16
__device__ float g_hct[(size_t)TOK * E_];
__device__ float g_x3[(size_t)TOK * E_];
__device__ float g_x4[(size_t)TOK * E_];
__device__ __half g_whf[(size_t)5636096];             // fp16 weights

// fp16 weight scratch offsets (elements)
#define OFF_FF1M 0
#define OFF_FF2M 1048576
#define OFF_IN   2097152
#define OFF_POS  2490368
#define OFF_OUT  2621440
#define OFF_PW1  2752512
#define OFF_PW2  3276800
#define OFF_FF1  3538944
#define OFF_FF2  4587520

// ---------------- helpers ------------------------------------------------------
__device__ __forceinline__ void mma_f16(float* c, const uint32_t* a, const uint32_t* b) {
    asm volatile(
        "mma.sync.aligned.m16n8k16.row.col.f32.f16.f16.f32 "
        "{%0,%1,%2,%3}, {%4,%5,%6,%7}, {%8,%9}, {%0,%1,%2,%3};"
        : "+f"(c[0]), "+f"(c[1]), "+f"(c[2]), "+f"(c[3])
        : "r"(a[0]), "r"(a[1]), "r"(a[2]), "r"(a[3]), "r"(b[0]), "r"(b[1]));
}
__device__ __forceinline__ void cp16s(uint32_t daddr, const void* src) {
    asm volatile("cp.async.ca.shared.global [%0], [%1], 16;\n" :: "r"(daddr), "l"(src));
}
__device__ __forceinline__ uint32_t smem_u32(const void* p) {
    uint32_t a;
    asm("{ .reg .u64 t; cvta.to.shared.u64 t, %1; cvt.u32.u64 %0, t; }" : "=r"(a) : "l"(p));
    return a;
}
__device__ __forceinline__ uint32_t pack_h2(float x, float y) {
    __half2 h = __floats2half2_rn(x, y);
    return *(uint32_t*)&h;
}

// -------- prepass: convert 9 weight matrices to fp16 into g_whf ----------------
struct CvtArgs {
    const float* src[9];
    int dstoff[9];
    int n4[9];
};
__global__ __launch_bounds__(256) void cvtw_kernel(CvtArgs args) {
    const int wi = blockIdx.y;
    const int idx = blockIdx.x * 256 + threadIdx.x;
    if (idx >= args.n4[wi]) return;
    float4 v = *(const float4*)(args.src[wi] + (size_t)idx * 4);
    uint32_t lo = pack_h2(v.x, v.y);
    uint32_t hi = pack_h2(v.z, v.w);
    *(uint2*)(g_whf + args.dstoff[wi] + (size_t)idx * 4) = make_uint2(lo, hi);
}

// ------- cp.async double-buffered fp16 GEMM, MT-row CTA tile ------------------
#define TH_STRIDE 40
#define TH_SMEM_MT(MT) ((2 * (MT) * TH_STRIDE + 2 * 128 * TH_STRIDE) * 2)
template <int EPI, int AH, int CH, int MT>
__global__ __launch_bounds__(256, 2) void hgemm(
    const void* __restrict__ Av, const __half* __restrict__ B,
    const float* __restrict__ bias, const float* __restrict__ res,
    void* __restrict__ Cv, int M, int Nn, int Kk)
{
    extern __shared__ __half smh[];
    const uint32_t smb = smem_u32(smh);
    const float*  A  = (const float*)Av;
    const __half* Ah = (const __half*)Av;
    float*  C  = (float*)Cv;
    __half* Ch = (__half*)Cv;

    constexpr int TPR  = 256 / MT;
    constexpr int CHK  = 32 / TPR;
    constexpr int ABUF = MT * TH_STRIDE;
    constexpr int BBUF = 128 * TH_STRIDE;
    constexpr int MTS  = MT / 32;

    const int tid   = threadIdx.x;
    const int wid   = tid >> 5;
    const int lane  = tid & 31;
    const int grp   = lane >> 2;
    const int tig   = lane & 3;
    const int row0  = blockIdx.y * MT;
    const int col0  = blockIdx.x * 128;
    const int wm    = (wid >> 2) * (MT / 2);
    const int wn    = (wid & 3) * 32;
    const int srow  = tid / TPR;
    const int scol  = (tid % TPR) * CHK;
    const int brow  = tid >> 1;
    const int bcol  = (tid & 1) * 16;

    float acc[MTS][4][4];
#pragma unroll
    for (int mt = 0; mt < MTS; mt++)
#pragma unroll
        for (int nt = 0; nt < 4; nt++)
#pragma unroll
            for (int q = 0; q < 4; q++) acc[mt][nt][q] = 0.f;

    float4 ast[CHK / 4];
#define LDGA(t) {                                                               \
        int ar = row0 + srow; if (ar >= M) ar = M - 1;                          \
        const float* ap = A + (size_t)ar * Kk + (t) * 32 + scol;                \
        _Pragma("unroll")                                                       \
        for (int i = 0; i < CHK / 4; i++) ast[i] = *(const float4*)(ap + i * 4); }
#define STSA(bf) {                                                              \
        __half* dst = smh + (bf) * ABUF + srow * TH_STRIDE + scol;              \
        _Pragma("unroll")                                                       \
        for (int i = 0; i < CHK / 4; i++) {                                     \
            uint32_t h0 = pack_h2(ast[i].x, ast[i].y);                          \
            uint32_t h1 = pack_h2(ast[i].z, ast[i].w);                          \
            *(uint2*)(dst + i * 4) = make_uint2(h0, h1); } }
#define LOADA(t) {                                                              \
        uint32_t base = smb + (uint32_t)(((t & 1) * ABUF + srow * TH_STRIDE + scol) * 2); \
        int ar = row0 + srow; if (ar >= M) ar = M - 1;                          \
        const __half* ap = Ah + (size_t)ar * Kk + (t) * 32 + scol;              \
        cp16s(base, ap);                                                        \
        if (CHK == 16) cp16s(base + 16, ap + 8); }
#define LOADB(t) {                                                              \
        uint32_t base = smb + (uint32_t)((2 * ABUF + ((t) & 1) * BBUF + brow * TH_STRIDE + bcol) * 2); \
        const __half* bp = B + (size_t)(col0 + brow) * Kk + (t) * 32 + bcol;    \
        cp16s(base,      bp);                                                   \
        cp16s(base + 16, bp + 8); }
#define COMMIT asm volatile("cp.async.commit_group;" ::: "memory")

    const int ntile = Kk >> 5;
    if (AH) { LOADA(0); }
    else    { LDGA(0); STSA(0); if (ntile > 1) LDGA(1); }
    LOADB(0); COMMIT;
    int buf = 0;
    for (int t = 0; t < ntile; t++) {
        if (t + 1 < ntile) {
            if (AH) LOADA(t + 1);
            LOADB(t + 1); COMMIT;
            if (!AH) { STSA(buf ^ 1); if (t + 2 < ntile) LDGA(t + 2); }
            asm volatile("cp.async.wait_group 1;" ::: "memory");
        } else {
            asm volatile("cp.async.wait_group 0;" ::: "memory");
        }
        __syncthreads();
        const __half* Ab = smh + buf * ABUF;
        const __half* Bb = smh + 2 * ABUF + buf * BBUF;
#pragma unroll
        for (int kst = 0; kst < 2; kst++) {
            const int kb = kst * 16;
            uint32_t a[MTS][4], b[4][2];
#pragma unroll
            for (int mt = 0; mt < MTS; mt++) {
                int mr = wm + mt * 16 + grp;
                a[mt][0] = *(const uint32_t*)(Ab + mr * TH_STRIDE + kb + tig * 2);
                a[mt][1] = *(const uint32_t*)(Ab + (mr + 8) * TH_STRIDE + kb + tig * 2);
                a[mt][2] = *(const uint32_t*)(Ab + mr * TH_STRIDE + kb + 8 + tig * 2);
                a[mt][3] = *(const uint32_t*)(Ab + (mr + 8) * TH_STRIDE + kb + 8 + tig * 2);
            }
#pragma unroll
            for (int nt = 0; nt < 4; nt++) {
                int nr = wn + nt * 8 + grp;
                b[nt][0] = *(const uint32_t*)(Bb + nr * TH_STRIDE + kb + tig * 2);
                b[nt][1] = *(const uint32_t*)(Bb + nr * TH_STRIDE + kb + 8 + tig * 2);
            }
#pragma unroll
            for (int mt = 0; mt < MTS; mt++)
#pragma unroll
                for (int nt = 0; nt < 4; nt++)
                    mma_f16(acc[mt][nt], a[mt], b[nt]);
        }
        __syncthreads();
        buf ^= 1;
    }
#undef LDGA
#undef STSA
#undef LOADA
#undef LOADB
#undef COMMIT

#pragma unroll
    for (int mt = 0; mt < MTS; mt++) {
        int rbase = row0 + wm + mt * 16 + grp;
#pragma unroll
        for (int nt = 0; nt < 4; nt++) {
            int col = col0 + wn + nt * 8 + tig * 2;
            float2 bb = make_float2(0.f, 0.f);
            if (bias) bb = *(const float2*)(bias + col);
#pragma unroll
            for (int half = 0; half < 2; half++) {
                int row = rbase + half * 8;
                if (row >= M) continue;
                float v0 = acc[mt][nt][half * 2 + 0] + bb.x;
                float v1 = acc[mt][nt][half * 2 + 1] + bb.y;
                if (EPI == 1) {
                    v0 = v0 / (1.f + expf(1.f - v0));
                    v1 = v1 / (1.f + expf(1.f - v1));
                }
                if (EPI == 2) {
                    float2 rr = *(const float2*)(res + (size_t)row * Nn + col);
                    v0 += rr.x; v1 += rr.y;
                }
                if (CH) {
                    *(uint32_t*)(Ch + (size_t)row * Nn + col) = pack_h2(v0, v1);
                } else {
                    *(float2*)(C + (size_t)row * Nn + col) = make_float2(v0, v1);
                }
            }
        }
    }
}

// -------- fp16-MMA scores -> fp16 logits: th = (QU·KS^T + rs(QV·PS^T))*scal ---
// phase1: QU/QV/KS [64][40] half, PS [128][40] half (12800 halves).
// phase2: ACs [64][68] + BDs [64][132] float (12800 floats). Union buffer.
#define SC_SMEM (12800 * (int)sizeof(float))   // 51200 bytes
__global__ __launch_bounds__(256) void scores_mma_kernel(
    const float* __restrict__ qkv, const float* __restrict__ p,
    const float* __restrict__ pu, const float* __restrict__ pv,
    __half* __restrict__ th)
{
    extern __shared__ float sm[];
    __half* QUh = (__half*)sm;           // [64][40]
    __half* QVh = QUh + 2560;            // [64][40]
    __half* KSh = QUh + 5120;            // [64][40]
    __half* PSh = QUh + 7680;            // [128][40]
    float* ACs = sm;                     // [64][68]  (phase 2)
    float* BDs = sm + 4352;              // [64][132] (phase 2)

    const int tid = threadIdx.x;
    const int nh = blockIdx.z;
    const int n = nh >> 3, h = nh & 7;
    const int l0 = blockIdx.y * 64;
    const int s0 = blockIdx.x * 64;
    const int mbase = (L_ - 64) - l0 + s0;

#pragma unroll
    for (int it = 0; it < 2; it++) {
        int u = tid + it * 256;
        int r = u >> 3, d4 = (u & 7) * 4;
        float4 qf = *(const float4*)(qkv + (size_t)((l0 + r) * NB + n) * 768 + h * 32 + d4);
        float4 uu = *(const float4*)(pu + h * 32 + d4);
        float4 vv = *(const float4*)(pv + h * 32 + d4);
        *(uint2*)(QUh + r * 40 + d4) =
            make_uint2(pack_h2(qf.x + uu.x, qf.y + uu.y), pack_h2(qf.z + uu.z, qf.w + uu.w));
        *(uint2*)(QVh + r * 40 + d4) =
            make_uint2(pack_h2(qf.x + vv.x, qf.y + vv.y), pack_h2(qf.z + vv.z, qf.w + vv.w));
        float4 kf = *(const float4*)(qkv + (size_t)((s0 + r) * NB + n) * 768 + 256 + h * 32 + d4);
        *(uint2*)(KSh + r * 40 + d4) =
            make_uint2(pack_h2(kf.x, kf.y), pack_h2(kf.z, kf.w));
    }
#pragma unroll
    for (int it = 0; it < 4; it++) {
        int u = tid + it * 256;
        int r = u >> 3, d4 = (u & 7) * 4;
        int m = mbase + r;
        float4 pf = make_float4(0.f, 0.f, 0.f, 0.f);
        if (m < PM) pf = *(const float4*)(p + (size_t)m * 256 + h * 32 + d4);
        *(uint2*)(PSh + r * 40 + d4) =
            make_uint2(pack_h2(pf.x, pf.y), pack_h2(pf.z, pf.w));
    }
    __syncthreads();

    const int wid = tid >> 5, lane = tid & 31;
    const int grp = lane >> 2, tig = lane & 3;
    const int wm = (wid >> 1) * 16;
    const int wnA = (wid & 1) * 32;
    const int wnB = (wid & 1) * 64;

    float acA[4][4] = {}, acB[8][4] = {};
#pragma unroll
    for (int kst = 0; kst < 2; kst++) {
        const int kb = kst * 16;
        uint32_t aU[4], aV[4];
        aU[0] = *(const uint32_t*)(QUh + (wm + grp) * 40 + kb + tig * 2);
        aU[1] = *(const uint32_t*)(QUh + (wm + grp + 8) * 40 + kb + tig * 2);
        aU[2] = *(const uint32_t*)(QUh + (wm + grp) * 40 + kb + 8 + tig * 2);
        aU[3] = *(const uint32_t*)(QUh + (wm + grp + 8) * 40 + kb + 8 + tig * 2);
        aV[0] = *(const uint32_t*)(QVh + (wm + grp) * 40 + kb + tig * 2);
        aV[1] = *(const uint32_t*)(QVh + (wm + grp + 8) * 40 + kb + tig * 2);
        aV[2] = *(const uint32_t*)(QVh + (wm + grp) * 40 + kb + 8 + tig * 2);
        aV[3] = *(const uint32_t*)(QVh + (wm + grp + 8) * 40 + kb + 8 + tig * 2);
#pragma unroll
        for (int nt = 0; nt < 4; nt++) {
            int nr = wnA + nt * 8 + grp;
            uint32_t b[2] = { *(const uint32_t*)(KSh + nr * 40 + kb + tig * 2),
                              *(const uint32_t*)(KSh + nr * 40 + kb + 8 + tig * 2) };
            mma_f16(acA[nt], aU, b);
        }
#pragma unroll
        for (int nt = 0; nt < 8; nt++) {
            int nr = wnB + nt * 8 + grp;
            uint32_t b[2] = { *(const uint32_t*)(PSh + nr * 40 + kb + tig * 2),
                              *(const uint32_t*)(PSh + nr * 40 + kb + 8 + tig * 2) };
            mma_f16(acB[nt], aV, b);
        }
    }
    __syncthreads();   // phase1 smem dead; reuse for accumulators

#pragma unroll
    for (int nt = 0; nt < 4; nt++) {
        int col = wnA + nt * 8 + tig * 2;
        *(float2*)&ACs[(wm + grp) * 68 + col]     = make_float2(acA[nt][0], acA[nt][1]);
        *(float2*)&ACs[(wm + grp + 8) * 68 + col] = make_float2(acA[nt][2], acA[nt][3]);
    }
#pragma unroll
    for (int nt = 0; nt < 8; nt++) {
        int col = wnB + nt * 8 + tig * 2;
        *(float2*)&BDs[(wm + grp) * 132 + col]     = make_float2(acB[nt][0], acB[nt][1]);
        *(float2*)&BDs[(wm + grp + 8) * 132 + col] = make_float2(acB[nt][2], acB[nt][3]);
    }
    __syncthreads();

    const float scal = 0.17677669529663687f;   // 1/sqrt(32)
    const int cc = (tid & 15) * 4;
    const int rb = tid >> 4;
#pragma unroll
    for (int it = 0; it < 4; it++) {
        int r = rb + it * 16;
        int off = 63 - r + cc;
        float o0 = (ACs[r * 68 + cc + 0] + BDs[r * 132 + off + 0]) * scal;
        float o1 = (ACs[r * 68 + cc + 1] + BDs[r * 132 + off + 1]) * scal;
        float o2 = (ACs[r * 68 + cc + 2] + BDs[r * 132 + off + 2]) * scal;
        float o3 = (ACs[r * 68 + cc + 3] + BDs[r * 132 + off + 3]) * scal;
        *(uint2*)(th + (((size_t)nh) << 20) + (size_t)(l0 + r) * L_ + s0 + cc)
            = make_uint2(pack_h2(o0, o1), pack_h2(o2, o3));
    }
}

// ---- fused proj_in + scores_out + softmax: one block per (n,l) row ------------
__global__ __launch_bounds__(256) void out_softmax_kernel(
    __half* __restrict__ th, const float* __restrict__ asi,
    const float* __restrict__ projIn, const float* __restrict__ projOut,
    float* __restrict__ scores_out)
{
    __shared__ float ts[8][1028];
    __shared__ float pin[64], pout[64];
    __shared__ float red[8][8];
    const int tid = threadIdx.x;
    const int b = blockIdx.x;
    const int n = b >> 10, l = b & 1023;
    if (tid < 64) { pin[tid] = projIn[tid]; pout[tid] = projOut[tid]; }

#pragma unroll
    for (int h = 0; h < 8; h++) {
        uint2 hv = *(const uint2*)(th + (((size_t)(n * 8 + h)) << 20)
                                      + ((size_t)l << 10) + tid * 4);
        float2 p0 = __half22float2(*(__half2*)&hv.x);
        float2 p1 = __half22float2(*(__half2*)&hv.y);
        *(float4*)&ts[h][tid * 4] = make_float4(p0.x, p0.y, p1.x, p1.y);
    }
    __syncthreads();

    const int s = tid * 4;
    const size_t abase = ((size_t)n << 23) + ((size_t)l << 13) + ((size_t)s << 3);
    for (int js = 0; js < 4; js++) {
        float4 a0 = *(const float4*)(asi + abase + js * 8);
        float4 a1 = *(const float4*)(asi + abase + js * 8 + 4);
        float a[8] = {a0.x, a0.y, a0.z, a0.w, a1.x, a1.y, a1.z, a1.w};
        float tn8[8];
#pragma unroll
        for (int h = 0; h < 8; h++) {
            float t = ts[h][s + js];
#pragma unroll
            for (int g = 0; g < 8; g++) t = fmaf(a[g], pin[g * 8 + h], t);
            tn8[h] = t;
        }
        float o[8];
#pragma unroll
        for (int g = 0; g < 8; g++) {
            float sum = a[g];
#pragma unroll
            for (int h = 0; h < 8; h++) sum = fmaf(tn8[h], pout[h * 8 + g], sum);
            o[g] = sum;
        }
        *(float4*)(scores_out + abase + js * 8)     = make_float4(o[0], o[1], o[2], o[3]);
        *(float4*)(scores_out + abase + js * 8 + 4) = make_float4(o[4], o[5], o[6], o[7]);
#pragma unroll
        for (int h = 0; h < 8; h++) ts[h][s + js] = tn8[h];
    }

    float mh[8];
#pragma unroll
    for (int h = 0; h < 8; h++) {
        float m = fmaxf(fmaxf(ts[h][s], ts[h][s+1]), fmaxf(ts[h][s+2], ts[h][s+3]));
#pragma unroll
        for (int o = 16; o > 0; o >>= 1) m = fmaxf(m, __shfl_xor_sync(0xffffffffu, m, o));
        mh[h] = m;
    }
    if ((tid & 31) == 0)
#pragma unroll
        for (int h = 0; h < 8; h++) red[h][tid >> 5] = mh[h];
    __syncthreads();
#pragma unroll
    for (int h = 0; h < 8; h++) {
        float m = red[h][0];
#pragma unroll
        for (int w = 1; w < 8; w++) m = fmaxf(m, red[h][w]);
        mh[h] = m;
    }
    __syncthreads();

    float sh[8];
#pragma unroll
    for (int h = 0; h < 8; h++) {
        float s0 = 0.f;
#pragma unroll
        for (int js = 0; js < 4; js++) {
            float e = expf(ts[h][s + js] - mh[h]);
            ts[h][s + js] = e;
            s0 += e;
        }
#pragma unroll
        for (int o = 16; o > 0; o >>= 1) s0 += __shfl_xor_sync(0xffffffffu, s0, o);
        sh[h] = s0;
    }
    if ((tid & 31) == 0)
#pragma unroll
        for (int h = 0; h < 8; h++) red[h][tid >> 5] = sh[h];
    __syncthreads();
#pragma unroll
    for (int h = 0; h < 8; h++) {
        float ss = red[h][0] + red[h][1] + red[h][2] + red[h][3]
                 + red[h][4] + red[h][5] + red[h][6] + red[h][7];
        float inv = 1.f / ss;
        uint32_t h0 = pack_h2(ts[h][s] * inv, ts[h][s+1] * inv);
        uint32_t h1v = pack_h2(ts[h][s+2] * inv, ts[h][s+3] * inv);
        *(uint2*)(th + (((size_t)(n * 8 + h)) << 20) + ((size_t)l << 10) + s)
            = make_uint2(h0, h1v);
    }
}

// -------- av via fp16 MMA: ctx[l,n,h*32+d] = sum_s attn[n,h,l,s]*v[s,n,h,d] ---
__global__ __launch_bounds__(128) void av_kernel(
    const __half* __restrict__ attnh, const float* __restrict__ qkv,
    float* __restrict__ ctx)
{
    __shared__ __half As[64 * 136];
    __shared__ __half Vt[32 * 136];
    const int tid = threadIdx.x;
    const int wid = tid >> 5, lane = tid & 31;
    const int grp = lane >> 2, tig = lane & 3;
    const int nh = blockIdx.y;
    const int n = nh >> 3, h = nh & 7;
    const int l0 = blockIdx.x * 64;
    const uint32_t asb = smem_u32(As);
    const int wm = wid * 16;

    float acc[4][4];
#pragma unroll
    for (int nt = 0; nt < 4; nt++)
#pragma unroll
        for (int q = 0; q < 4; q++) acc[nt][q] = 0.f;

    const __half* abase = attnh + (((size_t)nh) << 20) + ((size_t)l0 << 10);

    for (int sc = 0; sc < 1024; sc += 128) {
#pragma unroll
        for (int i = 0; i < 8; i++) {
            int idx = tid + 128 * i;
            int r = idx >> 4, c = idx & 15;
            cp16s(asb + (uint32_t)(r * 136 + c * 8) * 2,
                  abase + ((size_t)r << 10) + sc + c * 8);
        }
        asm volatile("cp.async.commit_group;" ::: "memory");
        {
            int sr = tid;
            const float* vp = qkv + (size_t)((sc + sr) * NB + n) * 768 + 512 + h * 32;
#pragma unroll
            for (int d4 = 0; d4 < 8; d4++) {
                float4 v = *(const float4*)(vp + d4 * 4);
                Vt[(d4 * 4 + 0) * 136 + sr] = __float2half_rn(v.x);
                Vt[(d4 * 4 + 1) * 136 + sr] = __float2half_rn(v.y);
                Vt[(d4 * 4 + 2) * 136 + sr] = __float2half_rn(v.z);
                Vt[(d4 * 4 + 3) * 136 + sr] = __float2half_rn(v.w);
            }
        }
        asm volatile("cp.async.wait_group 0;" ::: "memory");
        __syncthreads();
#pragma unroll
        for (int ks = 0; ks < 8; ks++) {
            const int kb = ks * 16;
            uint32_t a[4], b[4][2];
            a[0] = *(const uint32_t*)(As + (wm + grp) * 136 + kb + tig * 2);
            a[1] = *(const uint32_t*)(As + (wm + grp + 8) * 136 + kb + tig * 2);
            a[2] = *(const uint32_t*)(As + (wm + grp) * 136 + kb + 8 + tig * 2);
            a[3] = *(const uint32_t*)(As + (wm + grp + 8) * 136 + kb + 8 + tig * 2);
#pragma unroll
            for (int nt = 0; nt < 4; nt++) {
                int nr = nt * 8 + grp;
                b[nt][0] = *(const uint32_t*)(Vt + nr * 136 + kb + tig * 2);
                b[nt][1] = *(const uint32_t*)(Vt + nr * 136 + kb + 8 + tig * 2);
            }
#pragma unroll
            for (int nt = 0; nt < 4; nt++)
                mma_f16(acc[nt], a, b[nt]);
        }
        __syncthreads();
    }

#pragma unroll
    for (int nt = 0; nt < 4; nt++) {
        int d = nt * 8 + tig * 2;
#pragma unroll
        for (int half = 0; half < 2; half++) {
            int l = l0 + wm + grp + half * 8;
            *(float2*)(ctx + (size_t)(l * NB + n) * 256 + h * 32 + d)
                = make_float2(acc[nt][half * 2], acc[nt][half * 2 + 1]);
        }
    }
}

// ---- fused GLU + depthwise conv(K=31) + bias + DoubleSwish (y fp16) -----------
__global__ __launch_bounds__(256) void gludw_kernel(
    const __half* __restrict__ y, const float* __restrict__ w,
    const float* __restrict__ b, float* __restrict__ out)
{
    __shared__ float in_s[32 * 161];
    __shared__ float w_s[32 * 33];
    const int l0 = blockIdx.x * 128;
    const int c0 = blockIdx.y * 32;
    const int n  = blockIdx.z;

    for (int idx = threadIdx.x; idx < 32 * 160; idx += 256) {
        int c = idx & 31, col = idx >> 5;
        int gl = l0 + col - 15;
        float v = 0.f;
        if (col < 158 && gl >= 0 && gl < L_) {
            size_t base = (size_t)(gl * NB + n) * 1024;
            float a = __half2float(y[base + c0 + c]);
            float g = __half2float(y[base + c0 + c + 512]);
            v = a / (1.f + expf(-g));
        }
        in_s[c * 161 + col] = v;
    }
    for (int idx = threadIdx.x; idx < 32 * KW; idx += 256) {
        int c = idx / KW, k = idx % KW;
        w_s[c * 33 + k] = w[(c0 + c) * KW + k];
    }
    __syncthreads();

    const int ci = threadIdx.x & 31;
    const int lq = threadIdx.x >> 5;
    const float bb = b[c0 + ci];
#pragma unroll
    for (int lt = 0; lt < 16; lt++) {
        int ll = lt * 8 + lq;
        float s = bb;
#pragma unroll
        for (int k = 0; k < KW; k++)
            s = fmaf(in_s[ci * 161 + ll + k], w_s[ci * 33 + k], s);
        float v = s / (1.f + expf(1.f - s));
        out[(((size_t)((l0 + ll) * NB + n)) << 9) + c0 + ci] = v;
    }
}

// -------- BasicNorm -> d_out ---------------------------------------------------
__global__ __launch_bounds__(128) void norm_kernel(
    const float* __restrict__ x, const float* __restrict__ leps,
    float* __restrict__ out)
{
    __shared__ float red[4];
    const size_t base = (size_t)blockIdx.x * 512;
    float4 v = ((const float4*)(x + base))[threadIdx.x];
    float ss = v.x * v.x + v.y * v.y + v.z * v.z + v.w * v.w;
#pragma unroll
    for (int o = 16; o > 0; o >>= 1) ss += __shfl_xor_sync(0xffffffffu, ss, o);
    if ((threadIdx.x & 31) == 0) red[threadIdx.x >> 5] = ss;
    __syncthreads();
    float tot = red[0] + red[1] + red[2] + red[3];
    float scale = rsqrtf(tot * (1.f / 512.f) + expf(leps[0]));
    ((float4*)(out + base))[threadIdx.x] =
        make_float4(v.x * scale, v.y * scale, v.z * scale, v.w * scale);
}

// ------------------------------- launcher -------------------------------------
extern "C" void kernel_launch(void* const* d_in, const int* in_sizes, int n_in,
                              void* d_out, int out_size)
{
    const float* src      = (const float*)d_in[0];
    const float* pos_emb  = (const float*)d_in[1];
    const float* asi      = (const float*)d_in[2];
    const float* w_in     = (const float*)d_in[3];
    const float* b_in     = (const float*)d_in[4];
    const float* w_pos    = (const float*)d_in[5];
    const float* pbu      = (const float*)d_in[6];
    const float* pbv      = (const float*)d_in[7];
    const float* projIn   = (const float*)d_in[8];
    const float* projOut  = (const float*)d_in[9];
    const float* w_out    = (const float*)d_in[10];
    const float* b_out    = (const float*)d_in[11];
    const float* w_ff1m   = (const float*)d_in[12];
    const float* b_ff1m   = (const float*)d_in[13];
    const float* w_ff2m   = (const float*)d_in[14];
    const float* b_ff2m   = (const float*)d_in[15];
    const float* w_ff1    = (const float*)d_in[16];
    const float* b_ff1    = (const float*)d_in[17];
    const float* w_ff2    = (const float*)d_in[18];
    const float* b_ff2    = (const float*)d_in[19];
    const float* w_pw1    = (const float*)d_in[20];
    const float* b_pw1    = (const float*)d_in[21];
    const float* w_dw     = (const float*)d_in[22];
    const float* b_dw     = (const float*)d_in[23];
    const float* w_pw2    = (const float*)d_in[24];
    const float* b_pw2    = (const float*)d_in[25];
    const float* leps     = (const float*)d_in[26];

    float* out        = (float*)d_out;
    float* out_scores = out + (size_t)TOK * E_;

    float *h1, *x, *qkv, *p, *ctx, *x2, *hct, *x3, *x4;
    __half *whf, *th, *y;
    cudaGetSymbolAddress((void**)&h1,   g_h1);
    cudaGetSymbolAddress((void**)&x,    g_x);
    cudaGetSymbolAddress((void**)&qkv,  g_qkv);
    cudaGetSymbolAddress((void**)&p,    g_p);
    cudaGetSymbolAddress((void**)&th,   g_th);
    cudaGetSymbolAddress((void**)&ctx,  g_ctx);
    cudaGetSymbolAddress((void**)&x2,   g_x2);
    cudaGetSymbolAddress((void**)&y,    g_y);
    cudaGetSymbolAddress((void**)&hct,  g_hct);
    cudaGetSymbolAddress((void**)&x3,   g_x3);
    cudaGetSymbolAddress((void**)&x4,   g_x4);
    cudaGetSymbolAddress((void**)&whf,  g_whf);
    __half* h1h = (__half*)h1;

    static bool attr_set = false;
    if (!attr_set) {
        cudaFuncSetAttribute(hgemm<1,0,1,64>,  cudaFuncAttributeMaxDynamicSharedMemorySize, TH_SMEM_MT(64));
        cudaFuncSetAttribute(hgemm<0,0,0,64>,  cudaFuncAttributeMaxDynamicSharedMemorySize, TH_SMEM_MT(64));
        cudaFuncSetAttribute(hgemm<2,1,0,128>, cudaFuncAttributeMaxDynamicSharedMemorySize, TH_SMEM_MT(128));
        cudaFuncSetAttribute(hgemm<2,0,0,128>, cudaFuncAttributeMaxDynamicSharedMemorySize, TH_SMEM_MT(128));
        cudaFuncSetAttribute(hgemm<0,0,1,128>, cudaFuncAttributeMaxDynamicSharedMemorySize, TH_SMEM_MT(128));
        cudaFuncSetAttribute(scores_mma_kernel, cudaFuncAttributeMaxDynamicSharedMemorySize, SC_SMEM);
        attr_set = true;
    }

    // prepass: convert all B (weight) operands to fp16
    CvtArgs ca;
    ca.src[0] = w_ff1m; ca.dstoff[0] = OFF_FF1M; ca.n4[0] = (DFF_ * E_) / 4;
    ca.src[1] = w_ff2m; ca.dstoff[1] = OFF_FF2M; ca.n4[1] = (E_ * DFF_) / 4;
    ca.src[2] = w_in;   ca.dstoff[2] = OFF_IN;   ca.n4[2] = (768 * E_) / 4;
    ca.src[3] = w_pos;  ca.dstoff[3] = OFF_POS;  ca.n4[3] = (E2_ * E_) / 4;
    ca.src[4] = w_out;  ca.dstoff[4] = OFF_OUT;  ca.n4[4] = (E_ * E2_) / 4;
    ca.src[5] = w_pw1;  ca.dstoff[5] = OFF_PW1;  ca.n4[5] = (1024 * E_) / 4;
    ca.src[6] = w_pw2;  ca.dstoff[6] = OFF_PW2;  ca.n4[6] = (E_ * E_) / 4;
    ca.src[7] = w_ff1;  ca.dstoff[7] = OFF_FF1;  ca.n4[7] = (DFF_ * E_) / 4;
    ca.src[8] = w_ff2;  ca.dstoff[8] = OFF_FF2;  ca.n4[8] = (E_ * DFF_) / 4;
    cvtw_kernel<<<dim3(1024, 9), 256>>>(ca);

    // macaron FFN
    hgemm<1,0,1,64><<<dim3(DFF_ / 128, TOK / 64), 256, TH_SMEM_MT(64)>>>(src, whf + OFF_FF1M, b_ff1m, nullptr, h1h, TOK, DFF_, E_);
    hgemm<2,1,0,128><<<dim3(E_ / 128, TOK / 128), 256, TH_SMEM_MT(128)>>>(h1h, whf + OFF_FF2M, b_ff2m, src, x, TOK, E_, DFF_);

    // attention inputs
    hgemm<0,0,0,64><<<dim3(768 / 128, TOK / 64), 256, TH_SMEM_MT(64)>>>(x, whf + OFF_IN, b_in, nullptr, qkv, TOK, 768, E_);
    hgemm<0,0,0,64><<<dim3(2, 32), 256, TH_SMEM_MT(64)>>>(pos_emb, whf + OFF_POS, nullptr, nullptr, p, PM, 256, E_);

    // scores (fp16 MMA, fp16 logits) -> fused softmax (probs in place) -> AV
    scores_mma_kernel<<<dim3(16, 16, 32), 256, SC_SMEM>>>(qkv, p, pbu, pbv, th);
    out_softmax_kernel<<<4096, 256>>>(th, asi, projIn, projOut, out_scores);
    av_kernel<<<dim3(16, 32), 128>>>(th, qkv, ctx);
    hgemm<2,0,0,128><<<dim3(E_ / 128, TOK / 128), 256, TH_SMEM_MT(128)>>>(ctx, whf + OFF_OUT, b_out, x, x2, TOK, E_, E2_);

    // conv module (pw1 -> fp16 y; GLU fused into dwconv)
    hgemm<0,0,1,128><<<dim3(1024 / 128, TOK / 128), 256, TH_SMEM_MT(128)>>>(x2, whf + OFF_PW1, b_pw1, nullptr, y, TOK, 1024, E_);
    gludw_kernel<<<dim3(8, 16, NB), 256>>>(y, w_dw, b_dw, hct);
    hgemm<2,0,0,128><<<dim3(E_ / 128, TOK / 128), 256, TH_SMEM_MT(128)>>>(hct, whf + OFF_PW2, b_pw2, x2, x3, TOK, E_, E_);

    // final FFN + BasicNorm
    hgemm<1,0,1,64><<<dim3(DFF_ / 128, TOK / 64), 256, TH_SMEM_MT(64)>>>(x3, whf + OFF_FF1, b_ff1, nullptr, h1h, TOK, DFF_, E_);
    hgemm<2,1,0,128><<<dim3(E_ / 128, TOK / 128), 256, TH_SMEM_MT(128)>>>(h1h, whf + OFF_FF2, b_ff2, x3, x4, TOK, E_, DFF_);
    norm_kernel<<<TOK, 128>>>(x4, leps, out);
}

// round 16
// speedup vs baseline: 1.2288x; 1.0218x over previous
#include <cuda_runtime.h>
#include <cuda_fp16.h>
#include <math.h>
#include <stdint.h>

#define L_    1024
#define NB    4
#define E_    512
#define H_    8
#define D_    32
#define DFF_  2048
#define E2_   256
#define TOK   4096      // L*NB
#define PM    2047      // 2L-1
#define KW    31

// ---------------- scratch (static device globals; no allocation) -------------
__device__ float g_h1[(size_t)TOK * DFF_];            // reused as __half for h1
__device__ float g_x[(size_t)TOK * E_];
__device__ __half g_qkvh[(size_t)TOK * 768];          // qkv fp16
__device__ __half g_ph[(size_t)2048 * 256];           // pos projection fp16
__device__ __half g_th[(size_t)32 * 1024 * 1024];     // (N,H,L,S) logits -> probs
__device__ __half g_ctxh[(size_t)TOK * E2_];          // attn context fp16
__device__ float g_x2[(size_t)TOK * E_];
__device__ __half g_y[(size_t)TOK * 1024];            // pw1 output fp16
__device__ __half g_hcth[(size_t)TOK * E_];           // conv output fp16
__device__ float g_x3[(size_t)TOK * E_];
__device__ float g_x4[(size_t)TOK * E_];
__device__ __half g_whf[(size_t)5636096];             // fp16 weights

// fp16 weight scratch offsets (elements)
#define OFF_FF1M 0
#define OFF_FF2M 1048576
#define OFF_IN   2097152
#define OFF_POS  2490368
#define OFF_OUT  2621440
#define OFF_PW1  2752512
#define OFF_PW2  3276800
#define OFF_FF1  3538944
#define OFF_FF2  4587520

// ---------------- helpers ------------------------------------------------------
__device__ __forceinline__ void mma_f16(float* c, const uint32_t* a, const uint32_t* b) {
    asm volatile(
        "mma.sync.aligned.m16n8k16.row.col.f32.f16.f16.f32 "
        "{%0,%1,%2,%3}, {%4,%5,%6,%7}, {%8,%9}, {%0,%1,%2,%3};"
        : "+f"(c[0]), "+f"(c[1]), "+f"(c[2]), "+f"(c[3])
        : "r"(a[0]), "r"(a[1]), "r"(a[2]), "r"(a[3]), "r"(b[0]), "r"(b[1]));
}
__device__ __forceinline__ void cp16s(uint32_t daddr, const void* src) {
    asm volatile("cp.async.ca.shared.global [%0], [%1], 16;\n" :: "r"(daddr), "l"(src));
}
__device__ __forceinline__ uint32_t smem_u32(const void* p) {
    uint32_t a;
    asm("{ .reg .u64 t; cvta.to.shared.u64 t, %1; cvt.u32.u64 %0, t; }" : "=r"(a) : "l"(p));
    return a;
}
__device__ __forceinline__ uint32_t pack_h2(float x, float y) {
    __half2 h = __floats2half2_rn(x, y);
    return *(uint32_t*)&h;
}

// -------- prepass: convert 9 weight matrices to fp16 into g_whf ----------------
struct CvtArgs {
    const float* src[9];
    int dstoff[9];
    int n4[9];
};
__global__ __launch_bounds__(256) void cvtw_kernel(CvtArgs args) {
    const int wi = blockIdx.y;
    const int idx = blockIdx.x * 256 + threadIdx.x;
    if (idx >= args.n4[wi]) return;
    float4 v = *(const float4*)(args.src[wi] + (size_t)idx * 4);
    uint32_t lo = pack_h2(v.x, v.y);
    uint32_t hi = pack_h2(v.z, v.w);
    *(uint2*)(g_whf + args.dstoff[wi] + (size_t)idx * 4) = make_uint2(lo, hi);
}

// ------- cp.async double-buffered fp16 GEMM, MT-row CTA tile ------------------
#define TH_STRIDE 40
#define TH_SMEM_MT(MT) ((2 * (MT) * TH_STRIDE + 2 * 128 * TH_STRIDE) * 2)
template <int EPI, int AH, int CH, int MT>
__global__ __launch_bounds__(256, 2) void hgemm(
    const void* __restrict__ Av, const __half* __restrict__ B,
    const float* __restrict__ bias, const float* __restrict__ res,
    void* __restrict__ Cv, int M, int Nn, int Kk)
{
    extern __shared__ __half smh[];
    const uint32_t smb = smem_u32(smh);
    const float*  A  = (const float*)Av;
    const __half* Ah = (const __half*)Av;
    float*  C  = (float*)Cv;
    __half* Ch = (__half*)Cv;

    constexpr int TPR  = 256 / MT;
    constexpr int CHK  = 32 / TPR;
    constexpr int ABUF = MT * TH_STRIDE;
    constexpr int BBUF = 128 * TH_STRIDE;
    constexpr int MTS  = MT / 32;

    const int tid   = threadIdx.x;
    const int wid   = tid >> 5;
    const int lane  = tid & 31;
    const int grp   = lane >> 2;
    const int tig   = lane & 3;
    const int row0  = blockIdx.y * MT;
    const int col0  = blockIdx.x * 128;
    const int wm    = (wid >> 2) * (MT / 2);
    const int wn    = (wid & 3) * 32;
    const int srow  = tid / TPR;
    const int scol  = (tid % TPR) * CHK;
    const int brow  = tid >> 1;
    const int bcol  = (tid & 1) * 16;

    float acc[MTS][4][4];
#pragma unroll
    for (int mt = 0; mt < MTS; mt++)
#pragma unroll
        for (int nt = 0; nt < 4; nt++)
#pragma unroll
            for (int q = 0; q < 4; q++) acc[mt][nt][q] = 0.f;

    float4 ast[CHK / 4];
#define LDGA(t) {                                                               \
        int ar = row0 + srow; if (ar >= M) ar = M - 1;                          \
        const float* ap = A + (size_t)ar * Kk + (t) * 32 + scol;                \
        _Pragma("unroll")                                                       \
        for (int i = 0; i < CHK / 4; i++) ast[i] = *(const float4*)(ap + i * 4); }
#define STSA(bf) {                                                              \
        __half* dst = smh + (bf) * ABUF + srow * TH_STRIDE + scol;              \
        _Pragma("unroll")                                                       \
        for (int i = 0; i < CHK / 4; i++) {                                     \
            uint32_t h0 = pack_h2(ast[i].x, ast[i].y);                          \
            uint32_t h1 = pack_h2(ast[i].z, ast[i].w);                          \
            *(uint2*)(dst + i * 4) = make_uint2(h0, h1); } }
#define LOADA(t) {                                                              \
        uint32_t base = smb + (uint32_t)(((t & 1) * ABUF + srow * TH_STRIDE + scol) * 2); \
        int ar = row0 + srow; if (ar >= M) ar = M - 1;                          \
        const __half* ap = Ah + (size_t)ar * Kk + (t) * 32 + scol;              \
        cp16s(base, ap);                                                        \
        if (CHK == 16) cp16s(base + 16, ap + 8); }
#define LOADB(t) {                                                              \
        uint32_t base = smb + (uint32_t)((2 * ABUF + ((t) & 1) * BBUF + brow * TH_STRIDE + bcol) * 2); \
        const __half* bp = B + (size_t)(col0 + brow) * Kk + (t) * 32 + bcol;    \
        cp16s(base,      bp);                                                   \
        cp16s(base + 16, bp + 8); }
#define COMMIT asm volatile("cp.async.commit_group;" ::: "memory")

    const int ntile = Kk >> 5;
    if (AH) { LOADA(0); }
    else    { LDGA(0); STSA(0); if (ntile > 1) LDGA(1); }
    LOADB(0); COMMIT;
    int buf = 0;
    for (int t = 0; t < ntile; t++) {
        if (t + 1 < ntile) {
            if (AH) LOADA(t + 1);
            LOADB(t + 1); COMMIT;
            if (!AH) { STSA(buf ^ 1); if (t + 2 < ntile) LDGA(t + 2); }
            asm volatile("cp.async.wait_group 1;" ::: "memory");
        } else {
            asm volatile("cp.async.wait_group 0;" ::: "memory");
        }
        __syncthreads();
        const __half* Ab = smh + buf * ABUF;
        const __half* Bb = smh + 2 * ABUF + buf * BBUF;
#pragma unroll
        for (int kst = 0; kst < 2; kst++) {
            const int kb = kst * 16;
            uint32_t a[MTS][4], b[4][2];
#pragma unroll
            for (int mt = 0; mt < MTS; mt++) {
                int mr = wm + mt * 16 + grp;
                a[mt][0] = *(const uint32_t*)(Ab + mr * TH_STRIDE + kb + tig * 2);
                a[mt][1] = *(const uint32_t*)(Ab + (mr + 8) * TH_STRIDE + kb + tig * 2);
                a[mt][2] = *(const uint32_t*)(Ab + mr * TH_STRIDE + kb + 8 + tig * 2);
                a[mt][3] = *(const uint32_t*)(Ab + (mr + 8) * TH_STRIDE + kb + 8 + tig * 2);
            }
#pragma unroll
            for (int nt = 0; nt < 4; nt++) {
                int nr = wn + nt * 8 + grp;
                b[nt][0] = *(const uint32_t*)(Bb + nr * TH_STRIDE + kb + tig * 2);
                b[nt][1] = *(const uint32_t*)(Bb + nr * TH_STRIDE + kb + 8 + tig * 2);
            }
#pragma unroll
            for (int mt = 0; mt < MTS; mt++)
#pragma unroll
                for (int nt = 0; nt < 4; nt++)
                    mma_f16(acc[mt][nt], a[mt], b[nt]);
        }
        __syncthreads();
        buf ^= 1;
    }
#undef LDGA
#undef STSA
#undef LOADA
#undef LOADB
#undef COMMIT

#pragma unroll
    for (int mt = 0; mt < MTS; mt++) {
        int rbase = row0 + wm + mt * 16 + grp;
#pragma unroll
        for (int nt = 0; nt < 4; nt++) {
            int col = col0 + wn + nt * 8 + tig * 2;
            float2 bb = make_float2(0.f, 0.f);
            if (bias) bb = *(const float2*)(bias + col);
#pragma unroll
            for (int half = 0; half < 2; half++) {
                int row = rbase + half * 8;
                if (row >= M) continue;
                float v0 = acc[mt][nt][half * 2 + 0] + bb.x;
                float v1 = acc[mt][nt][half * 2 + 1] + bb.y;
                if (EPI == 1) {
                    v0 = v0 / (1.f + expf(1.f - v0));
                    v1 = v1 / (1.f + expf(1.f - v1));
                }
                if (EPI == 2) {
                    float2 rr = *(const float2*)(res + (size_t)row * Nn + col);
                    v0 += rr.x; v1 += rr.y;
                }
                if (CH) {
                    *(uint32_t*)(Ch + (size_t)row * Nn + col) = pack_h2(v0, v1);
                } else {
                    *(float2*)(C + (size_t)row * Nn + col) = make_float2(v0, v1);
                }
            }
        }
    }
}

// -------- fp16-MMA scores -> fp16 logits (qkv/p already fp16) ------------------
#define SC_SMEM (12800 * (int)sizeof(float))   // 51200 bytes
__global__ __launch_bounds__(256) void scores_mma_kernel(
    const __half* __restrict__ qkvh, const __half* __restrict__ ph,
    const float* __restrict__ pu, const float* __restrict__ pv,
    __half* __restrict__ th)
{
    extern __shared__ float sm[];
    __half* QUh = (__half*)sm;           // [64][40]
    __half* QVh = QUh + 2560;            // [64][40]
    __half* KSh = QUh + 5120;            // [64][40]
    __half* PSh = QUh + 7680;            // [128][40]
    float* ACs = sm;                     // [64][68]  (phase 2)
    float* BDs = sm + 4352;              // [64][132] (phase 2)

    const int tid = threadIdx.x;
    const int nh = blockIdx.z;
    const int n = nh >> 3, h = nh & 7;
    const int l0 = blockIdx.y * 64;
    const int s0 = blockIdx.x * 64;
    const int mbase = (L_ - 64) - l0 + s0;

#pragma unroll
    for (int it = 0; it < 2; it++) {
        int u = tid + it * 256;
        int r = u >> 3, d4 = (u & 7) * 4;
        uint2 qv2 = *(const uint2*)(qkvh + (size_t)((l0 + r) * NB + n) * 768 + h * 32 + d4);
        float2 q01 = __half22float2(*(__half2*)&qv2.x);
        float2 q23 = __half22float2(*(__half2*)&qv2.y);
        float4 uu = *(const float4*)(pu + h * 32 + d4);
        float4 vv = *(const float4*)(pv + h * 32 + d4);
        *(uint2*)(QUh + r * 40 + d4) =
            make_uint2(pack_h2(q01.x + uu.x, q01.y + uu.y), pack_h2(q23.x + uu.z, q23.y + uu.w));
        *(uint2*)(QVh + r * 40 + d4) =
            make_uint2(pack_h2(q01.x + vv.x, q01.y + vv.y), pack_h2(q23.x + vv.z, q23.y + vv.w));
        *(uint2*)(KSh + r * 40 + d4) =
            *(const uint2*)(qkvh + (size_t)((s0 + r) * NB + n) * 768 + 256 + h * 32 + d4);
    }
#pragma unroll
    for (int it = 0; it < 4; it++) {
        int u = tid + it * 256;
        int r = u >> 3, d4 = (u & 7) * 4;
        int m = mbase + r;
        uint2 pf = make_uint2(0u, 0u);
        if (m < PM) pf = *(const uint2*)(ph + (size_t)m * 256 + h * 32 + d4);
        *(uint2*)(PSh + r * 40 + d4) = pf;
    }
    __syncthreads();

    const int wid = tid >> 5, lane = tid & 31;
    const int grp = lane >> 2, tig = lane & 3;
    const int wm = (wid >> 1) * 16;
    const int wnA = (wid & 1) * 32;
    const int wnB = (wid & 1) * 64;

    float acA[4][4] = {}, acB[8][4] = {};
#pragma unroll
    for (int kst = 0; kst < 2; kst++) {
        const int kb = kst * 16;
        uint32_t aU[4], aV[4];
        aU[0] = *(const uint32_t*)(QUh + (wm + grp) * 40 + kb + tig * 2);
        aU[1] = *(const uint32_t*)(QUh + (wm + grp + 8) * 40 + kb + tig * 2);
        aU[2] = *(const uint32_t*)(QUh + (wm + grp) * 40 + kb + 8 + tig * 2);
        aU[3] = *(const uint32_t*)(QUh + (wm + grp + 8) * 40 + kb + 8 + tig * 2);
        aV[0] = *(const uint32_t*)(QVh + (wm + grp) * 40 + kb + tig * 2);
        aV[1] = *(const uint32_t*)(QVh + (wm + grp + 8) * 40 + kb + tig * 2);
        aV[2] = *(const uint32_t*)(QVh + (wm + grp) * 40 + kb + 8 + tig * 2);
        aV[3] = *(const uint32_t*)(QVh + (wm + grp + 8) * 40 + kb + 8 + tig * 2);
#pragma unroll
        for (int nt = 0; nt < 4; nt++) {
            int nr = wnA + nt * 8 + grp;
            uint32_t b[2] = { *(const uint32_t*)(KSh + nr * 40 + kb + tig * 2),
                              *(const uint32_t*)(KSh + nr * 40 + kb + 8 + tig * 2) };
            mma_f16(acA[nt], aU, b);
        }
#pragma unroll
        for (int nt = 0; nt < 8; nt++) {
            int nr = wnB + nt * 8 + grp;
            uint32_t b[2] = { *(const uint32_t*)(PSh + nr * 40 + kb + tig * 2),
                              *(const uint32_t*)(PSh + nr * 40 + kb + 8 + tig * 2) };
            mma_f16(acB[nt], aV, b);
        }
    }
    __syncthreads();

#pragma unroll
    for (int nt = 0; nt < 4; nt++) {
        int col = wnA + nt * 8 + tig * 2;
        *(float2*)&ACs[(wm + grp) * 68 + col]     = make_float2(acA[nt][0], acA[nt][1]);
        *(float2*)&ACs[(wm + grp + 8) * 68 + col] = make_float2(acA[nt][2], acA[nt][3]);
    }
#pragma unroll
    for (int nt = 0; nt < 8; nt++) {
        int col = wnB + nt * 8 + tig * 2;
        *(float2*)&BDs[(wm + grp) * 132 + col]     = make_float2(acB[nt][0], acB[nt][1]);
        *(float2*)&BDs[(wm + grp + 8) * 132 + col] = make_float2(acB[nt][2], acB[nt][3]);
    }
    __syncthreads();

    const float scal = 0.17677669529663687f;   // 1/sqrt(32)
    const int cc = (tid & 15) * 4;
    const int rb = tid >> 4;
#pragma unroll
    for (int it = 0; it < 4; it++) {
        int r = rb + it * 16;
        int off = 63 - r + cc;
        float o0 = (ACs[r * 68 + cc + 0] + BDs[r * 132 + off + 0]) * scal;
        float o1 = (ACs[r * 68 + cc + 1] + BDs[r * 132 + off + 1]) * scal;
        float o2 = (ACs[r * 68 + cc + 2] + BDs[r * 132 + off + 2]) * scal;
        float o3 = (ACs[r * 68 + cc + 3] + BDs[r * 132 + off + 3]) * scal;
        *(uint2*)(th + (((size_t)nh) << 20) + (size_t)(l0 + r) * L_ + s0 + cc)
            = make_uint2(pack_h2(o0, o1), pack_h2(o2, o3));
    }
}

// ---- fused proj_in + scores_out + softmax: one block per (n,l) row ------------
__global__ __launch_bounds__(256) void out_softmax_kernel(
    __half* __restrict__ th, const float* __restrict__ asi,
    const float* __restrict__ projIn, const float* __restrict__ projOut,
    float* __restrict__ scores_out)
{
    __shared__ float ts[8][1028];
    __shared__ float pin[64], pout[64];
    __shared__ float red[8][8];
    const int tid = threadIdx.x;
    const int b = blockIdx.x;
    const int n = b >> 10, l = b & 1023;
    if (tid < 64) { pin[tid] = projIn[tid]; pout[tid] = projOut[tid]; }

#pragma unroll
    for (int h = 0; h < 8; h++) {
        uint2 hv = *(const uint2*)(th + (((size_t)(n * 8 + h)) << 20)
                                      + ((size_t)l << 10) + tid * 4);
        float2 p0 = __half22float2(*(__half2*)&hv.x);
        float2 p1 = __half22float2(*(__half2*)&hv.y);
        *(float4*)&ts[h][tid * 4] = make_float4(p0.x, p0.y, p1.x, p1.y);
    }
    __syncthreads();

    const int s = tid * 4;
    const size_t abase = ((size_t)n << 23) + ((size_t)l << 13) + ((size_t)s << 3);
    for (int js = 0; js < 4; js++) {
        float4 a0 = *(const float4*)(asi + abase + js * 8);
        float4 a1 = *(const float4*)(asi + abase + js * 8 + 4);
        float a[8] = {a0.x, a0.y, a0.z, a0.w, a1.x, a1.y, a1.z, a1.w};
        float tn8[8];
#pragma unroll
        for (int h = 0; h < 8; h++) {
            float t = ts[h][s + js];
#pragma unroll
            for (int g = 0; g < 8; g++) t = fmaf(a[g], pin[g * 8 + h], t);
            tn8[h] = t;
        }
        float o[8];
#pragma unroll
        for (int g = 0; g < 8; g++) {
            float sum = a[g];
#pragma unroll
            for (int h = 0; h < 8; h++) sum = fmaf(tn8[h], pout[h * 8 + g], sum);
            o[g] = sum;
        }
        *(float4*)(scores_out + abase + js * 8)     = make_float4(o[0], o[1], o[2], o[3]);
        *(float4*)(scores_out + abase + js * 8 + 4) = make_float4(o[4], o[5], o[6], o[7]);
#pragma unroll
        for (int h = 0; h < 8; h++) ts[h][s + js] = tn8[h];
    }

    float mh[8];
#pragma unroll
    for (int h = 0; h < 8; h++) {
        float m = fmaxf(fmaxf(ts[h][s], ts[h][s+1]), fmaxf(ts[h][s+2], ts[h][s+3]));
#pragma unroll
        for (int o = 16; o > 0; o >>= 1) m = fmaxf(m, __shfl_xor_sync(0xffffffffu, m, o));
        mh[h] = m;
    }
    if ((tid & 31) == 0)
#pragma unroll
        for (int h = 0; h < 8; h++) red[h][tid >> 5] = mh[h];
    __syncthreads();
#pragma unroll
    for (int h = 0; h < 8; h++) {
        float m = red[h][0];
#pragma unroll
        for (int w = 1; w < 8; w++) m = fmaxf(m, red[h][w]);
        mh[h] = m;
    }
    __syncthreads();

    float sh[8];
#pragma unroll
    for (int h = 0; h < 8; h++) {
        float s0 = 0.f;
#pragma unroll
        for (int js = 0; js < 4; js++) {
            float e = expf(ts[h][s + js] - mh[h]);
            ts[h][s + js] = e;
            s0 += e;
        }
#pragma unroll
        for (int o = 16; o > 0; o >>= 1) s0 += __shfl_xor_sync(0xffffffffu, s0, o);
        sh[h] = s0;
    }
    if ((tid & 31) == 0)
#pragma unroll
        for (int h = 0; h < 8; h++) red[h][tid >> 5] = sh[h];
    __syncthreads();
#pragma unroll
    for (int h = 0; h < 8; h++) {
        float ss = red[h][0] + red[h][1] + red[h][2] + red[h][3]
                 + red[h][4] + red[h][5] + red[h][6] + red[h][7];
        float inv = 1.f / ss;
        uint32_t h0 = pack_h2(ts[h][s] * inv, ts[h][s+1] * inv);
        uint32_t h1v = pack_h2(ts[h][s+2] * inv, ts[h][s+3] * inv);
        *(uint2*)(th + (((size_t)(n * 8 + h)) << 20) + ((size_t)l << 10) + s)
            = make_uint2(h0, h1v);
    }
}

// -------- av via fp16 MMA (qkv fp16, ctx fp16 out) ----------------------------
__global__ __launch_bounds__(128) void av_kernel(
    const __half* __restrict__ attnh, const __half* __restrict__ qkvh,
    __half* __restrict__ ctxh)
{
    __shared__ __half As[64 * 136];
    __shared__ __half Vt[32 * 136];
    const int tid = threadIdx.x;
    const int wid = tid >> 5, lane = tid & 31;
    const int grp = lane >> 2, tig = lane & 3;
    const int nh = blockIdx.y;
    const int n = nh >> 3, h = nh & 7;
    const int l0 = blockIdx.x * 64;
    const uint32_t asb = smem_u32(As);
    const int wm = wid * 16;

    float acc[4][4];
#pragma unroll
    for (int nt = 0; nt < 4; nt++)
#pragma unroll
        for (int q = 0; q < 4; q++) acc[nt][q] = 0.f;

    const __half* abase = attnh + (((size_t)nh) << 20) + ((size_t)l0 << 10);

    for (int sc = 0; sc < 1024; sc += 128) {
#pragma unroll
        for (int i = 0; i < 8; i++) {
            int idx = tid + 128 * i;
            int r = idx >> 4, c = idx & 15;
            cp16s(asb + (uint32_t)(r * 136 + c * 8) * 2,
                  abase + ((size_t)r << 10) + sc + c * 8);
        }
        asm volatile("cp.async.commit_group;" ::: "memory");
        {
            int sr = tid;
            const __half* vp = qkvh + (size_t)((sc + sr) * NB + n) * 768 + 512 + h * 32;
#pragma unroll
            for (int d8 = 0; d8 < 4; d8++) {
                uint4 v = *(const uint4*)(vp + d8 * 8);
                const __half* hp = (const __half*)&v;
#pragma unroll
                for (int j = 0; j < 8; j++)
                    Vt[(d8 * 8 + j) * 136 + sr] = hp[j];
            }
        }
        asm volatile("cp.async.wait_group 0;" ::: "memory");
        __syncthreads();
#pragma unroll
        for (int ks = 0; ks < 8; ks++) {
            const int kb = ks * 16;
            uint32_t a[4], b[4][2];
            a[0] = *(const uint32_t*)(As + (wm + grp) * 136 + kb + tig * 2);
            a[1] = *(const uint32_t*)(As + (wm + grp + 8) * 136 + kb + tig * 2);
            a[2] = *(const uint32_t*)(As + (wm + grp) * 136 + kb + 8 + tig * 2);
            a[3] = *(const uint32_t*)(As + (wm + grp + 8) * 136 + kb + 8 + tig * 2);
#pragma unroll
            for (int nt = 0; nt < 4; nt++) {
                int nr = nt * 8 + grp;
                b[nt][0] = *(const uint32_t*)(Vt + nr * 136 + kb + tig * 2);
                b[nt][1] = *(const uint32_t*)(Vt + nr * 136 + kb + 8 + tig * 2);
            }
#pragma unroll
            for (int nt = 0; nt < 4; nt++)
                mma_f16(acc[nt], a, b[nt]);
        }
        __syncthreads();
    }

#pragma unroll
    for (int nt = 0; nt < 4; nt++) {
        int d = nt * 8 + tig * 2;
#pragma unroll
        for (int half = 0; half < 2; half++) {
            int l = l0 + wm + grp + half * 8;
            *(uint32_t*)(ctxh + (size_t)(l * NB + n) * 256 + h * 32 + d)
                = pack_h2(acc[nt][half * 2], acc[nt][half * 2 + 1]);
        }
    }
}

// ---- fused GLU + depthwise conv(K=31) + bias + DoubleSwish (y fp16 -> hct fp16)
__global__ __launch_bounds__(256) void gludw_kernel(
    const __half* __restrict__ y, const float* __restrict__ w,
    const float* __restrict__ b, __half* __restrict__ out)
{
    __shared__ float in_s[32 * 161];
    __shared__ float w_s[32 * 33];
    const int l0 = blockIdx.x * 128;
    const int c0 = blockIdx.y * 32;
    const int n  = blockIdx.z;

    for (int idx = threadIdx.x; idx < 32 * 160; idx += 256) {
        int c = idx & 31, col = idx >> 5;
        int gl = l0 + col - 15;
        float v = 0.f;
        if (col < 158 && gl >= 0 && gl < L_) {
            size_t base = (size_t)(gl * NB + n) * 1024;
            float a = __half2float(y[base + c0 + c]);
            float g = __half2float(y[base + c0 + c + 512]);
            v = a / (1.f + expf(-g));
        }
        in_s[c * 161 + col] = v;
    }
    for (int idx = threadIdx.x; idx < 32 * KW; idx += 256) {
        int c = idx / KW, k = idx % KW;
        w_s[c * 33 + k] = w[(c0 + c) * KW + k];
    }
    __syncthreads();

    const int ci = threadIdx.x & 31;
    const int lq = threadIdx.x >> 5;
    const float bb = b[c0 + ci];
#pragma unroll
    for (int lt = 0; lt < 16; lt++) {
        int ll = lt * 8 + lq;
        float s = bb;
#pragma unroll
        for (int k = 0; k < KW; k++)
            s = fmaf(in_s[ci * 161 + ll + k], w_s[ci * 33 + k], s);
        float v = s / (1.f + expf(1.f - s));
        out[(((size_t)((l0 + ll) * NB + n)) << 9) + c0 + ci] = __float2half_rn(v);
    }
}

// -------- BasicNorm -> d_out ---------------------------------------------------
__global__ __launch_bounds__(128) void norm_kernel(
    const float* __restrict__ x, const float* __restrict__ leps,
    float* __restrict__ out)
{
    __shared__ float red[4];
    const size_t base = (size_t)blockIdx.x * 512;
    float4 v = ((const float4*)(x + base))[threadIdx.x];
    float ss = v.x * v.x + v.y * v.y + v.z * v.z + v.w * v.w;
#pragma unroll
    for (int o = 16; o > 0; o >>= 1) ss += __shfl_xor_sync(0xffffffffu, ss, o);
    if ((threadIdx.x & 31) == 0) red[threadIdx.x >> 5] = ss;
    __syncthreads();
    float tot = red[0] + red[1] + red[2] + red[3];
    float scale = rsqrtf(tot * (1.f / 512.f) + expf(leps[0]));
    ((float4*)(out + base))[threadIdx.x] =
        make_float4(v.x * scale, v.y * scale, v.z * scale, v.w * scale);
}

// ------------------------------- launcher -------------------------------------
extern "C" void kernel_launch(void* const* d_in, const int* in_sizes, int n_in,
                              void* d_out, int out_size)
{
    const float* src      = (const float*)d_in[0];
    const float* pos_emb  = (const float*)d_in[1];
    const float* asi      = (const float*)d_in[2];
    const float* w_in     = (const float*)d_in[3];
    const float* b_in     = (const float*)d_in[4];
    const float* w_pos    = (const float*)d_in[5];
    const float* pbu      = (const float*)d_in[6];
    const float* pbv      = (const float*)d_in[7];
    const float* projIn   = (const float*)d_in[8];
    const float* projOut  = (const float*)d_in[9];
    const float* w_out    = (const float*)d_in[10];
    const float* b_out    = (const float*)d_in[11];
    const float* w_ff1m   = (const float*)d_in[12];
    const float* b_ff1m   = (const float*)d_in[13];
    const float* w_ff2m   = (const float*)d_in[14];
    const float* b_ff2m   = (const float*)d_in[15];
    const float* w_ff1    = (const float*)d_in[16];
    const float* b_ff1    = (const float*)d_in[17];
    const float* w_ff2    = (const float*)d_in[18];
    const float* b_ff2    = (const float*)d_in[19];
    const float* w_pw1    = (const float*)d_in[20];
    const float* b_pw1    = (const float*)d_in[21];
    const float* w_dw     = (const float*)d_in[22];
    const float* b_dw     = (const float*)d_in[23];
    const float* w_pw2    = (const float*)d_in[24];
    const float* b_pw2    = (const float*)d_in[25];
    const float* leps     = (const float*)d_in[26];

    float* out        = (float*)d_out;
    float* out_scores = out + (size_t)TOK * E_;

    float *h1, *x, *x2, *x3, *x4;
    __half *whf, *th, *y, *qkvh, *ph, *ctxh, *hcth;
    cudaGetSymbolAddress((void**)&h1,   g_h1);
    cudaGetSymbolAddress((void**)&x,    g_x);
    cudaGetSymbolAddress((void**)&qkvh, g_qkvh);
    cudaGetSymbolAddress((void**)&ph,   g_ph);
    cudaGetSymbolAddress((void**)&th,   g_th);
    cudaGetSymbolAddress((void**)&ctxh, g_ctxh);
    cudaGetSymbolAddress((void**)&x2,   g_x2);
    cudaGetSymbolAddress((void**)&y,    g_y);
    cudaGetSymbolAddress((void**)&hcth, g_hcth);
    cudaGetSymbolAddress((void**)&x3,   g_x3);
    cudaGetSymbolAddress((void**)&x4,   g_x4);
    cudaGetSymbolAddress((void**)&whf,  g_whf);
    __half* h1h = (__half*)h1;

    static bool attr_set = false;
    if (!attr_set) {
        cudaFuncSetAttribute(hgemm<1,0,1,64>,  cudaFuncAttributeMaxDynamicSharedMemorySize, TH_SMEM_MT(64));
        cudaFuncSetAttribute(hgemm<0,0,1,64>,  cudaFuncAttributeMaxDynamicSharedMemorySize, TH_SMEM_MT(64));
        cudaFuncSetAttribute(hgemm<2,1,0,128>, cudaFuncAttributeMaxDynamicSharedMemorySize, TH_SMEM_MT(128));
        cudaFuncSetAttribute(hgemm<0,0,1,128>, cudaFuncAttributeMaxDynamicSharedMemorySize, TH_SMEM_MT(128));
        cudaFuncSetAttribute(scores_mma_kernel, cudaFuncAttributeMaxDynamicSharedMemorySize, SC_SMEM);
        attr_set = true;
    }

    // prepass: convert all B (weight) operands to fp16
    CvtArgs ca;
    ca.src[0] = w_ff1m; ca.dstoff[0] = OFF_FF1M; ca.n4[0] = (DFF_ * E_) / 4;
    ca.src[1] = w_ff2m; ca.dstoff[1] = OFF_FF2M; ca.n4[1] = (E_ * DFF_) / 4;
    ca.src[2] = w_in;   ca.dstoff[2] = OFF_IN;   ca.n4[2] = (768 * E_) / 4;
    ca.src[3] = w_pos;  ca.dstoff[3] = OFF_POS;  ca.n4[3] = (E2_ * E_) / 4;
    ca.src[4] = w_out;  ca.dstoff[4] = OFF_OUT;  ca.n4[4] = (E_ * E2_) / 4;
    ca.src[5] = w_pw1;  ca.dstoff[5] = OFF_PW1;  ca.n4[5] = (1024 * E_) / 4;
    ca.src[6] = w_pw2;  ca.dstoff[6] = OFF_PW2;  ca.n4[6] = (E_ * E_) / 4;
    ca.src[7] = w_ff1;  ca.dstoff[7] = OFF_FF1;  ca.n4[7] = (DFF_ * E_) / 4;
    ca.src[8] = w_ff2;  ca.dstoff[8] = OFF_FF2;  ca.n4[8] = (E_ * DFF_) / 4;
    cvtw_kernel<<<dim3(1024, 9), 256>>>(ca);

    // macaron FFN
    hgemm<1,0,1,64><<<dim3(DFF_ / 128, TOK / 64), 256, TH_SMEM_MT(64)>>>(src, whf + OFF_FF1M, b_ff1m, nullptr, h1h, TOK, DFF_, E_);
    hgemm<2,1,0,128><<<dim3(E_ / 128, TOK / 128), 256, TH_SMEM_MT(128)>>>(h1h, whf + OFF_FF2M, b_ff2m, src, x, TOK, E_, DFF_);

    // attention inputs (qkv + pos both fp16 out)
    hgemm<0,0,1,64><<<dim3(768 / 128, TOK / 64), 256, TH_SMEM_MT(64)>>>(x, whf + OFF_IN, b_in, nullptr, qkvh, TOK, 768, E_);
    hgemm<0,0,1,64><<<dim3(2, 32), 256, TH_SMEM_MT(64)>>>(pos_emb, whf + OFF_POS, nullptr, nullptr, ph, PM, 256, E_);

    // scores (fp16 MMA) -> fused softmax (probs in place) -> AV (ctx fp16)
    scores_mma_kernel<<<dim3(16, 16, 32), 256, SC_SMEM>>>(qkvh, ph, pbu, pbv, th);
    out_softmax_kernel<<<4096, 256>>>(th, asi, projIn, projOut, out_scores);
    av_kernel<<<dim3(16, 32), 128>>>(th, qkvh, ctxh);
    hgemm<2,1,0,128><<<dim3(E_ / 128, TOK / 128), 256, TH_SMEM_MT(128)>>>(ctxh, whf + OFF_OUT, b_out, x, x2, TOK, E_, E2_);

    // conv module (pw1 -> fp16 y; GLU fused into dwconv; hct fp16)
    hgemm<0,0,1,128><<<dim3(1024 / 128, TOK / 128), 256, TH_SMEM_MT(128)>>>(x2, whf + OFF_PW1, b_pw1, nullptr, y, TOK, 1024, E_);
    gludw_kernel<<<dim3(8, 16, NB), 256>>>(y, w_dw, b_dw, hcth);
    hgemm<2,1,0,128><<<dim3(E_ / 128, TOK / 128), 256, TH_SMEM_MT(128)>>>(hcth, whf + OFF_PW2, b_pw2, x2, x3, TOK, E_, E_);

    // final FFN + BasicNorm
    hgemm<1,0,1,64><<<dim3(DFF_ / 128, TOK / 64), 256, TH_SMEM_MT(64)>>>(x3, whf + OFF_FF1, b_ff1, nullptr, h1h, TOK, DFF_, E_);
    hgemm<2,1,0,128><<<dim3(E_ / 128, TOK / 128), 256, TH_SMEM_MT(128)>>>(h1h, whf + OFF_FF2, b_ff2, x3, x4, TOK, E_, DFF_);
    norm_kernel<<<TOK, 128>>>(x4, leps, out);
}